// round 4
// baseline (speedup 1.0000x reference)
#include <cuda_runtime.h>
#include <cuda_fp16.h>
#include <cstdint>

#define C2    2048
#define NPIX  4096
#define BATCH 2

typedef __half fp16;

// ---------------------------------------------------------------------------
// Static device scratch (no allocations anywhere)
// ---------------------------------------------------------------------------
__device__ fp16 g_Xt_h[(size_t)BATCH * NPIX * 2 * C2];   // [b][pix][4096 ch]
__device__ fp16 g_Xt_l[(size_t)BATCH * NPIX * 2 * C2];
__device__ fp16 g_wq_h[(size_t)C2 * 2 * C2];
__device__ fp16 g_wq_l[(size_t)C2 * 2 * C2];
__device__ fp16 g_wk_h[(size_t)C2 * 2 * C2];
__device__ fp16 g_wk_l[(size_t)C2 * 2 * C2];
__device__ fp16 g_wv2_h[(size_t)C2 * 2 * C2];            // folded V weights
__device__ fp16 g_wv2_l[(size_t)C2 * 2 * C2];
__device__ float g_bv2[C2];
__device__ fp16 g_Qt_h[(size_t)BATCH * NPIX * C2];       // [b][pix][ch]
__device__ fp16 g_Qt_l[(size_t)BATCH * NPIX * C2];
__device__ fp16 g_Kt_h[(size_t)BATCH * NPIX * C2];
__device__ fp16 g_Kt_l[(size_t)BATCH * NPIX * C2];
__device__ fp16 g_V2_h[(size_t)BATCH * C2 * NPIX];       // [b][ch][pix]
__device__ fp16 g_V2_l[(size_t)BATCH * C2 * NPIX];
__device__ fp16 g_At_h[(size_t)BATCH * NPIX * NPIX];     // attn fp16 pair
__device__ fp16 g_At_l[(size_t)BATCH * NPIX * NPIX];

// ---------------------------------------------------------------------------
// helpers
// ---------------------------------------------------------------------------
__device__ __forceinline__ uint32_t smem_u32(const void* p) {
    uint32_t a;
    asm("{ .reg .u64 t; cvta.to.shared.u64 t, %1; cvt.u32.u64 %0, t; }"
        : "=r"(a) : "l"(p));
    return a;
}
__device__ __forceinline__ uint32_t swz64(uint32_t b) {     // 64B-row swizzle
    return b ^ ((b >> 3) & 0x30);
}
__device__ __forceinline__ void cp_async16(uint32_t dst, const void* src) {
    asm volatile("cp.async.cg.shared.global [%0], [%1], 16;\n"
                 :: "r"(dst), "l"(src) : "memory");
}
__device__ __forceinline__ void ldsm_x4(uint32_t* r, uint32_t addr) {
    asm volatile("ldmatrix.sync.aligned.m8n8.x4.shared.b16 {%0,%1,%2,%3}, [%4];"
                 : "=r"(r[0]), "=r"(r[1]), "=r"(r[2]), "=r"(r[3]) : "r"(addr));
}
__device__ __forceinline__ void mma16816(float* d, const uint32_t* a,
                                         uint32_t b0, uint32_t b1) {
    asm volatile(
        "mma.sync.aligned.m16n8k16.row.col.f32.f16.f16.f32 "
        "{%0,%1,%2,%3}, {%4,%5,%6,%7}, {%8,%9}, {%0,%1,%2,%3};"
        : "+f"(d[0]), "+f"(d[1]), "+f"(d[2]), "+f"(d[3])
        : "r"(a[0]), "r"(a[1]), "r"(a[2]), "r"(a[3]), "r"(b0), "r"(b1));
}
__device__ __forceinline__ void split_h(float v, fp16& h, fp16& l) {
    h = __float2half_rn(v);
    l = __float2half_rn(v - __half2float(h));
}

// ---------------------------------------------------------------------------
// Pack + transpose: f_rgb/f_i -> fp32 output copies and Xt hi/lo (fp16)
// ---------------------------------------------------------------------------
__global__ void pack_transpose_kernel(const float* __restrict__ frgb,
                                      const float* __restrict__ fi,
                                      float* __restrict__ out)
{
    __shared__ float tile[32][33];
    const int s = blockIdx.z & 1, b = blockIdx.z >> 1;
    const float* src = s ? fi : frgb;
    const int pix0 = blockIdx.x * 32, ch0 = blockIdx.y * 32;
    const size_t base = (size_t)b * C2 * NPIX;
    const size_t PER  = (size_t)BATCH * C2 * NPIX;
    const int tx = threadIdx.x, ty = threadIdx.y;
#pragma unroll
    for (int i = 0; i < 4; ++i) {
        const int ch = ch0 + ty + i * 8;
        const size_t idx = base + (size_t)ch * NPIX + pix0 + tx;
        float v = src[idx];
        out[PER * (1 + s) + idx] = v;          // f_rgb / f_i copy
        tile[ty + i * 8][tx] = v;
    }
    __syncthreads();
    const size_t xbase = (size_t)b * NPIX * (2 * C2) + (size_t)s * C2;
#pragma unroll
    for (int i = 0; i < 4; ++i) {
        const int pix = pix0 + ty + i * 8;
        float v = tile[tx][ty + i * 8];
        fp16 h, l; split_h(v, h, l);
        const size_t idx = xbase + (size_t)pix * (2 * C2) + ch0 + tx;
        g_Xt_h[idx] = h;
        g_Xt_l[idx] = l;
    }
}

// ---------------------------------------------------------------------------
// Weight prep: split wq/wk, fold+split wv, fold bv
// ---------------------------------------------------------------------------
__global__ void weights_prep_kernel(const float* __restrict__ wq,
                                    const float* __restrict__ wk,
                                    const float* __restrict__ wv,
                                    const float* __restrict__ bv)
{
    const size_t NW = (size_t)C2 * 2 * C2;
    size_t i = (size_t)blockIdx.x * blockDim.x + threadIdx.x;
    if (i < NW) {
        fp16 h, l;
        split_h(wq[i], h, l);              g_wq_h[i] = h;  g_wq_l[i] = l;
        split_h(wk[i], h, l);              g_wk_h[i] = h;  g_wk_l[i] = l;
        split_h(wv[i] + wv[i + NW], h, l); g_wv2_h[i] = h; g_wv2_l[i] = l;
    }
    if (i < C2) g_bv2[i] = bv[i] + bv[i + C2];
}

// ---------------------------------------------------------------------------
// HMMA GEMM:  D[M,N] = alpha * A[M,K] @ B[N,K]^T (+bias), fp16 hi/lo 3-product
// CTA tile 128x256, 8 warps (warp tile 64x64), kTile 32, 4-stage cp.async.
// MODE 0: out fp16 hi/lo pair, row-major; MODE 1: out f32 row-major * alpha.
// ---------------------------------------------------------------------------
static constexpr int STAGE_B   = 49152;     // Ah8K + Al8K + Bh16K + Bl16K
static constexpr int GEMM_SMEM = 4 * STAGE_B + 128;

template<int MODE>
__global__ void __launch_bounds__(256, 1)
hgemm(const fp16* __restrict__ Ah, const fp16* __restrict__ Al,
      const fp16* __restrict__ Bh, const fp16* __restrict__ Bl,
      size_t sAb, size_t sBb, int K,
      void* __restrict__ out0v, void* __restrict__ out1v,
      int ldo, size_t sOb, float alpha,
      const float* __restrict__ bias_m, const float* __restrict__ bias_n)
{
    extern __shared__ __align__(128) char dsm[];
    const uint32_t smbase = (smem_u32(dsm) + 127u) & ~127u;

    const int tid  = threadIdx.x;
    const int lane = tid & 31, warp = tid >> 5;
    const int m0 = blockIdx.y * 128;
    const int n0 = blockIdx.x * 256;
    const int b  = blockIdx.z;
    Ah += sAb * b;  Al += sAb * b;
    Bh += sBb * b;  Bl += sBb * b;

    const int wm = (warp >> 2) * 64;     // warp M offset (2 warps in M)
    const int wn = (warp & 3) * 64;      // warp N offset (4 warps in N)

    float acc[4][8][4];
#pragma unroll
    for (int i = 0; i < 4; ++i)
#pragma unroll
        for (int j = 0; j < 8; ++j)
#pragma unroll
            for (int q = 0; q < 4; ++q) acc[i][j][q] = 0.f;

    // hoisted ldmatrix addressing (64B rows, SW64 swizzle)
    const int arow = wm + (lane & 15);
    const int brow = wn + (lane & 15);
    const uint32_t hk  = (uint32_t)(lane >> 4);
    const uint32_t sxa = (uint32_t)((arow >> 1) & 3);
    const uint32_t sxb = (uint32_t)((brow >> 1) & 3);
    uint32_t aoff[4], boff[4];
#pragma unroll
    for (int mi = 0; mi < 4; ++mi) aoff[mi] = (uint32_t)((arow + mi * 16) * 64);
#pragma unroll
    for (int g = 0; g < 4; ++g)    boff[g] = (uint32_t)((brow + g * 16) * 64);

    const int NK = K / 32;

    auto load_stage = [&](int kt) {
        if (kt < NK) {
            const uint32_t sb = smbase + (uint32_t)(kt & 3) * STAGE_B;
            const int k0 = kt * 32;
#pragma unroll
            for (int t = 0; t < 2; ++t) {                  // A hi/lo: 128x32
                const fp16* g = t ? Al : Ah;
                const uint32_t tb = sb + t * 8192;
#pragma unroll
                for (int j = 0; j < 2; ++j) {
                    int idx = tid + j * 256;
                    int r = idx >> 2, c = idx & 3;
                    cp_async16(tb + swz64((uint32_t)(r * 64 + c * 16)),
                               g + (size_t)(m0 + r) * K + k0 + c * 8);
                }
            }
#pragma unroll
            for (int t = 0; t < 2; ++t) {                  // B hi/lo: 256x32
                const fp16* g = t ? Bl : Bh;
                const uint32_t tb = sb + 16384 + t * 16384;
#pragma unroll
                for (int j = 0; j < 4; ++j) {
                    int idx = tid + j * 256;
                    int r = idx >> 2, c = idx & 3;
                    cp_async16(tb + swz64((uint32_t)(r * 64 + c * 16)),
                               g + (size_t)(n0 + r) * K + k0 + c * 8);
                }
            }
        }
        asm volatile("cp.async.commit_group;" ::: "memory");
    };

    load_stage(0); load_stage(1); load_stage(2);

    for (int kt = 0; kt < NK; ++kt) {
        asm volatile("cp.async.wait_group 2;" ::: "memory");
        __syncthreads();
        load_stage(kt + 3);

        const uint32_t sb = smbase + (uint32_t)(kt & 3) * STAGE_B;
        const uint32_t aH = sb, aL = sb + 8192;
        const uint32_t bHs = sb + 16384, bLs = sb + 32768;

#pragma unroll
        for (int kc = 0; kc < 2; ++kc) {
            const uint32_t colA = ((kc * 2 + hk) ^ sxa) << 4;
            const uint32_t colB = ((kc * 2 + hk) ^ sxb) << 4;
            uint32_t a1[4][4], a2[4][4];
#pragma unroll
            for (int mi = 0; mi < 4; ++mi)
                ldsm_x4(a1[mi], aH + aoff[mi] + colA);
#pragma unroll
            for (int mi = 0; mi < 4; ++mi)
                ldsm_x4(a2[mi], aL + aoff[mi] + colA);

#pragma unroll
            for (int g = 0; g < 4; ++g) {
                uint32_t th[4], tl[4];
                ldsm_x4(th, bHs + boff[g] + colB);
                ldsm_x4(tl, bLs + boff[g] + colB);
                const int n0i = 2 * g, n1i = 2 * g + 1;
#pragma unroll
                for (int mi = 0; mi < 4; ++mi) {
                    mma16816(acc[mi][n0i], a1[mi], th[0], th[2]);   // hh
                    mma16816(acc[mi][n1i], a1[mi], th[1], th[3]);
                    mma16816(acc[mi][n0i], a1[mi], tl[0], tl[2]);   // hl
                    mma16816(acc[mi][n1i], a1[mi], tl[1], tl[3]);
                    mma16816(acc[mi][n0i], a2[mi], th[0], th[2]);   // lh
                    mma16816(acc[mi][n1i], a2[mi], th[1], th[3]);
                }
            }
        }
    }

    // ------------------------------- epilogue ------------------------------
    const int r0 = m0 + wm + (lane >> 2);
    const int c0 = n0 + wn + (lane & 3) * 2;
#pragma unroll
    for (int mi = 0; mi < 4; ++mi) {
        const int rA = r0 + mi * 16, rB = rA + 8;
        float bmA = 0.f, bmB = 0.f;
        if (MODE == 0 && bias_m) { bmA = bias_m[rA]; bmB = bias_m[rB]; }
#pragma unroll
        for (int ni = 0; ni < 8; ++ni) {
            const int col = c0 + ni * 8;
            if (MODE == 1) {
                float* o = (float*)out0v + sOb * b;
                float2 u;
                u.x = acc[mi][ni][0] * alpha; u.y = acc[mi][ni][1] * alpha;
                *(float2*)(o + (size_t)rA * ldo + col) = u;
                u.x = acc[mi][ni][2] * alpha; u.y = acc[mi][ni][3] * alpha;
                *(float2*)(o + (size_t)rB * ldo + col) = u;
            } else {
                fp16* oh = (fp16*)out0v + sOb * b;
                fp16* ol = (fp16*)out1v + sOb * b;
                float bn0 = 0.f, bn1 = 0.f;
                if (bias_n) { bn0 = bias_n[col]; bn1 = bias_n[col + 1]; }
                float v0 = acc[mi][ni][0] + bmA + bn0;
                float v1 = acc[mi][ni][1] + bmA + bn1;
                float v2 = acc[mi][ni][2] + bmB + bn0;
                float v3 = acc[mi][ni][3] + bmB + bn1;
                fp16 h0, l0, h1, l1, h2, l2, h3, l3;
                split_h(v0, h0, l0); split_h(v1, h1, l1);
                split_h(v2, h2, l2); split_h(v3, h3, l3);
                *(__half2*)(oh + (size_t)rA * ldo + col) = __halves2half2(h0, h1);
                *(__half2*)(ol + (size_t)rA * ldo + col) = __halves2half2(l0, l1);
                *(__half2*)(oh + (size_t)rB * ldo + col) = __halves2half2(h2, h3);
                *(__half2*)(ol + (size_t)rB * ldo + col) = __halves2half2(l2, l3);
            }
        }
    }
}

// ---------------------------------------------------------------------------
// Row softmax: f32 in/out on attn, plus fp16 hi/lo pair for the final GEMM
// ---------------------------------------------------------------------------
__global__ void softmax_kernel(float* __restrict__ attn,
                               fp16* __restrict__ ah, fp16* __restrict__ al)
{
    const size_t roff = (size_t)blockIdx.x * NPIX;
    float* p = attn + roff;
    const int t = threadIdx.x;
    float v[16];
    float mx = -1e30f;
#pragma unroll
    for (int j = 0; j < 16; ++j) {
        v[j] = p[t + 256 * j];
        mx = fmaxf(mx, v[j]);
    }
    __shared__ float sred[8];
#pragma unroll
    for (int o = 16; o; o >>= 1)
        mx = fmaxf(mx, __shfl_xor_sync(0xffffffffu, mx, o));
    if ((t & 31) == 0) sred[t >> 5] = mx;
    __syncthreads();
    mx = sred[0];
#pragma unroll
    for (int k = 1; k < 8; ++k) mx = fmaxf(mx, sred[k]);

    float s = 0.f;
#pragma unroll
    for (int j = 0; j < 16; ++j) {
        v[j] = __expf(v[j] - mx);
        s += v[j];
    }
#pragma unroll
    for (int o = 16; o; o >>= 1)
        s += __shfl_xor_sync(0xffffffffu, s, o);
    __syncthreads();
    if ((t & 31) == 0) sred[t >> 5] = s;
    __syncthreads();
    s = 0.f;
#pragma unroll
    for (int k = 0; k < 8; ++k) s += sred[k];

    const float inv = 1.f / s;
#pragma unroll
    for (int j = 0; j < 16; ++j) {
        const int idx = t + 256 * j;
        float o = v[j] * inv;
        p[idx] = o;
        fp16 h, l; split_h(o, h, l);
        ah[roff + idx] = h;
        al[roff + idx] = l;
    }
}

// ---------------------------------------------------------------------------
// kernel_launch
// Inputs: f_rgb, f_i, wq, bq, wk, bk, wv, bv
// Output: [f_final | f_rgb | f_i | attn] fp32
// ---------------------------------------------------------------------------
extern "C" void kernel_launch(void* const* d_in, const int* in_sizes, int n_in,
                              void* d_out, int out_size)
{
    const float* f_rgb = (const float*)d_in[0];
    const float* f_i   = (const float*)d_in[1];
    const float* wq    = (const float*)d_in[2];
    const float* bq    = (const float*)d_in[3];
    const float* wk    = (const float*)d_in[4];
    const float* bk    = (const float*)d_in[5];
    const float* wv    = (const float*)d_in[6];
    const float* bv    = (const float*)d_in[7];
    float* out = (float*)d_out;

    cudaFuncSetAttribute(hgemm<0>, cudaFuncAttributeMaxDynamicSharedMemorySize, GEMM_SMEM);
    cudaFuncSetAttribute(hgemm<1>, cudaFuncAttributeMaxDynamicSharedMemorySize, GEMM_SMEM);

    fp16 *Xh, *Xl, *qh, *ql, *kh, *kl, *vh, *vl;
    fp16 *Qh, *Ql, *Kh, *Kl, *Vh, *Vl, *Ath, *Atl;
    float* bv2;
    cudaGetSymbolAddress((void**)&Xh,  g_Xt_h);
    cudaGetSymbolAddress((void**)&Xl,  g_Xt_l);
    cudaGetSymbolAddress((void**)&qh,  g_wq_h);
    cudaGetSymbolAddress((void**)&ql,  g_wq_l);
    cudaGetSymbolAddress((void**)&kh,  g_wk_h);
    cudaGetSymbolAddress((void**)&kl,  g_wk_l);
    cudaGetSymbolAddress((void**)&vh,  g_wv2_h);
    cudaGetSymbolAddress((void**)&vl,  g_wv2_l);
    cudaGetSymbolAddress((void**)&Qh,  g_Qt_h);
    cudaGetSymbolAddress((void**)&Ql,  g_Qt_l);
    cudaGetSymbolAddress((void**)&Kh,  g_Kt_h);
    cudaGetSymbolAddress((void**)&Kl,  g_Kt_l);
    cudaGetSymbolAddress((void**)&Vh,  g_V2_h);
    cudaGetSymbolAddress((void**)&Vl,  g_V2_l);
    cudaGetSymbolAddress((void**)&Ath, g_At_h);
    cudaGetSymbolAddress((void**)&Atl, g_At_l);
    cudaGetSymbolAddress((void**)&bv2, g_bv2);

    float* f_final = out;
    float* attn    = out + (size_t)3 * BATCH * C2 * NPIX;

    const size_t sX = (size_t)NPIX * 2 * C2;
    const size_t sQ = (size_t)NPIX * C2;
    const size_t sS = (size_t)NPIX * NPIX;

    // 1) copies + transpose/split X
    pack_transpose_kernel<<<dim3(NPIX / 32, C2 / 32, BATCH * 2), dim3(32, 8)>>>(
        f_rgb, f_i, out);
    // 2) weight split / fold
    weights_prep_kernel<<<(unsigned)((size_t)C2 * 2 * C2 / 256), 256>>>(wq, wk, wv, bv);

    // 3) projections: Qt[pix][ch], Kt[pix][ch], V2[ch][pix]
    hgemm<0><<<dim3(C2 / 256, NPIX / 128, BATCH), 256, GEMM_SMEM>>>(
        Xh, Xl, qh, ql, sX, 0, 2 * C2, Qh, Ql, C2, sQ, 1.f, nullptr, bq);
    hgemm<0><<<dim3(C2 / 256, NPIX / 128, BATCH), 256, GEMM_SMEM>>>(
        Xh, Xl, kh, kl, sX, 0, 2 * C2, Kh, Kl, C2, sQ, 1.f, nullptr, bk);
    hgemm<0><<<dim3(NPIX / 256, C2 / 128, BATCH), 256, GEMM_SMEM>>>(
        vh, vl, Xh, Xl, 0, sX, 2 * C2, Vh, Vl, NPIX, sQ, 1.f, bv2, nullptr);

    // 4) scores S[n][m] = QK/64 (f32 into attn region)
    hgemm<1><<<dim3(NPIX / 256, NPIX / 128, BATCH), 256, GEMM_SMEM>>>(
        Qh, Ql, Kh, Kl, sQ, sQ, C2, attn, nullptr, NPIX, sS, 1.f / 64.f,
        nullptr, nullptr);

    // 5) softmax (f32 out + fp16 pair)
    softmax_kernel<<<BATCH * NPIX, 256>>>(attn, Ath, Atl);

    // 6) f_final[c][n] = sum_m V2[c,m] attn[n,m]  (row-major f32 out)
    hgemm<1><<<dim3(NPIX / 256, C2 / 128, BATCH), 256, GEMM_SMEM>>>(
        Vh, Vl, Ath, Atl, sQ, sS, NPIX, f_final, nullptr, NPIX, sQ, 1.f,
        nullptr, nullptr);
}

// round 5
// speedup vs baseline: 1.1348x; 1.1348x over previous
#include <cuda_runtime.h>
#include <cuda_fp16.h>
#include <cstdint>

#define C2    2048
#define NPIX  4096
#define BATCH 2

typedef __half fp16;

// ---------------------------------------------------------------------------
// Static device scratch (no allocations anywhere)
// ---------------------------------------------------------------------------
__device__ fp16 g_Xt_h[(size_t)BATCH * NPIX * 2 * C2];   // [b][pix][4096 ch]
__device__ fp16 g_Xt_l[(size_t)BATCH * NPIX * 2 * C2];
__device__ fp16 g_wq_h[(size_t)C2 * 2 * C2];
__device__ fp16 g_wq_l[(size_t)C2 * 2 * C2];
__device__ fp16 g_wk_h[(size_t)C2 * 2 * C2];
__device__ fp16 g_wk_l[(size_t)C2 * 2 * C2];
__device__ fp16 g_wv2_h[(size_t)C2 * 2 * C2];            // folded V weights
__device__ fp16 g_wv2_l[(size_t)C2 * 2 * C2];
__device__ float g_bv2[C2];
__device__ fp16 g_Qt_h[(size_t)BATCH * NPIX * C2];       // [b][pix][ch]
__device__ fp16 g_Qt_l[(size_t)BATCH * NPIX * C2];
__device__ fp16 g_Kt_h[(size_t)BATCH * NPIX * C2];
__device__ fp16 g_Kt_l[(size_t)BATCH * NPIX * C2];
__device__ fp16 g_V2_h[(size_t)BATCH * C2 * NPIX];       // [b][ch][pix]
__device__ fp16 g_V2_l[(size_t)BATCH * C2 * NPIX];
__device__ fp16 g_At_h[(size_t)BATCH * NPIX * NPIX];     // attn fp16 pair
__device__ fp16 g_At_l[(size_t)BATCH * NPIX * NPIX];

// ---------------------------------------------------------------------------
// helpers
// ---------------------------------------------------------------------------
__device__ __forceinline__ uint32_t smem_u32(const void* p) {
    uint32_t a;
    asm("{ .reg .u64 t; cvta.to.shared.u64 t, %1; cvt.u32.u64 %0, t; }"
        : "=r"(a) : "l"(p));
    return a;
}
__device__ __forceinline__ uint32_t swz(uint32_t b) {       // 128B-row swizzle
    return b ^ ((b >> 3) & 0x70);
}
__device__ __forceinline__ void cp_async16(uint32_t dst, const void* src) {
    asm volatile("cp.async.cg.shared.global [%0], [%1], 16;\n"
                 :: "r"(dst), "l"(src) : "memory");
}
__device__ __forceinline__ void ldsm_x4(uint32_t* r, uint32_t addr) {
    asm volatile("ldmatrix.sync.aligned.m8n8.x4.shared.b16 {%0,%1,%2,%3}, [%4];"
                 : "=r"(r[0]), "=r"(r[1]), "=r"(r[2]), "=r"(r[3]) : "r"(addr));
}
__device__ __forceinline__ void mma16816(float* d, const uint32_t* a,
                                         const uint32_t* b) {
    asm volatile(
        "mma.sync.aligned.m16n8k16.row.col.f32.f16.f16.f32 "
        "{%0,%1,%2,%3}, {%4,%5,%6,%7}, {%8,%9}, {%0,%1,%2,%3};"
        : "+f"(d[0]), "+f"(d[1]), "+f"(d[2]), "+f"(d[3])
        : "r"(a[0]), "r"(a[1]), "r"(a[2]), "r"(a[3]), "r"(b[0]), "r"(b[1]));
}
__device__ __forceinline__ void split_h(float v, fp16& h, fp16& l) {
    h = __float2half_rn(v);
    l = __float2half_rn(v - __half2float(h));
}

// ---------------------------------------------------------------------------
// Pack + transpose: f_rgb/f_i -> fp32 output copies and Xt hi/lo (fp16)
// ---------------------------------------------------------------------------
__global__ void pack_transpose_kernel(const float* __restrict__ frgb,
                                      const float* __restrict__ fi,
                                      float* __restrict__ out)
{
    __shared__ float tile[32][33];
    const int s = blockIdx.z & 1, b = blockIdx.z >> 1;
    const float* src = s ? fi : frgb;
    const int pix0 = blockIdx.x * 32, ch0 = blockIdx.y * 32;
    const size_t base = (size_t)b * C2 * NPIX;
    const size_t PER  = (size_t)BATCH * C2 * NPIX;
    const int tx = threadIdx.x, ty = threadIdx.y;
#pragma unroll
    for (int i = 0; i < 4; ++i) {
        const int ch = ch0 + ty + i * 8;
        const size_t idx = base + (size_t)ch * NPIX + pix0 + tx;
        float v = src[idx];
        out[PER * (1 + s) + idx] = v;          // f_rgb / f_i copy
        tile[ty + i * 8][tx] = v;
    }
    __syncthreads();
    const size_t xbase = (size_t)b * NPIX * (2 * C2) + (size_t)s * C2;
#pragma unroll
    for (int i = 0; i < 4; ++i) {
        const int pix = pix0 + ty + i * 8;
        float v = tile[tx][ty + i * 8];
        fp16 h, l; split_h(v, h, l);
        const size_t idx = xbase + (size_t)pix * (2 * C2) + ch0 + tx;
        g_Xt_h[idx] = h;
        g_Xt_l[idx] = l;
    }
}

// ---------------------------------------------------------------------------
// Weight prep: split wq/wk, fold+split wv, fold bv
// ---------------------------------------------------------------------------
__global__ void weights_prep_kernel(const float* __restrict__ wq,
                                    const float* __restrict__ wk,
                                    const float* __restrict__ wv,
                                    const float* __restrict__ bv)
{
    const size_t NW = (size_t)C2 * 2 * C2;
    size_t i = (size_t)blockIdx.x * blockDim.x + threadIdx.x;
    if (i < NW) {
        fp16 h, l;
        split_h(wq[i], h, l);              g_wq_h[i] = h;  g_wq_l[i] = l;
        split_h(wk[i], h, l);              g_wk_h[i] = h;  g_wk_l[i] = l;
        split_h(wv[i] + wv[i + NW], h, l); g_wv2_h[i] = h; g_wv2_l[i] = l;
    }
    if (i < C2) g_bv2[i] = bv[i] + bv[i + C2];
}

// ---------------------------------------------------------------------------
// HMMA GEMM:  D[M,N] = alpha * A[M,K] @ B[N,K]^T (+bias), fp16 hi/lo 3-product
// CTA tile 128x128, kTile 64, 8 warps (warp tile 64x32), 3-stage cp.async
// ring with wait_group 1; pass-ordered MMAs (acc reuse distance 16).
// MODE 0: out fp16 hi/lo pair, row-major; MODE 1: out f32 row-major * alpha.
// ---------------------------------------------------------------------------
static constexpr int TILE16K   = 16384;          // one 128x64 fp16 tile
static constexpr int STAGE_B   = 4 * TILE16K;    // Ah, Al, Bh, Bl = 64KB
static constexpr int GEMM_SMEM = 3 * STAGE_B + 128;

template<int MODE>
__global__ void __launch_bounds__(256, 1)
hgemm(const fp16* __restrict__ Ah, const fp16* __restrict__ Al,
      const fp16* __restrict__ Bh, const fp16* __restrict__ Bl,
      size_t sAb, size_t sBb, int K,
      void* __restrict__ out0v, void* __restrict__ out1v,
      int ldo, size_t sOb, float alpha,
      const float* __restrict__ bias_m, const float* __restrict__ bias_n)
{
    extern __shared__ __align__(128) char dsm[];
    const uint32_t smbase = (smem_u32(dsm) + 127u) & ~127u;

    const int tid  = threadIdx.x;
    const int lane = tid & 31, warp = tid >> 5;
    const int m0 = blockIdx.y * 128;
    const int n0 = blockIdx.x * 128;
    const int b  = blockIdx.z;
    Ah += sAb * b;  Al += sAb * b;
    Bh += sBb * b;  Bl += sBb * b;

    const int wm = (warp >> 2) * 64;     // warp M offset
    const int wn = (warp & 3) * 32;      // warp N offset

    float acc[4][4][4];
#pragma unroll
    for (int i = 0; i < 4; ++i)
#pragma unroll
        for (int j = 0; j < 4; ++j)
#pragma unroll
            for (int q = 0; q < 4; ++q) acc[i][j][q] = 0.f;

    // ---- hoisted ldmatrix addressing ----
    const int arow = wm + (lane & 15);
    const int brow = wn + (lane & 15);
    const uint32_t hk  = (uint32_t)(lane >> 4);
    const uint32_t sxa = (uint32_t)(arow & 7);
    const uint32_t sxb = (uint32_t)(brow & 7);
    uint32_t colA[4], colB[4], aoff[4];
#pragma unroll
    for (int kc = 0; kc < 4; ++kc) {
        colA[kc] = (((uint32_t)(kc * 2) + hk) ^ sxa) << 4;
        colB[kc] = (((uint32_t)(kc * 2) + hk) ^ sxb) << 4;
    }
#pragma unroll
    for (int mi = 0; mi < 4; ++mi) aoff[mi] = (uint32_t)((arow + mi * 16) * 128);
    const uint32_t boff0 = (uint32_t)(brow * 128);
    const uint32_t boff1 = (uint32_t)((brow + 16) * 128);

    // ---- hoisted cp.async addressing ----
    const int r0t = tid >> 3;                         // row 0..31 (first chunk)
    const int c8  = (tid & 7) * 8;                    // fp16 col of 16B chunk
    const size_t gA0 = (size_t)(m0 + r0t) * K + c8;
    const size_t gB0 = (size_t)(n0 + r0t) * K + c8;
    const size_t gstep = (size_t)32 * K;              // +32 rows per chunk
    const uint32_t soff0 = swz((uint32_t)(r0t * 128 + (tid & 7) * 16));

    const int NK = K / 64;

    auto load_stage = [&](int kt, int slot) {
        if (kt < NK) {
            const uint32_t sb = smbase + (uint32_t)slot * STAGE_B;
            const int k0 = kt * 64;
            const fp16* pAh = Ah + gA0 + k0;
            const fp16* pAl = Al + gA0 + k0;
            const fp16* pBh = Bh + gB0 + k0;
            const fp16* pBl = Bl + gB0 + k0;
#pragma unroll
            for (int j = 0; j < 4; ++j) {
                const uint32_t so = soff0 + (uint32_t)(j * 4096);
                const size_t go = (size_t)j * gstep;
                cp_async16(sb + so,               pAh + go);
                cp_async16(sb + TILE16K + so,     pAl + go);
                cp_async16(sb + 2 * TILE16K + so, pBh + go);
                cp_async16(sb + 3 * TILE16K + so, pBl + go);
            }
        }
        asm volatile("cp.async.commit_group;" ::: "memory");
    };

    load_stage(0, 0);
    load_stage(1, 1);
    int cur = 0, wr = 2;

    for (int kt = 0; kt < NK; ++kt) {
        asm volatile("cp.async.wait_group 1;" ::: "memory");
        __syncthreads();
        load_stage(kt + 2, wr);
        wr = (wr == 2) ? 0 : wr + 1;

        const uint32_t sb = smbase + (uint32_t)cur * STAGE_B;
        cur = (cur == 2) ? 0 : cur + 1;
        const uint32_t aH = sb, aL = sb + TILE16K;
        const uint32_t bH = sb + 2 * TILE16K, bL = sb + 3 * TILE16K;

#pragma unroll
        for (int kc = 0; kc < 4; ++kc) {
            const uint32_t cA = colA[kc], cB = colB[kc];
            uint32_t a1[4][4], a2[4][4], b1[4][2], b2[4][2], t[4];

#pragma unroll
            for (int mi = 0; mi < 4; ++mi)
                ldsm_x4(a1[mi], aH + aoff[mi] + cA);
            ldsm_x4(t, bH + boff0 + cB);
            b1[0][0] = t[0]; b1[0][1] = t[2]; b1[1][0] = t[1]; b1[1][1] = t[3];
            ldsm_x4(t, bH + boff1 + cB);
            b1[2][0] = t[0]; b1[2][1] = t[2]; b1[3][0] = t[1]; b1[3][1] = t[3];
#pragma unroll
            for (int mi = 0; mi < 4; ++mi)
#pragma unroll
                for (int ni = 0; ni < 4; ++ni)
                    mma16816(acc[mi][ni], a1[mi], b1[ni]);      // hh

            ldsm_x4(t, bL + boff0 + cB);
            b2[0][0] = t[0]; b2[0][1] = t[2]; b2[1][0] = t[1]; b2[1][1] = t[3];
            ldsm_x4(t, bL + boff1 + cB);
            b2[2][0] = t[0]; b2[2][1] = t[2]; b2[3][0] = t[1]; b2[3][1] = t[3];
#pragma unroll
            for (int mi = 0; mi < 4; ++mi)
#pragma unroll
                for (int ni = 0; ni < 4; ++ni)
                    mma16816(acc[mi][ni], a1[mi], b2[ni]);      // hl

#pragma unroll
            for (int mi = 0; mi < 4; ++mi)
                ldsm_x4(a2[mi], aL + aoff[mi] + cA);
#pragma unroll
            for (int mi = 0; mi < 4; ++mi)
#pragma unroll
                for (int ni = 0; ni < 4; ++ni)
                    mma16816(acc[mi][ni], a2[mi], b1[ni]);      // lh
        }
    }

    // ------------------------------- epilogue ------------------------------
    const int r0 = m0 + wm + (lane >> 2);
    const int c0 = n0 + wn + (lane & 3) * 2;
#pragma unroll
    for (int mi = 0; mi < 4; ++mi) {
        const int rA = r0 + mi * 16, rB = rA + 8;
        float bmA = 0.f, bmB = 0.f;
        if (MODE == 0 && bias_m) { bmA = bias_m[rA]; bmB = bias_m[rB]; }
#pragma unroll
        for (int ni = 0; ni < 4; ++ni) {
            const int col = c0 + ni * 8;
            if (MODE == 1) {
                float* o = (float*)out0v + sOb * b;
                float2 u;
                u.x = acc[mi][ni][0] * alpha; u.y = acc[mi][ni][1] * alpha;
                *(float2*)(o + (size_t)rA * ldo + col) = u;
                u.x = acc[mi][ni][2] * alpha; u.y = acc[mi][ni][3] * alpha;
                *(float2*)(o + (size_t)rB * ldo + col) = u;
            } else {
                fp16* oh = (fp16*)out0v + sOb * b;
                fp16* ol = (fp16*)out1v + sOb * b;
                float bn0 = 0.f, bn1 = 0.f;
                if (bias_n) { bn0 = bias_n[col]; bn1 = bias_n[col + 1]; }
                float v0 = acc[mi][ni][0] + bmA + bn0;
                float v1 = acc[mi][ni][1] + bmA + bn1;
                float v2 = acc[mi][ni][2] + bmB + bn0;
                float v3 = acc[mi][ni][3] + bmB + bn1;
                fp16 h0, l0, h1, l1, h2, l2, h3, l3;
                split_h(v0, h0, l0); split_h(v1, h1, l1);
                split_h(v2, h2, l2); split_h(v3, h3, l3);
                *(__half2*)(oh + (size_t)rA * ldo + col) = __halves2half2(h0, h1);
                *(__half2*)(ol + (size_t)rA * ldo + col) = __halves2half2(l0, l1);
                *(__half2*)(oh + (size_t)rB * ldo + col) = __halves2half2(h2, h3);
                *(__half2*)(ol + (size_t)rB * ldo + col) = __halves2half2(l2, l3);
            }
        }
    }
}

// ---------------------------------------------------------------------------
// Row softmax: f32 in/out on attn, plus fp16 hi/lo pair for the final GEMM
// ---------------------------------------------------------------------------
__global__ void softmax_kernel(float* __restrict__ attn,
                               fp16* __restrict__ ah, fp16* __restrict__ al)
{
    const size_t roff = (size_t)blockIdx.x * NPIX;
    float* p = attn + roff;
    const int t = threadIdx.x;
    float v[16];
    float mx = -1e30f;
#pragma unroll
    for (int j = 0; j < 16; ++j) {
        v[j] = p[t + 256 * j];
        mx = fmaxf(mx, v[j]);
    }
    __shared__ float sred[8];
#pragma unroll
    for (int o = 16; o; o >>= 1)
        mx = fmaxf(mx, __shfl_xor_sync(0xffffffffu, mx, o));
    if ((t & 31) == 0) sred[t >> 5] = mx;
    __syncthreads();
    mx = sred[0];
#pragma unroll
    for (int k = 1; k < 8; ++k) mx = fmaxf(mx, sred[k]);

    float s = 0.f;
#pragma unroll
    for (int j = 0; j < 16; ++j) {
        v[j] = __expf(v[j] - mx);
        s += v[j];
    }
#pragma unroll
    for (int o = 16; o; o >>= 1)
        s += __shfl_xor_sync(0xffffffffu, s, o);
    __syncthreads();
    if ((t & 31) == 0) sred[t >> 5] = s;
    __syncthreads();
    s = 0.f;
#pragma unroll
    for (int k = 0; k < 8; ++k) s += sred[k];

    const float inv = 1.f / s;
#pragma unroll
    for (int j = 0; j < 16; ++j) {
        const int idx = t + 256 * j;
        float o = v[j] * inv;
        p[idx] = o;
        fp16 h, l; split_h(o, h, l);
        ah[roff + idx] = h;
        al[roff + idx] = l;
    }
}

// ---------------------------------------------------------------------------
// kernel_launch
// Inputs: f_rgb, f_i, wq, bq, wk, bk, wv, bv
// Output: [f_final | f_rgb | f_i | attn] fp32
// ---------------------------------------------------------------------------
extern "C" void kernel_launch(void* const* d_in, const int* in_sizes, int n_in,
                              void* d_out, int out_size)
{
    const float* f_rgb = (const float*)d_in[0];
    const float* f_i   = (const float*)d_in[1];
    const float* wq    = (const float*)d_in[2];
    const float* bq    = (const float*)d_in[3];
    const float* wk    = (const float*)d_in[4];
    const float* bk    = (const float*)d_in[5];
    const float* wv    = (const float*)d_in[6];
    const float* bv    = (const float*)d_in[7];
    float* out = (float*)d_out;

    cudaFuncSetAttribute(hgemm<0>, cudaFuncAttributeMaxDynamicSharedMemorySize, GEMM_SMEM);
    cudaFuncSetAttribute(hgemm<1>, cudaFuncAttributeMaxDynamicSharedMemorySize, GEMM_SMEM);

    fp16 *Xh, *Xl, *qh, *ql, *kh, *kl, *vh, *vl;
    fp16 *Qh, *Ql, *Kh, *Kl, *Vh, *Vl, *Ath, *Atl;
    float* bv2;
    cudaGetSymbolAddress((void**)&Xh,  g_Xt_h);
    cudaGetSymbolAddress((void**)&Xl,  g_Xt_l);
    cudaGetSymbolAddress((void**)&qh,  g_wq_h);
    cudaGetSymbolAddress((void**)&ql,  g_wq_l);
    cudaGetSymbolAddress((void**)&kh,  g_wk_h);
    cudaGetSymbolAddress((void**)&kl,  g_wk_l);
    cudaGetSymbolAddress((void**)&vh,  g_wv2_h);
    cudaGetSymbolAddress((void**)&vl,  g_wv2_l);
    cudaGetSymbolAddress((void**)&Qh,  g_Qt_h);
    cudaGetSymbolAddress((void**)&Ql,  g_Qt_l);
    cudaGetSymbolAddress((void**)&Kh,  g_Kt_h);
    cudaGetSymbolAddress((void**)&Kl,  g_Kt_l);
    cudaGetSymbolAddress((void**)&Vh,  g_V2_h);
    cudaGetSymbolAddress((void**)&Vl,  g_V2_l);
    cudaGetSymbolAddress((void**)&Ath, g_At_h);
    cudaGetSymbolAddress((void**)&Atl, g_At_l);
    cudaGetSymbolAddress((void**)&bv2, g_bv2);

    float* f_final = out;
    float* attn    = out + (size_t)3 * BATCH * C2 * NPIX;

    const size_t sX = (size_t)NPIX * 2 * C2;
    const size_t sQ = (size_t)NPIX * C2;
    const size_t sS = (size_t)NPIX * NPIX;

    // 1) copies + transpose/split X
    pack_transpose_kernel<<<dim3(NPIX / 32, C2 / 32, BATCH * 2), dim3(32, 8)>>>(
        f_rgb, f_i, out);
    // 2) weight split / fold
    weights_prep_kernel<<<(unsigned)((size_t)C2 * 2 * C2 / 256), 256>>>(wq, wk, wv, bv);

    // 3) projections: Qt[pix][ch], Kt[pix][ch], V2[ch][pix]
    hgemm<0><<<dim3(C2 / 128, NPIX / 128, BATCH), 256, GEMM_SMEM>>>(
        Xh, Xl, qh, ql, sX, 0, 2 * C2, Qh, Ql, C2, sQ, 1.f, nullptr, bq);
    hgemm<0><<<dim3(C2 / 128, NPIX / 128, BATCH), 256, GEMM_SMEM>>>(
        Xh, Xl, kh, kl, sX, 0, 2 * C2, Kh, Kl, C2, sQ, 1.f, nullptr, bk);
    hgemm<0><<<dim3(NPIX / 128, C2 / 128, BATCH), 256, GEMM_SMEM>>>(
        vh, vl, Xh, Xl, 0, sX, 2 * C2, Vh, Vl, NPIX, sQ, 1.f, bv2, nullptr);

    // 4) scores S[n][m] = QK/64 (f32 into attn region)
    hgemm<1><<<dim3(NPIX / 128, NPIX / 128, BATCH), 256, GEMM_SMEM>>>(
        Qh, Ql, Kh, Kl, sQ, sQ, C2, attn, nullptr, NPIX, sS, 1.f / 64.f,
        nullptr, nullptr);

    // 5) softmax (f32 out + fp16 pair)
    softmax_kernel<<<BATCH * NPIX, 256>>>(attn, Ath, Atl);

    // 6) f_final[c][n] = sum_m V2[c,m] attn[n,m]  (row-major f32 out)
    hgemm<1><<<dim3(NPIX / 128, C2 / 128, BATCH), 256, GEMM_SMEM>>>(
        Vh, Vl, Ath, Atl, sQ, sS, NPIX, f_final, nullptr, NPIX, sQ, 1.f,
        nullptr, nullptr);
}

// round 6
// speedup vs baseline: 1.7223x; 1.5177x over previous
#include <cuda_runtime.h>
#include <cuda_fp16.h>
#include <cstdint>

#define C2    2048
#define NPIX  4096
#define BATCH 2

typedef __half fp16;

// ---------------------------------------------------------------------------
// Static device scratch (no allocations anywhere)
// ---------------------------------------------------------------------------
__device__ fp16 g_Xt_h[(size_t)BATCH * NPIX * 2 * C2];   // [b][pix][4096 ch]
__device__ fp16 g_Xt_l[(size_t)BATCH * NPIX * 2 * C2];
__device__ fp16 g_wq_h[(size_t)C2 * 2 * C2];
__device__ fp16 g_wq_l[(size_t)C2 * 2 * C2];
__device__ fp16 g_wk_h[(size_t)C2 * 2 * C2];
__device__ fp16 g_wk_l[(size_t)C2 * 2 * C2];
__device__ fp16 g_wv2_h[(size_t)C2 * 2 * C2];            // folded V weights (hi only)
__device__ float g_bv2[C2];
__device__ fp16 g_Qt_h[(size_t)BATCH * NPIX * C2];       // [b][pix][ch] (hi only)
__device__ fp16 g_Kt_h[(size_t)BATCH * NPIX * C2];
__device__ fp16 g_Kt_l[(size_t)BATCH * NPIX * C2];
__device__ fp16 g_V2_h[(size_t)BATCH * C2 * NPIX];       // [b][ch][pix] (hi only)
__device__ fp16 g_At_h[(size_t)BATCH * NPIX * NPIX];     // attn fp16 pair
__device__ fp16 g_At_l[(size_t)BATCH * NPIX * NPIX];

// ---------------------------------------------------------------------------
// helpers
// ---------------------------------------------------------------------------
__device__ __forceinline__ uint32_t smem_u32(const void* p) {
    uint32_t a;
    asm("{ .reg .u64 t; cvta.to.shared.u64 t, %1; cvt.u32.u64 %0, t; }"
        : "=r"(a) : "l"(p));
    return a;
}
__device__ __forceinline__ uint32_t swz(uint32_t b) {       // 128B-row swizzle
    return b ^ ((b >> 3) & 0x70);
}
__device__ __forceinline__ void cp_async16(uint32_t dst, const void* src) {
    asm volatile("cp.async.cg.shared.global [%0], [%1], 16;\n"
                 :: "r"(dst), "l"(src) : "memory");
}
__device__ __forceinline__ void ldsm_x4(uint32_t* r, uint32_t addr) {
    asm volatile("ldmatrix.sync.aligned.m8n8.x4.shared.b16 {%0,%1,%2,%3}, [%4];"
                 : "=r"(r[0]), "=r"(r[1]), "=r"(r[2]), "=r"(r[3]) : "r"(addr));
}
__device__ __forceinline__ void mma16816(float* d, const uint32_t* a,
                                         const uint32_t* b) {
    asm volatile(
        "mma.sync.aligned.m16n8k16.row.col.f32.f16.f16.f32 "
        "{%0,%1,%2,%3}, {%4,%5,%6,%7}, {%8,%9}, {%0,%1,%2,%3};"
        : "+f"(d[0]), "+f"(d[1]), "+f"(d[2]), "+f"(d[3])
        : "r"(a[0]), "r"(a[1]), "r"(a[2]), "r"(a[3]), "r"(b[0]), "r"(b[1]));
}
__device__ __forceinline__ void split_h(float v, fp16& h, fp16& l) {
    h = __float2half_rn(v);
    l = __float2half_rn(v - __half2float(h));
}

// ---------------------------------------------------------------------------
// Pack + transpose: f_rgb/f_i -> fp32 output copies and Xt hi/lo (fp16)
// ---------------------------------------------------------------------------
__global__ void pack_transpose_kernel(const float* __restrict__ frgb,
                                      const float* __restrict__ fi,
                                      float* __restrict__ out)
{
    __shared__ float tile[32][33];
    const int s = blockIdx.z & 1, b = blockIdx.z >> 1;
    const float* src = s ? fi : frgb;
    const int pix0 = blockIdx.x * 32, ch0 = blockIdx.y * 32;
    const size_t base = (size_t)b * C2 * NPIX;
    const size_t PER  = (size_t)BATCH * C2 * NPIX;
    const int tx = threadIdx.x, ty = threadIdx.y;
#pragma unroll
    for (int i = 0; i < 4; ++i) {
        const int ch = ch0 + ty + i * 8;
        const size_t idx = base + (size_t)ch * NPIX + pix0 + tx;
        float v = src[idx];
        out[PER * (1 + s) + idx] = v;          // f_rgb / f_i copy
        tile[ty + i * 8][tx] = v;
    }
    __syncthreads();
    const size_t xbase = (size_t)b * NPIX * (2 * C2) + (size_t)s * C2;
#pragma unroll
    for (int i = 0; i < 4; ++i) {
        const int pix = pix0 + ty + i * 8;
        float v = tile[tx][ty + i * 8];
        fp16 h, l; split_h(v, h, l);
        const size_t idx = xbase + (size_t)pix * (2 * C2) + ch0 + tx;
        g_Xt_h[idx] = h;
        g_Xt_l[idx] = l;
    }
}

// ---------------------------------------------------------------------------
// Weight prep: split wq/wk (hi+lo), fold wv -> hi only, fold bv
// ---------------------------------------------------------------------------
__global__ void weights_prep_kernel(const float* __restrict__ wq,
                                    const float* __restrict__ wk,
                                    const float* __restrict__ wv,
                                    const float* __restrict__ bv)
{
    const size_t NW = (size_t)C2 * 2 * C2;
    size_t i = (size_t)blockIdx.x * blockDim.x + threadIdx.x;
    if (i < NW) {
        fp16 h, l;
        split_h(wq[i], h, l);  g_wq_h[i] = h;  g_wq_l[i] = l;
        split_h(wk[i], h, l);  g_wk_h[i] = h;  g_wk_l[i] = l;
        g_wv2_h[i] = __float2half_rn(wv[i] + wv[i + NW]);
    }
    if (i < C2) g_bv2[i] = bv[i] + bv[i + C2];
}

// ---------------------------------------------------------------------------
// HMMA GEMM:  D[M,N] = alpha * A[M,K] @ B[N,K]^T (+bias)
// 2-product split: D ~= Ah*Bh + Ah*Bl  (A carries hi only)
// CTA tile 128x128, kTile 64, 8 warps (warp tile 64x32), 3-stage cp.async
// ring with wait_group 1; pass-ordered MMAs (acc reuse distance 16).
// MODE 0: out fp16 hi (+lo if out1v), row-major; MODE 1: out f32 * alpha.
// ---------------------------------------------------------------------------
static constexpr int TILE16K   = 16384;          // one 128x64 fp16 tile
static constexpr int STAGE_B   = 3 * TILE16K;    // Ah, Bh, Bl = 48KB
static constexpr int GEMM_SMEM = 3 * STAGE_B + 128;

template<int MODE>
__global__ void __launch_bounds__(256, 1)
hgemm(const fp16* __restrict__ Ah,
      const fp16* __restrict__ Bh, const fp16* __restrict__ Bl,
      size_t sAb, size_t sBb, int K,
      void* __restrict__ out0v, void* __restrict__ out1v,
      int ldo, size_t sOb, float alpha,
      const float* __restrict__ bias_m, const float* __restrict__ bias_n)
{
    extern __shared__ __align__(128) char dsm[];
    const uint32_t smbase = (smem_u32(dsm) + 127u) & ~127u;

    const int tid  = threadIdx.x;
    const int lane = tid & 31, warp = tid >> 5;
    const int m0 = blockIdx.y * 128;
    const int n0 = blockIdx.x * 128;
    const int b  = blockIdx.z;
    Ah += sAb * b;
    Bh += sBb * b;  Bl += sBb * b;

    const int wm = (warp >> 2) * 64;     // warp M offset
    const int wn = (warp & 3) * 32;      // warp N offset

    float acc[4][4][4];
#pragma unroll
    for (int i = 0; i < 4; ++i)
#pragma unroll
        for (int j = 0; j < 4; ++j)
#pragma unroll
            for (int q = 0; q < 4; ++q) acc[i][j][q] = 0.f;

    // ---- hoisted ldmatrix addressing ----
    const int arow = wm + (lane & 15);
    const int brow = wn + (lane & 15);
    const uint32_t hk  = (uint32_t)(lane >> 4);
    const uint32_t sxa = (uint32_t)(arow & 7);
    const uint32_t sxb = (uint32_t)(brow & 7);
    uint32_t colA[4], colB[4], aoff[4];
#pragma unroll
    for (int kc = 0; kc < 4; ++kc) {
        colA[kc] = (((uint32_t)(kc * 2) + hk) ^ sxa) << 4;
        colB[kc] = (((uint32_t)(kc * 2) + hk) ^ sxb) << 4;
    }
#pragma unroll
    for (int mi = 0; mi < 4; ++mi) aoff[mi] = (uint32_t)((arow + mi * 16) * 128);
    const uint32_t boff0 = (uint32_t)(brow * 128);
    const uint32_t boff1 = (uint32_t)((brow + 16) * 128);

    // ---- hoisted cp.async addressing ----
    const int r0t = tid >> 3;                         // row 0..31 (first chunk)
    const int c8  = (tid & 7) * 8;                    // fp16 col of 16B chunk
    const size_t gA0 = (size_t)(m0 + r0t) * K + c8;
    const size_t gB0 = (size_t)(n0 + r0t) * K + c8;
    const size_t gstep = (size_t)32 * K;              // +32 rows per chunk
    const uint32_t soff0 = swz((uint32_t)(r0t * 128 + (tid & 7) * 16));

    const int NK = K / 64;

    auto load_stage = [&](int kt, int slot) {
        if (kt < NK) {
            const uint32_t sb = smbase + (uint32_t)slot * STAGE_B;
            const int k0 = kt * 64;
            const fp16* pAh = Ah + gA0 + k0;
            const fp16* pBh = Bh + gB0 + k0;
            const fp16* pBl = Bl + gB0 + k0;
#pragma unroll
            for (int j = 0; j < 4; ++j) {
                const uint32_t so = soff0 + (uint32_t)(j * 4096);
                const size_t go = (size_t)j * gstep;
                cp_async16(sb + so,               pAh + go);
                cp_async16(sb + TILE16K + so,     pBh + go);
                cp_async16(sb + 2 * TILE16K + so, pBl + go);
            }
        }
        asm volatile("cp.async.commit_group;" ::: "memory");
    };

    load_stage(0, 0);
    load_stage(1, 1);
    int cur = 0, wr = 2;

    for (int kt = 0; kt < NK; ++kt) {
        asm volatile("cp.async.wait_group 1;" ::: "memory");
        __syncthreads();
        load_stage(kt + 2, wr);
        wr = (wr == 2) ? 0 : wr + 1;

        const uint32_t sb = smbase + (uint32_t)cur * STAGE_B;
        cur = (cur == 2) ? 0 : cur + 1;
        const uint32_t aH = sb;
        const uint32_t bH = sb + TILE16K, bL = sb + 2 * TILE16K;

#pragma unroll
        for (int kc = 0; kc < 4; ++kc) {
            const uint32_t cA = colA[kc], cB = colB[kc];
            uint32_t a1[4][4], b1[4][2], b2[4][2], t[4];

#pragma unroll
            for (int mi = 0; mi < 4; ++mi)
                ldsm_x4(a1[mi], aH + aoff[mi] + cA);
            ldsm_x4(t, bH + boff0 + cB);
            b1[0][0] = t[0]; b1[0][1] = t[2]; b1[1][0] = t[1]; b1[1][1] = t[3];
            ldsm_x4(t, bH + boff1 + cB);
            b1[2][0] = t[0]; b1[2][1] = t[2]; b1[3][0] = t[1]; b1[3][1] = t[3];
#pragma unroll
            for (int mi = 0; mi < 4; ++mi)
#pragma unroll
                for (int ni = 0; ni < 4; ++ni)
                    mma16816(acc[mi][ni], a1[mi], b1[ni]);      // hh

            ldsm_x4(t, bL + boff0 + cB);
            b2[0][0] = t[0]; b2[0][1] = t[2]; b2[1][0] = t[1]; b2[1][1] = t[3];
            ldsm_x4(t, bL + boff1 + cB);
            b2[2][0] = t[0]; b2[2][1] = t[2]; b2[3][0] = t[1]; b2[3][1] = t[3];
#pragma unroll
            for (int mi = 0; mi < 4; ++mi)
#pragma unroll
                for (int ni = 0; ni < 4; ++ni)
                    mma16816(acc[mi][ni], a1[mi], b2[ni]);      // hl
        }
    }

    // ------------------------------- epilogue ------------------------------
    const int r0 = m0 + wm + (lane >> 2);
    const int c0 = n0 + wn + (lane & 3) * 2;
#pragma unroll
    for (int mi = 0; mi < 4; ++mi) {
        const int rA = r0 + mi * 16, rB = rA + 8;
        float bmA = 0.f, bmB = 0.f;
        if (MODE == 0 && bias_m) { bmA = bias_m[rA]; bmB = bias_m[rB]; }
#pragma unroll
        for (int ni = 0; ni < 4; ++ni) {
            const int col = c0 + ni * 8;
            if (MODE == 1) {
                float* o = (float*)out0v + sOb * b;
                float2 u;
                u.x = acc[mi][ni][0] * alpha; u.y = acc[mi][ni][1] * alpha;
                *(float2*)(o + (size_t)rA * ldo + col) = u;
                u.x = acc[mi][ni][2] * alpha; u.y = acc[mi][ni][3] * alpha;
                *(float2*)(o + (size_t)rB * ldo + col) = u;
            } else {
                fp16* oh = (fp16*)out0v + sOb * b;
                float bn0 = 0.f, bn1 = 0.f;
                if (bias_n) { bn0 = bias_n[col]; bn1 = bias_n[col + 1]; }
                float v0 = acc[mi][ni][0] + bmA + bn0;
                float v1 = acc[mi][ni][1] + bmA + bn1;
                float v2 = acc[mi][ni][2] + bmB + bn0;
                float v3 = acc[mi][ni][3] + bmB + bn1;
                fp16 h0, l0, h1, l1, h2, l2, h3, l3;
                split_h(v0, h0, l0); split_h(v1, h1, l1);
                split_h(v2, h2, l2); split_h(v3, h3, l3);
                *(__half2*)(oh + (size_t)rA * ldo + col) = __halves2half2(h0, h1);
                *(__half2*)(oh + (size_t)rB * ldo + col) = __halves2half2(h2, h3);
                if (out1v) {
                    fp16* ol = (fp16*)out1v + sOb * b;
                    *(__half2*)(ol + (size_t)rA * ldo + col) = __halves2half2(l0, l1);
                    *(__half2*)(ol + (size_t)rB * ldo + col) = __halves2half2(l2, l3);
                }
            }
        }
    }
}

// ---------------------------------------------------------------------------
// Row softmax: f32 in/out on attn, plus fp16 hi/lo pair for the final GEMM
// ---------------------------------------------------------------------------
__global__ void softmax_kernel(float* __restrict__ attn,
                               fp16* __restrict__ ah, fp16* __restrict__ al)
{
    const size_t roff = (size_t)blockIdx.x * NPIX;
    float* p = attn + roff;
    const int t = threadIdx.x;
    float v[16];
    float mx = -1e30f;
#pragma unroll
    for (int j = 0; j < 16; ++j) {
        v[j] = p[t + 256 * j];
        mx = fmaxf(mx, v[j]);
    }
    __shared__ float sred[8];
#pragma unroll
    for (int o = 16; o; o >>= 1)
        mx = fmaxf(mx, __shfl_xor_sync(0xffffffffu, mx, o));
    if ((t & 31) == 0) sred[t >> 5] = mx;
    __syncthreads();
    mx = sred[0];
#pragma unroll
    for (int k = 1; k < 8; ++k) mx = fmaxf(mx, sred[k]);

    float s = 0.f;
#pragma unroll
    for (int j = 0; j < 16; ++j) {
        v[j] = __expf(v[j] - mx);
        s += v[j];
    }
#pragma unroll
    for (int o = 16; o; o >>= 1)
        s += __shfl_xor_sync(0xffffffffu, s, o);
    __syncthreads();
    if ((t & 31) == 0) sred[t >> 5] = s;
    __syncthreads();
    s = 0.f;
#pragma unroll
    for (int k = 0; k < 8; ++k) s += sred[k];

    const float inv = 1.f / s;
#pragma unroll
    for (int j = 0; j < 16; ++j) {
        const int idx = t + 256 * j;
        float o = v[j] * inv;
        p[idx] = o;
        fp16 h, l; split_h(o, h, l);
        ah[roff + idx] = h;
        al[roff + idx] = l;
    }
}

// ---------------------------------------------------------------------------
// kernel_launch
// Inputs: f_rgb, f_i, wq, bq, wk, bk, wv, bv
// Output: [f_final | f_rgb | f_i | attn] fp32
// ---------------------------------------------------------------------------
extern "C" void kernel_launch(void* const* d_in, const int* in_sizes, int n_in,
                              void* d_out, int out_size)
{
    const float* f_rgb = (const float*)d_in[0];
    const float* f_i   = (const float*)d_in[1];
    const float* wq    = (const float*)d_in[2];
    const float* bq    = (const float*)d_in[3];
    const float* wk    = (const float*)d_in[4];
    const float* bk    = (const float*)d_in[5];
    const float* wv    = (const float*)d_in[6];
    const float* bv    = (const float*)d_in[7];
    float* out = (float*)d_out;

    cudaFuncSetAttribute(hgemm<0>, cudaFuncAttributeMaxDynamicSharedMemorySize, GEMM_SMEM);
    cudaFuncSetAttribute(hgemm<1>, cudaFuncAttributeMaxDynamicSharedMemorySize, GEMM_SMEM);

    fp16 *Xh, *Xl, *qh, *ql, *kh, *kl, *vh;
    fp16 *Qh, *Kh, *Kl, *Vh, *Ath, *Atl;
    float* bv2;
    cudaGetSymbolAddress((void**)&Xh,  g_Xt_h);
    cudaGetSymbolAddress((void**)&Xl,  g_Xt_l);
    cudaGetSymbolAddress((void**)&qh,  g_wq_h);
    cudaGetSymbolAddress((void**)&ql,  g_wq_l);
    cudaGetSymbolAddress((void**)&kh,  g_wk_h);
    cudaGetSymbolAddress((void**)&kl,  g_wk_l);
    cudaGetSymbolAddress((void**)&vh,  g_wv2_h);
    cudaGetSymbolAddress((void**)&Qh,  g_Qt_h);
    cudaGetSymbolAddress((void**)&Kh,  g_Kt_h);
    cudaGetSymbolAddress((void**)&Kl,  g_Kt_l);
    cudaGetSymbolAddress((void**)&Vh,  g_V2_h);
    cudaGetSymbolAddress((void**)&Ath, g_At_h);
    cudaGetSymbolAddress((void**)&Atl, g_At_l);
    cudaGetSymbolAddress((void**)&bv2, g_bv2);

    float* f_final = out;
    float* attn    = out + (size_t)3 * BATCH * C2 * NPIX;

    const size_t sX = (size_t)NPIX * 2 * C2;
    const size_t sQ = (size_t)NPIX * C2;
    const size_t sS = (size_t)NPIX * NPIX;

    // 1) copies + transpose/split X
    pack_transpose_kernel<<<dim3(NPIX / 32, C2 / 32, BATCH * 2), dim3(32, 8)>>>(
        f_rgb, f_i, out);
    // 2) weight split / fold
    weights_prep_kernel<<<(unsigned)((size_t)C2 * 2 * C2 / 256), 256>>>(wq, wk, wv, bv);

    // 3) projections: Qt[pix][ch] (hi), Kt[pix][ch] (hi+lo), V2[ch][pix] (hi)
    hgemm<0><<<dim3(C2 / 128, NPIX / 128, BATCH), 256, GEMM_SMEM>>>(
        Xh, qh, ql, sX, 0, 2 * C2, Qh, nullptr, C2, sQ, 1.f, nullptr, bq);
    hgemm<0><<<dim3(C2 / 128, NPIX / 128, BATCH), 256, GEMM_SMEM>>>(
        Xh, kh, kl, sX, 0, 2 * C2, Kh, Kl, C2, sQ, 1.f, nullptr, bk);
    hgemm<0><<<dim3(NPIX / 128, C2 / 128, BATCH), 256, GEMM_SMEM>>>(
        vh, Xh, Xl, 0, sX, 2 * C2, Vh, nullptr, NPIX, sQ, 1.f, bv2, nullptr);

    // 4) scores S[n][m] = QK/64 (f32 into attn region)
    hgemm<1><<<dim3(NPIX / 128, NPIX / 128, BATCH), 256, GEMM_SMEM>>>(
        Qh, Kh, Kl, sQ, sQ, C2, attn, nullptr, NPIX, sS, 1.f / 64.f,
        nullptr, nullptr);

    // 5) softmax (f32 out + fp16 pair)
    softmax_kernel<<<BATCH * NPIX, 256>>>(attn, Ath, Atl);

    // 6) f_final[c][n] = sum_m V2[c,m] attn[n,m]  (row-major f32 out)
    hgemm<1><<<dim3(NPIX / 128, C2 / 128, BATCH), 256, GEMM_SMEM>>>(
        Vh, Ath, Atl, sQ, sS, NPIX, f_final, nullptr, NPIX, sQ, 1.f,
        nullptr, nullptr);
}

// round 7
// speedup vs baseline: 1.8967x; 1.1013x over previous
#include <cuda_runtime.h>
#include <cuda_fp16.h>
#include <cstdint>

#define C2    2048
#define NPIX  4096
#define BATCH 2

typedef __half fp16;

// ---------------------------------------------------------------------------
// Static device scratch (no allocations anywhere)
// ---------------------------------------------------------------------------
__device__ fp16 g_Xt_h[(size_t)BATCH * NPIX * 2 * C2];   // [b][pix][4096 ch]
__device__ fp16 g_Xt_l[(size_t)BATCH * NPIX * 2 * C2];
__device__ fp16 g_wq_h[(size_t)C2 * 2 * C2];
__device__ fp16 g_wq_l[(size_t)C2 * 2 * C2];
__device__ fp16 g_wk_h[(size_t)C2 * 2 * C2];
__device__ fp16 g_wk_l[(size_t)C2 * 2 * C2];
__device__ fp16 g_wv2_h[(size_t)C2 * 2 * C2];            // folded V weights (hi only)
__device__ float g_bv2[C2];
__device__ fp16 g_Qt_h[(size_t)BATCH * NPIX * C2];       // [b][pix][ch] (hi only)
__device__ fp16 g_Kt_h[(size_t)BATCH * NPIX * C2];
__device__ fp16 g_Kt_l[(size_t)BATCH * NPIX * C2];
__device__ fp16 g_V2_h[(size_t)BATCH * C2 * NPIX];       // [b][ch][pix] (hi only)
__device__ fp16 g_At_h[(size_t)BATCH * NPIX * NPIX];     // attn fp16 pair
__device__ fp16 g_At_l[(size_t)BATCH * NPIX * NPIX];

// ---------------------------------------------------------------------------
// helpers
// ---------------------------------------------------------------------------
__device__ __forceinline__ uint32_t smem_u32(const void* p) {
    uint32_t a;
    asm("{ .reg .u64 t; cvta.to.shared.u64 t, %1; cvt.u32.u64 %0, t; }"
        : "=r"(a) : "l"(p));
    return a;
}
__device__ __forceinline__ uint32_t swz(uint32_t b) {       // 128B-row swizzle
    return b ^ ((b >> 3) & 0x70);
}
__device__ __forceinline__ void cp_async16(uint32_t dst, const void* src) {
    asm volatile("cp.async.cg.shared.global [%0], [%1], 16;\n"
                 :: "r"(dst), "l"(src) : "memory");
}
__device__ __forceinline__ void ldsm_x4(uint32_t* r, uint32_t addr) {
    asm volatile("ldmatrix.sync.aligned.m8n8.x4.shared.b16 {%0,%1,%2,%3}, [%4];"
                 : "=r"(r[0]), "=r"(r[1]), "=r"(r[2]), "=r"(r[3]) : "r"(addr));
}
__device__ __forceinline__ void mma16816(float* d, const uint32_t* a,
                                         const uint32_t* b) {
    asm volatile(
        "mma.sync.aligned.m16n8k16.row.col.f32.f16.f16.f32 "
        "{%0,%1,%2,%3}, {%4,%5,%6,%7}, {%8,%9}, {%0,%1,%2,%3};"
        : "+f"(d[0]), "+f"(d[1]), "+f"(d[2]), "+f"(d[3])
        : "r"(a[0]), "r"(a[1]), "r"(a[2]), "r"(a[3]), "r"(b[0]), "r"(b[1]));
}
__device__ __forceinline__ void split_h(float v, fp16& h, fp16& l) {
    h = __float2half_rn(v);
    l = __float2half_rn(v - __half2float(h));
}

// ---------------------------------------------------------------------------
// Pack + transpose: f_rgb/f_i -> fp32 output copies and Xt hi/lo (fp16)
// ---------------------------------------------------------------------------
__global__ void pack_transpose_kernel(const float* __restrict__ frgb,
                                      const float* __restrict__ fi,
                                      float* __restrict__ out)
{
    __shared__ float tile[32][33];
    const int s = blockIdx.z & 1, b = blockIdx.z >> 1;
    const float* src = s ? fi : frgb;
    const int pix0 = blockIdx.x * 32, ch0 = blockIdx.y * 32;
    const size_t base = (size_t)b * C2 * NPIX;
    const size_t PER  = (size_t)BATCH * C2 * NPIX;
    const int tx = threadIdx.x, ty = threadIdx.y;
#pragma unroll
    for (int i = 0; i < 4; ++i) {
        const int ch = ch0 + ty + i * 8;
        const size_t idx = base + (size_t)ch * NPIX + pix0 + tx;
        float v = src[idx];
        out[PER * (1 + s) + idx] = v;          // f_rgb / f_i copy
        tile[ty + i * 8][tx] = v;
    }
    __syncthreads();
    const size_t xbase = (size_t)b * NPIX * (2 * C2) + (size_t)s * C2;
#pragma unroll
    for (int i = 0; i < 4; ++i) {
        const int pix = pix0 + ty + i * 8;
        float v = tile[tx][ty + i * 8];
        fp16 h, l; split_h(v, h, l);
        const size_t idx = xbase + (size_t)pix * (2 * C2) + ch0 + tx;
        g_Xt_h[idx] = h;
        g_Xt_l[idx] = l;
    }
}

// ---------------------------------------------------------------------------
// Weight prep: split wq/wk (hi+lo), fold wv -> hi only, fold bv
// ---------------------------------------------------------------------------
__global__ void weights_prep_kernel(const float* __restrict__ wq,
                                    const float* __restrict__ wk,
                                    const float* __restrict__ wv,
                                    const float* __restrict__ bv)
{
    const size_t NW = (size_t)C2 * 2 * C2;
    size_t i = (size_t)blockIdx.x * blockDim.x + threadIdx.x;
    if (i < NW) {
        fp16 h, l;
        split_h(wq[i], h, l);  g_wq_h[i] = h;  g_wq_l[i] = l;
        split_h(wk[i], h, l);  g_wk_h[i] = h;  g_wk_l[i] = l;
        g_wv2_h[i] = __float2half_rn(wv[i] + wv[i + NW]);
    }
    if (i < C2) g_bv2[i] = bv[i] + bv[i + C2];
}

// ---------------------------------------------------------------------------
// HMMA GEMM:  D[M,N] = alpha * A[M,K] @ B[N,K]^T (+bias)
// 2-product split: D ~= Ah*Bh + Ah*Bl  (A carries hi only)
// CTA tile 128x128, kTile 64, 8 warps (warp tile 64x32), 2-stage cp.async
// (96KB smem) -> 2 CTAs/SM for cross-CTA bubble hiding.
// MODE 0: out fp16 hi (+lo if out1v), row-major; MODE 1: out f32 * alpha.
// ---------------------------------------------------------------------------
static constexpr int TILE16K   = 16384;          // one 128x64 fp16 tile
static constexpr int STAGE_B   = 3 * TILE16K;    // Ah, Bh, Bl = 48KB
static constexpr int GEMM_SMEM = 2 * STAGE_B + 128;

template<int MODE>
__global__ void __launch_bounds__(256, 2)
hgemm(const fp16* __restrict__ Ah,
      const fp16* __restrict__ Bh, const fp16* __restrict__ Bl,
      size_t sAb, size_t sBb, int K,
      void* __restrict__ out0v, void* __restrict__ out1v,
      int ldo, size_t sOb, float alpha,
      const float* __restrict__ bias_m, const float* __restrict__ bias_n)
{
    extern __shared__ __align__(128) char dsm[];
    const uint32_t smbase = (smem_u32(dsm) + 127u) & ~127u;

    const int tid  = threadIdx.x;
    const int lane = tid & 31, warp = tid >> 5;
    const int m0 = blockIdx.y * 128;
    const int n0 = blockIdx.x * 128;
    const int b  = blockIdx.z;
    Ah += sAb * b;
    Bh += sBb * b;  Bl += sBb * b;

    const int wm = (warp >> 2) * 64;     // warp M offset
    const int wn = (warp & 3) * 32;      // warp N offset

    float acc[4][4][4];
#pragma unroll
    for (int i = 0; i < 4; ++i)
#pragma unroll
        for (int j = 0; j < 4; ++j)
#pragma unroll
            for (int q = 0; q < 4; ++q) acc[i][j][q] = 0.f;

    // ---- hoisted ldmatrix addressing ----
    const int arow = wm + (lane & 15);
    const int brow = wn + (lane & 15);
    const uint32_t hk  = (uint32_t)(lane >> 4);
    const uint32_t sxa = (uint32_t)(arow & 7);
    const uint32_t sxb = (uint32_t)(brow & 7);
    uint32_t colA[4], colB[4], aoff[4];
#pragma unroll
    for (int kc = 0; kc < 4; ++kc) {
        colA[kc] = (((uint32_t)(kc * 2) + hk) ^ sxa) << 4;
        colB[kc] = (((uint32_t)(kc * 2) + hk) ^ sxb) << 4;
    }
#pragma unroll
    for (int mi = 0; mi < 4; ++mi) aoff[mi] = (uint32_t)((arow + mi * 16) * 128);
    const uint32_t boff0 = (uint32_t)(brow * 128);
    const uint32_t boff1 = (uint32_t)((brow + 16) * 128);

    // ---- hoisted cp.async addressing ----
    const int r0t = tid >> 3;                         // row 0..31 (first chunk)
    const int c8  = (tid & 7) * 8;                    // fp16 col of 16B chunk
    const size_t gA0 = (size_t)(m0 + r0t) * K + c8;
    const size_t gB0 = (size_t)(n0 + r0t) * K + c8;
    const size_t gstep = (size_t)32 * K;              // +32 rows per chunk
    const uint32_t soff0 = swz((uint32_t)(r0t * 128 + (tid & 7) * 16));

    const int NK = K / 64;

    auto load_stage = [&](int kt, int slot) {
        if (kt < NK) {
            const uint32_t sb = smbase + (uint32_t)slot * STAGE_B;
            const int k0 = kt * 64;
            const fp16* pAh = Ah + gA0 + k0;
            const fp16* pBh = Bh + gB0 + k0;
            const fp16* pBl = Bl + gB0 + k0;
#pragma unroll
            for (int j = 0; j < 4; ++j) {
                const uint32_t so = soff0 + (uint32_t)(j * 4096);
                const size_t go = (size_t)j * gstep;
                cp_async16(sb + so,               pAh + go);
                cp_async16(sb + TILE16K + so,     pBh + go);
                cp_async16(sb + 2 * TILE16K + so, pBl + go);
            }
        }
        asm volatile("cp.async.commit_group;" ::: "memory");
    };

    load_stage(0, 0);

    for (int kt = 0; kt < NK; ++kt) {
        const int buf = kt & 1;
        asm volatile("cp.async.wait_group 0;" ::: "memory");
        __syncthreads();
        load_stage(kt + 1, buf ^ 1);

        const uint32_t sb = smbase + (uint32_t)buf * STAGE_B;
        const uint32_t aH = sb;
        const uint32_t bH = sb + TILE16K, bL = sb + 2 * TILE16K;

#pragma unroll
        for (int kc = 0; kc < 4; ++kc) {
            const uint32_t cA = colA[kc], cB = colB[kc];
            uint32_t a1[4][4], b1[4][2], b2[4][2], t[4];

#pragma unroll
            for (int mi = 0; mi < 4; ++mi)
                ldsm_x4(a1[mi], aH + aoff[mi] + cA);
            ldsm_x4(t, bH + boff0 + cB);
            b1[0][0] = t[0]; b1[0][1] = t[2]; b1[1][0] = t[1]; b1[1][1] = t[3];
            ldsm_x4(t, bH + boff1 + cB);
            b1[2][0] = t[0]; b1[2][1] = t[2]; b1[3][0] = t[1]; b1[3][1] = t[3];
#pragma unroll
            for (int mi = 0; mi < 4; ++mi)
#pragma unroll
                for (int ni = 0; ni < 4; ++ni)
                    mma16816(acc[mi][ni], a1[mi], b1[ni]);      // hh

            ldsm_x4(t, bL + boff0 + cB);
            b2[0][0] = t[0]; b2[0][1] = t[2]; b2[1][0] = t[1]; b2[1][1] = t[3];
            ldsm_x4(t, bL + boff1 + cB);
            b2[2][0] = t[0]; b2[2][1] = t[2]; b2[3][0] = t[1]; b2[3][1] = t[3];
#pragma unroll
            for (int mi = 0; mi < 4; ++mi)
#pragma unroll
                for (int ni = 0; ni < 4; ++ni)
                    mma16816(acc[mi][ni], a1[mi], b2[ni]);      // hl
        }
        __syncthreads();
    }

    // ------------------------------- epilogue ------------------------------
    const int r0 = m0 + wm + (lane >> 2);
    const int c0 = n0 + wn + (lane & 3) * 2;
#pragma unroll
    for (int mi = 0; mi < 4; ++mi) {
        const int rA = r0 + mi * 16, rB = rA + 8;
        float bmA = 0.f, bmB = 0.f;
        if (MODE == 0 && bias_m) { bmA = bias_m[rA]; bmB = bias_m[rB]; }
#pragma unroll
        for (int ni = 0; ni < 4; ++ni) {
            const int col = c0 + ni * 8;
            if (MODE == 1) {
                float* o = (float*)out0v + sOb * b;
                float2 u;
                u.x = acc[mi][ni][0] * alpha; u.y = acc[mi][ni][1] * alpha;
                *(float2*)(o + (size_t)rA * ldo + col) = u;
                u.x = acc[mi][ni][2] * alpha; u.y = acc[mi][ni][3] * alpha;
                *(float2*)(o + (size_t)rB * ldo + col) = u;
            } else {
                fp16* oh = (fp16*)out0v + sOb * b;
                float bn0 = 0.f, bn1 = 0.f;
                if (bias_n) { bn0 = bias_n[col]; bn1 = bias_n[col + 1]; }
                float v0 = acc[mi][ni][0] + bmA + bn0;
                float v1 = acc[mi][ni][1] + bmA + bn1;
                float v2 = acc[mi][ni][2] + bmB + bn0;
                float v3 = acc[mi][ni][3] + bmB + bn1;
                fp16 h0, l0, h1, l1, h2, l2, h3, l3;
                split_h(v0, h0, l0); split_h(v1, h1, l1);
                split_h(v2, h2, l2); split_h(v3, h3, l3);
                *(__half2*)(oh + (size_t)rA * ldo + col) = __halves2half2(h0, h1);
                *(__half2*)(oh + (size_t)rB * ldo + col) = __halves2half2(h2, h3);
                if (out1v) {
                    fp16* ol = (fp16*)out1v + sOb * b;
                    *(__half2*)(ol + (size_t)rA * ldo + col) = __halves2half2(l0, l1);
                    *(__half2*)(ol + (size_t)rB * ldo + col) = __halves2half2(l2, l3);
                }
            }
        }
    }
}

// ---------------------------------------------------------------------------
// Row softmax: f32 in/out on attn, plus fp16 hi/lo pair for the final GEMM
// ---------------------------------------------------------------------------
__global__ void softmax_kernel(float* __restrict__ attn,
                               fp16* __restrict__ ah, fp16* __restrict__ al)
{
    const size_t roff = (size_t)blockIdx.x * NPIX;
    float* p = attn + roff;
    const int t = threadIdx.x;
    float v[16];
    float mx = -1e30f;
#pragma unroll
    for (int j = 0; j < 16; ++j) {
        v[j] = p[t + 256 * j];
        mx = fmaxf(mx, v[j]);
    }
    __shared__ float sred[8];
#pragma unroll
    for (int o = 16; o; o >>= 1)
        mx = fmaxf(mx, __shfl_xor_sync(0xffffffffu, mx, o));
    if ((t & 31) == 0) sred[t >> 5] = mx;
    __syncthreads();
    mx = sred[0];
#pragma unroll
    for (int k = 1; k < 8; ++k) mx = fmaxf(mx, sred[k]);

    float s = 0.f;
#pragma unroll
    for (int j = 0; j < 16; ++j) {
        v[j] = __expf(v[j] - mx);
        s += v[j];
    }
#pragma unroll
    for (int o = 16; o; o >>= 1)
        s += __shfl_xor_sync(0xffffffffu, s, o);
    __syncthreads();
    if ((t & 31) == 0) sred[t >> 5] = s;
    __syncthreads();
    s = 0.f;
#pragma unroll
    for (int k = 0; k < 8; ++k) s += sred[k];

    const float inv = 1.f / s;
#pragma unroll
    for (int j = 0; j < 16; ++j) {
        const int idx = t + 256 * j;
        float o = v[j] * inv;
        p[idx] = o;
        fp16 h, l; split_h(o, h, l);
        ah[roff + idx] = h;
        al[roff + idx] = l;
    }
}

// ---------------------------------------------------------------------------
// kernel_launch
// Inputs: f_rgb, f_i, wq, bq, wk, bk, wv, bv
// Output: [f_final | f_rgb | f_i | attn] fp32
// ---------------------------------------------------------------------------
extern "C" void kernel_launch(void* const* d_in, const int* in_sizes, int n_in,
                              void* d_out, int out_size)
{
    const float* f_rgb = (const float*)d_in[0];
    const float* f_i   = (const float*)d_in[1];
    const float* wq    = (const float*)d_in[2];
    const float* bq    = (const float*)d_in[3];
    const float* wk    = (const float*)d_in[4];
    const float* bk    = (const float*)d_in[5];
    const float* wv    = (const float*)d_in[6];
    const float* bv    = (const float*)d_in[7];
    float* out = (float*)d_out;

    cudaFuncSetAttribute(hgemm<0>, cudaFuncAttributeMaxDynamicSharedMemorySize, GEMM_SMEM);
    cudaFuncSetAttribute(hgemm<1>, cudaFuncAttributeMaxDynamicSharedMemorySize, GEMM_SMEM);

    fp16 *Xh, *Xl, *qh, *ql, *kh, *kl, *vh;
    fp16 *Qh, *Kh, *Kl, *Vh, *Ath, *Atl;
    float* bv2;
    cudaGetSymbolAddress((void**)&Xh,  g_Xt_h);
    cudaGetSymbolAddress((void**)&Xl,  g_Xt_l);
    cudaGetSymbolAddress((void**)&qh,  g_wq_h);
    cudaGetSymbolAddress((void**)&ql,  g_wq_l);
    cudaGetSymbolAddress((void**)&kh,  g_wk_h);
    cudaGetSymbolAddress((void**)&kl,  g_wk_l);
    cudaGetSymbolAddress((void**)&vh,  g_wv2_h);
    cudaGetSymbolAddress((void**)&Qh,  g_Qt_h);
    cudaGetSymbolAddress((void**)&Kh,  g_Kt_h);
    cudaGetSymbolAddress((void**)&Kl,  g_Kt_l);
    cudaGetSymbolAddress((void**)&Vh,  g_V2_h);
    cudaGetSymbolAddress((void**)&Ath, g_At_h);
    cudaGetSymbolAddress((void**)&Atl, g_At_l);
    cudaGetSymbolAddress((void**)&bv2, g_bv2);

    float* f_final = out;
    float* attn    = out + (size_t)3 * BATCH * C2 * NPIX;

    const size_t sX = (size_t)NPIX * 2 * C2;
    const size_t sQ = (size_t)NPIX * C2;
    const size_t sS = (size_t)NPIX * NPIX;

    // 1) copies + transpose/split X
    pack_transpose_kernel<<<dim3(NPIX / 32, C2 / 32, BATCH * 2), dim3(32, 8)>>>(
        f_rgb, f_i, out);
    // 2) weight split / fold
    weights_prep_kernel<<<(unsigned)((size_t)C2 * 2 * C2 / 256), 256>>>(wq, wk, wv, bv);

    // 3) projections: Qt[pix][ch] (hi), Kt[pix][ch] (hi+lo), V2[ch][pix] (hi)
    hgemm<0><<<dim3(C2 / 128, NPIX / 128, BATCH), 256, GEMM_SMEM>>>(
        Xh, qh, ql, sX, 0, 2 * C2, Qh, nullptr, C2, sQ, 1.f, nullptr, bq);
    hgemm<0><<<dim3(C2 / 128, NPIX / 128, BATCH), 256, GEMM_SMEM>>>(
        Xh, kh, kl, sX, 0, 2 * C2, Kh, Kl, C2, sQ, 1.f, nullptr, bk);
    hgemm<0><<<dim3(NPIX / 128, C2 / 128, BATCH), 256, GEMM_SMEM>>>(
        vh, Xh, Xl, 0, sX, 2 * C2, Vh, nullptr, NPIX, sQ, 1.f, bv2, nullptr);

    // 4) scores S[n][m] = QK/64 (f32 into attn region)
    hgemm<1><<<dim3(NPIX / 128, NPIX / 128, BATCH), 256, GEMM_SMEM>>>(
        Qh, Kh, Kl, sQ, sQ, C2, attn, nullptr, NPIX, sS, 1.f / 64.f,
        nullptr, nullptr);

    // 5) softmax (f32 out + fp16 pair)
    softmax_kernel<<<BATCH * NPIX, 256>>>(attn, Ath, Atl);

    // 6) f_final[c][n] = sum_m V2[c,m] attn[n,m]  (row-major f32 out)
    hgemm<1><<<dim3(NPIX / 128, C2 / 128, BATCH), 256, GEMM_SMEM>>>(
        Vh, Ath, Atl, sQ, sS, NPIX, f_final, nullptr, NPIX, sQ, 1.f,
        nullptr, nullptr);
}

// round 9
// speedup vs baseline: 2.0552x; 1.0836x over previous
#include <cuda_runtime.h>
#include <cuda_fp16.h>
#include <cstdint>

#define C2    2048
#define NPIX  4096
#define BATCH 2

typedef __half fp16;

// ---------------------------------------------------------------------------
// Static device scratch (no allocations anywhere)
// ---------------------------------------------------------------------------
__device__ fp16 g_Xt_h[(size_t)BATCH * NPIX * 2 * C2];   // [b][pix][4096 ch]
__device__ fp16 g_Xt_l[(size_t)BATCH * NPIX * 2 * C2];
__device__ fp16 g_wqk_h[(size_t)2 * C2 * 2 * C2];        // [wq;wk] fused, hi
__device__ fp16 g_wqk_l[(size_t)2 * C2 * 2 * C2];        // [wq;wk] fused, lo
__device__ fp16 g_wv2_h[(size_t)C2 * 2 * C2];            // folded V weights (hi only)
__device__ float g_bqk[2 * C2];                          // [bq;bk]
__device__ float g_bv2[C2];
__device__ fp16 g_QKt_h[(size_t)BATCH * NPIX * 2 * C2];  // [b][pix][Q 0..2047|K 2048..4095]
__device__ fp16 g_QKt_l[(size_t)BATCH * NPIX * 2 * C2];
__device__ fp16 g_V2_h[(size_t)BATCH * C2 * NPIX];       // [b][ch][pix] (hi only)
__device__ fp16 g_At_h[(size_t)BATCH * NPIX * NPIX];     // attn fp16 (hi only)

// ---------------------------------------------------------------------------
// helpers
// ---------------------------------------------------------------------------
__device__ __forceinline__ uint32_t smem_u32(const void* p) {
    uint32_t a;
    asm("{ .reg .u64 t; cvta.to.shared.u64 t, %1; cvt.u32.u64 %0, t; }"
        : "=r"(a) : "l"(p));
    return a;
}
__device__ __forceinline__ uint32_t swz(uint32_t b) {       // 128B-row swizzle
    return b ^ ((b >> 3) & 0x70);
}
__device__ __forceinline__ void cp_async16(uint32_t dst, const void* src) {
    asm volatile("cp.async.cg.shared.global [%0], [%1], 16;\n"
                 :: "r"(dst), "l"(src) : "memory");
}
__device__ __forceinline__ void ldsm_x4(uint32_t* r, uint32_t addr) {
    asm volatile("ldmatrix.sync.aligned.m8n8.x4.shared.b16 {%0,%1,%2,%3}, [%4];"
                 : "=r"(r[0]), "=r"(r[1]), "=r"(r[2]), "=r"(r[3]) : "r"(addr));
}
__device__ __forceinline__ void mma16816(float* d, const uint32_t* a,
                                         const uint32_t* b) {
    asm volatile(
        "mma.sync.aligned.m16n8k16.row.col.f32.f16.f16.f32 "
        "{%0,%1,%2,%3}, {%4,%5,%6,%7}, {%8,%9}, {%0,%1,%2,%3};"
        : "+f"(d[0]), "+f"(d[1]), "+f"(d[2]), "+f"(d[3])
        : "r"(a[0]), "r"(a[1]), "r"(a[2]), "r"(a[3]), "r"(b[0]), "r"(b[1]));
}
__device__ __forceinline__ void split_h(float v, fp16& h, fp16& l) {
    h = __float2half_rn(v);
    l = __float2half_rn(v - __half2float(h));
}

// ---------------------------------------------------------------------------
// Pack + transpose: f_rgb/f_i -> fp32 output copies and Xt hi/lo (fp16)
// ---------------------------------------------------------------------------
__global__ void pack_transpose_kernel(const float* __restrict__ frgb,
                                      const float* __restrict__ fi,
                                      float* __restrict__ out)
{
    __shared__ float tile[32][33];
    const int s = blockIdx.z & 1, b = blockIdx.z >> 1;
    const float* src = s ? fi : frgb;
    const int pix0 = blockIdx.x * 32, ch0 = blockIdx.y * 32;
    const size_t base = (size_t)b * C2 * NPIX;
    const size_t PER  = (size_t)BATCH * C2 * NPIX;
    const int tx = threadIdx.x, ty = threadIdx.y;
#pragma unroll
    for (int i = 0; i < 4; ++i) {
        const int ch = ch0 + ty + i * 8;
        const size_t idx = base + (size_t)ch * NPIX + pix0 + tx;
        float v = src[idx];
        out[PER * (1 + s) + idx] = v;          // f_rgb / f_i copy
        tile[ty + i * 8][tx] = v;
    }
    __syncthreads();
    const size_t xbase = (size_t)b * NPIX * (2 * C2) + (size_t)s * C2;
#pragma unroll
    for (int i = 0; i < 4; ++i) {
        const int pix = pix0 + ty + i * 8;
        float v = tile[tx][ty + i * 8];
        fp16 h, l; split_h(v, h, l);
        const size_t idx = xbase + (size_t)pix * (2 * C2) + ch0 + tx;
        g_Xt_h[idx] = h;
        g_Xt_l[idx] = l;
    }
}

// ---------------------------------------------------------------------------
// Weight prep: fused [wq;wk] hi/lo, fold wv -> hi only, biases
// ---------------------------------------------------------------------------
__global__ void weights_prep_kernel(const float* __restrict__ wq,
                                    const float* __restrict__ wk,
                                    const float* __restrict__ wv,
                                    const float* __restrict__ bq,
                                    const float* __restrict__ bk,
                                    const float* __restrict__ bv)
{
    const size_t NW = (size_t)C2 * 2 * C2;
    size_t i = (size_t)blockIdx.x * blockDim.x + threadIdx.x;
    if (i < NW) {
        fp16 h, l;
        split_h(wq[i], h, l);  g_wqk_h[i] = h;       g_wqk_l[i] = l;
        split_h(wk[i], h, l);  g_wqk_h[NW + i] = h;  g_wqk_l[NW + i] = l;
        g_wv2_h[i] = __float2half_rn(wv[i] + wv[i + NW]);
    }
    if (i < C2) {
        g_bqk[i]      = bq[i];
        g_bqk[C2 + i] = bk[i];
        g_bv2[i]      = bv[i] + bv[i + C2];
    }
}

// ---------------------------------------------------------------------------
// HMMA GEMM:  D[M,N] = alpha * A[M,K] @ B[N,K]^T (+bias)
// 2-product split (LO=true): D ~= Ah*Bh + Ah*Bl;  LO=false: D = Ah*Bh.
// lda/ldb: row strides of A/B (reduction length K may be smaller).
// CTA tile 128x128, kTile 64, 8 warps (warp tile 64x32), 2-stage cp.async
// (96KB smem) -> 2 CTAs/SM.
// MODE 0: out fp16 hi (+lo if out1v), row-major; MODE 1: out f32 * alpha.
// ---------------------------------------------------------------------------
static constexpr int TILE16K   = 16384;          // one 128x64 fp16 tile
static constexpr int STAGE_B   = 3 * TILE16K;    // Ah, Bh, Bl = 48KB
static constexpr int GEMM_SMEM = 2 * STAGE_B + 128;

template<int MODE, bool LO>
__global__ void __launch_bounds__(256, 2)
hgemm(const fp16* __restrict__ Ah,
      const fp16* __restrict__ Bh, const fp16* __restrict__ Bl,
      size_t sAb, size_t sBb, int lda, int ldb, int K,
      void* __restrict__ out0v, void* __restrict__ out1v,
      int ldo, size_t sOb, float alpha,
      const float* __restrict__ bias_m, const float* __restrict__ bias_n)
{
    extern __shared__ __align__(128) char dsm[];
    const uint32_t smbase = (smem_u32(dsm) + 127u) & ~127u;

    const int tid  = threadIdx.x;
    const int lane = tid & 31, warp = tid >> 5;
    const int m0 = blockIdx.y * 128;
    const int n0 = blockIdx.x * 128;
    const int b  = blockIdx.z;
    Ah += sAb * b;
    Bh += sBb * b;  if (LO) Bl += sBb * b;

    const int wm = (warp >> 2) * 64;     // warp M offset
    const int wn = (warp & 3) * 32;      // warp N offset

    float acc[4][4][4];
#pragma unroll
    for (int i = 0; i < 4; ++i)
#pragma unroll
        for (int j = 0; j < 4; ++j)
#pragma unroll
            for (int q = 0; q < 4; ++q) acc[i][j][q] = 0.f;

    // ---- hoisted ldmatrix addressing ----
    const int arow = wm + (lane & 15);
    const int brow = wn + (lane & 15);
    const uint32_t hk  = (uint32_t)(lane >> 4);
    const uint32_t sxa = (uint32_t)(arow & 7);
    const uint32_t sxb = (uint32_t)(brow & 7);
    uint32_t colA[4], colB[4], aoff[4];
#pragma unroll
    for (int kc = 0; kc < 4; ++kc) {
        colA[kc] = (((uint32_t)(kc * 2) + hk) ^ sxa) << 4;
        colB[kc] = (((uint32_t)(kc * 2) + hk) ^ sxb) << 4;
    }
#pragma unroll
    for (int mi = 0; mi < 4; ++mi) aoff[mi] = (uint32_t)((arow + mi * 16) * 128);
    const uint32_t boff0 = (uint32_t)(brow * 128);
    const uint32_t boff1 = (uint32_t)((brow + 16) * 128);

    // ---- hoisted cp.async addressing ----
    const int r0t = tid >> 3;                         // row 0..31 (first chunk)
    const int c8  = (tid & 7) * 8;                    // fp16 col of 16B chunk
    const size_t gA0 = (size_t)(m0 + r0t) * lda + c8;
    const size_t gB0 = (size_t)(n0 + r0t) * ldb + c8;
    const size_t gstepA = (size_t)32 * lda;           // +32 rows per chunk
    const size_t gstepB = (size_t)32 * ldb;
    const uint32_t soff0 = swz((uint32_t)(r0t * 128 + (tid & 7) * 16));

    const int NK = K / 64;

    auto load_stage = [&](int kt, int slot) {
        if (kt < NK) {
            const uint32_t sb = smbase + (uint32_t)slot * STAGE_B;
            const int k0 = kt * 64;
            const fp16* pAh = Ah + gA0 + k0;
            const fp16* pBh = Bh + gB0 + k0;
            const fp16* pBl = LO ? (Bl + gB0 + k0) : nullptr;
#pragma unroll
            for (int j = 0; j < 4; ++j) {
                const uint32_t so = soff0 + (uint32_t)(j * 4096);
                cp_async16(sb + so,           pAh + (size_t)j * gstepA);
                cp_async16(sb + TILE16K + so, pBh + (size_t)j * gstepB);
                if (LO)
                    cp_async16(sb + 2 * TILE16K + so, pBl + (size_t)j * gstepB);
            }
        }
        asm volatile("cp.async.commit_group;" ::: "memory");
    };

    load_stage(0, 0);

    for (int kt = 0; kt < NK; ++kt) {
        const int buf = kt & 1;
        asm volatile("cp.async.wait_group 0;" ::: "memory");
        __syncthreads();
        load_stage(kt + 1, buf ^ 1);

        const uint32_t sb = smbase + (uint32_t)buf * STAGE_B;
        const uint32_t aH = sb;
        const uint32_t bH = sb + TILE16K, bL = sb + 2 * TILE16K;

#pragma unroll
        for (int kc = 0; kc < 4; ++kc) {
            const uint32_t cA = colA[kc], cB = colB[kc];
            uint32_t a1[4][4], b1[4][2], t[4];

#pragma unroll
            for (int mi = 0; mi < 4; ++mi)
                ldsm_x4(a1[mi], aH + aoff[mi] + cA);
            ldsm_x4(t, bH + boff0 + cB);
            b1[0][0] = t[0]; b1[0][1] = t[2]; b1[1][0] = t[1]; b1[1][1] = t[3];
            ldsm_x4(t, bH + boff1 + cB);
            b1[2][0] = t[0]; b1[2][1] = t[2]; b1[3][0] = t[1]; b1[3][1] = t[3];
#pragma unroll
            for (int mi = 0; mi < 4; ++mi)
#pragma unroll
                for (int ni = 0; ni < 4; ++ni)
                    mma16816(acc[mi][ni], a1[mi], b1[ni]);      // hh

            if (LO) {
                uint32_t b2[4][2];
                ldsm_x4(t, bL + boff0 + cB);
                b2[0][0] = t[0]; b2[0][1] = t[2]; b2[1][0] = t[1]; b2[1][1] = t[3];
                ldsm_x4(t, bL + boff1 + cB);
                b2[2][0] = t[0]; b2[2][1] = t[2]; b2[3][0] = t[1]; b2[3][1] = t[3];
#pragma unroll
                for (int mi = 0; mi < 4; ++mi)
#pragma unroll
                    for (int ni = 0; ni < 4; ++ni)
                        mma16816(acc[mi][ni], a1[mi], b2[ni]);  // hl
            }
        }
        __syncthreads();
    }

    // ------------------------------- epilogue ------------------------------
    const int r0 = m0 + wm + (lane >> 2);
    const int c0 = n0 + wn + (lane & 3) * 2;
#pragma unroll
    for (int mi = 0; mi < 4; ++mi) {
        const int rA = r0 + mi * 16, rB = rA + 8;
        float bmA = 0.f, bmB = 0.f;
        if (MODE == 0 && bias_m) { bmA = bias_m[rA]; bmB = bias_m[rB]; }
#pragma unroll
        for (int ni = 0; ni < 4; ++ni) {
            const int col = c0 + ni * 8;
            if (MODE == 1) {
                float* o = (float*)out0v + sOb * b;
                float2 u;
                u.x = acc[mi][ni][0] * alpha; u.y = acc[mi][ni][1] * alpha;
                *(float2*)(o + (size_t)rA * ldo + col) = u;
                u.x = acc[mi][ni][2] * alpha; u.y = acc[mi][ni][3] * alpha;
                *(float2*)(o + (size_t)rB * ldo + col) = u;
            } else {
                fp16* oh = (fp16*)out0v + sOb * b;
                float bn0 = 0.f, bn1 = 0.f;
                if (bias_n) { bn0 = bias_n[col]; bn1 = bias_n[col + 1]; }
                float v0 = acc[mi][ni][0] + bmA + bn0;
                float v1 = acc[mi][ni][1] + bmA + bn1;
                float v2 = acc[mi][ni][2] + bmB + bn0;
                float v3 = acc[mi][ni][3] + bmB + bn1;
                fp16 h0, l0, h1, l1, h2, l2, h3, l3;
                split_h(v0, h0, l0); split_h(v1, h1, l1);
                split_h(v2, h2, l2); split_h(v3, h3, l3);
                *(__half2*)(oh + (size_t)rA * ldo + col) = __halves2half2(h0, h1);
                *(__half2*)(oh + (size_t)rB * ldo + col) = __halves2half2(h2, h3);
                if (out1v) {
                    fp16* ol = (fp16*)out1v + sOb * b;
                    *(__half2*)(ol + (size_t)rA * ldo + col) = __halves2half2(l0, l1);
                    *(__half2*)(ol + (size_t)rB * ldo + col) = __halves2half2(l2, l3);
                }
            }
        }
    }
}

// ---------------------------------------------------------------------------
// Row softmax: f32 in/out on attn, plus fp16 hi for the final GEMM
// ---------------------------------------------------------------------------
__global__ void softmax_kernel(float* __restrict__ attn,
                               fp16* __restrict__ ah)
{
    const size_t roff = (size_t)blockIdx.x * NPIX;
    float* p = attn + roff;
    const int t = threadIdx.x;
    float v[16];
    float mx = -1e30f;
#pragma unroll
    for (int j = 0; j < 16; ++j) {
        v[j] = p[t + 256 * j];
        mx = fmaxf(mx, v[j]);
    }
    __shared__ float sred[8];
#pragma unroll
    for (int o = 16; o; o >>= 1)
        mx = fmaxf(mx, __shfl_xor_sync(0xffffffffu, mx, o));
    if ((t & 31) == 0) sred[t >> 5] = mx;
    __syncthreads();
    mx = sred[0];
#pragma unroll
    for (int k = 1; k < 8; ++k) mx = fmaxf(mx, sred[k]);

    float s = 0.f;
#pragma unroll
    for (int j = 0; j < 16; ++j) {
        v[j] = __expf(v[j] - mx);
        s += v[j];
    }
#pragma unroll
    for (int o = 16; o; o >>= 1)
        s += __shfl_xor_sync(0xffffffffu, s, o);
    __syncthreads();
    if ((t & 31) == 0) sred[t >> 5] = s;
    __syncthreads();
    s = 0.f;
#pragma unroll
    for (int k = 0; k < 8; ++k) s += sred[k];

    const float inv = 1.f / s;
#pragma unroll
    for (int j = 0; j < 16; ++j) {
        const int idx = t + 256 * j;
        float o = v[j] * inv;
        p[idx] = o;
        ah[roff + idx] = __float2half_rn(o);
    }
}

// ---------------------------------------------------------------------------
// kernel_launch (single stream — graph-capture safe, no resource creation)
// Inputs: f_rgb, f_i, wq, bq, wk, bk, wv, bv
// Output: [f_final | f_rgb | f_i | attn] fp32
// ---------------------------------------------------------------------------
extern "C" void kernel_launch(void* const* d_in, const int* in_sizes, int n_in,
                              void* d_out, int out_size)
{
    const float* f_rgb = (const float*)d_in[0];
    const float* f_i   = (const float*)d_in[1];
    const float* wq    = (const float*)d_in[2];
    const float* bq    = (const float*)d_in[3];
    const float* wk    = (const float*)d_in[4];
    const float* bk    = (const float*)d_in[5];
    const float* wv    = (const float*)d_in[6];
    const float* bv    = (const float*)d_in[7];
    float* out = (float*)d_out;

    cudaFuncSetAttribute(hgemm<0, true>,  cudaFuncAttributeMaxDynamicSharedMemorySize, GEMM_SMEM);
    cudaFuncSetAttribute(hgemm<1, true>,  cudaFuncAttributeMaxDynamicSharedMemorySize, GEMM_SMEM);
    cudaFuncSetAttribute(hgemm<1, false>, cudaFuncAttributeMaxDynamicSharedMemorySize, GEMM_SMEM);

    fp16 *Xh, *Xl, *qkh, *qkl, *vh;
    fp16 *QKh, *QKl, *Vh, *Ath;
    float *bqk, *bv2;
    cudaGetSymbolAddress((void**)&Xh,  g_Xt_h);
    cudaGetSymbolAddress((void**)&Xl,  g_Xt_l);
    cudaGetSymbolAddress((void**)&qkh, g_wqk_h);
    cudaGetSymbolAddress((void**)&qkl, g_wqk_l);
    cudaGetSymbolAddress((void**)&vh,  g_wv2_h);
    cudaGetSymbolAddress((void**)&QKh, g_QKt_h);
    cudaGetSymbolAddress((void**)&QKl, g_QKt_l);
    cudaGetSymbolAddress((void**)&Vh,  g_V2_h);
    cudaGetSymbolAddress((void**)&Ath, g_At_h);
    cudaGetSymbolAddress((void**)&bqk, g_bqk);
    cudaGetSymbolAddress((void**)&bv2, g_bv2);

    float* f_final = out;
    float* attn    = out + (size_t)3 * BATCH * C2 * NPIX;

    const size_t sX  = (size_t)NPIX * 2 * C2;  // per-batch Xt / QKt
    const size_t sQ  = (size_t)NPIX * C2;      // per-batch V2 / f_final
    const size_t sS  = (size_t)NPIX * NPIX;    // per-batch attn

    // 1) copies + transpose/split X
    pack_transpose_kernel<<<dim3(NPIX / 32, C2 / 32, BATCH * 2), dim3(32, 8)>>>(
        f_rgb, f_i, out);
    // 2) weight prep (fused [wq;wk], folded wv, biases)
    weights_prep_kernel<<<(unsigned)((size_t)C2 * 2 * C2 / 256), 256>>>(
        wq, wk, wv, bq, bk, bv);

    // 3a) fused Q+K projection: QKt[pix][4096] hi+lo  (one 2048-CTA launch)
    hgemm<0, true><<<dim3(2 * C2 / 128, NPIX / 128, BATCH), 256, GEMM_SMEM>>>(
        Xh, qkh, qkl, sX, 0, 2 * C2, 2 * C2, 2 * C2,
        QKh, QKl, 2 * C2, sX, 1.f, nullptr, bqk);

    // 3b) V2[ch][pix] hi
    hgemm<0, true><<<dim3(NPIX / 128, C2 / 128, BATCH), 256, GEMM_SMEM>>>(
        vh, Xh, Xl, 0, sX, 2 * C2, 2 * C2, 2 * C2,
        Vh, nullptr, NPIX, sQ, 1.f, bv2, nullptr);

    // 4) scores S[n][m] = Q.K/64 : A = Q half (cols 0..2047), B = K half
    hgemm<1, true><<<dim3(NPIX / 128, NPIX / 128, BATCH), 256, GEMM_SMEM>>>(
        QKh, QKh + C2, QKl + C2, sX, sX, 2 * C2, 2 * C2, C2,
        attn, nullptr, NPIX, sS, 1.f / 64.f, nullptr, nullptr);

    // 5) softmax (f32 out + fp16 hi)
    softmax_kernel<<<BATCH * NPIX, 256>>>(attn, Ath);

    // 6) f_final[c][n] = sum_m V2[c,m] attn[n,m]  (single-product)
    hgemm<1, false><<<dim3(NPIX / 128, C2 / 128, BATCH), 256, GEMM_SMEM>>>(
        Vh, Ath, nullptr, sQ, sS, NPIX, NPIX, NPIX,
        f_final, nullptr, NPIX, sQ, 1.f, nullptr, nullptr);
}

// round 10
// speedup vs baseline: 2.2182x; 1.0793x over previous
#include <cuda_runtime.h>
#include <cuda_fp16.h>
#include <cstdint>

#define C2    2048
#define NPIX  4096
#define BATCH 2

typedef __half fp16;

// ---------------------------------------------------------------------------
// Static device scratch (no allocations anywhere)
// ---------------------------------------------------------------------------
__device__ fp16 g_Xt_h[(size_t)BATCH * NPIX * 2 * C2];   // [b][pix][4096 ch]
__device__ fp16 g_Xt_l[(size_t)BATCH * NPIX * 2 * C2];
__device__ fp16 g_wqk_h[(size_t)2 * C2 * 2 * C2];        // [wq;wk] fused, hi only
__device__ fp16 g_wv2_h[(size_t)C2 * 2 * C2];            // folded V weights (hi only)
__device__ float g_bqk[2 * C2];                          // [bq;bk]
__device__ float g_bv2[C2];
__device__ fp16 g_QKt_h[(size_t)BATCH * NPIX * 2 * C2];  // [b][pix][Q 0..2047|K 2048..4095]
__device__ fp16 g_QKt_l[(size_t)BATCH * NPIX * 2 * C2];
__device__ fp16 g_V2_h[(size_t)BATCH * C2 * NPIX];       // [b][ch][pix] (hi only)
__device__ fp16 g_At_h[(size_t)BATCH * NPIX * NPIX];     // attn fp16 hi
__device__ fp16 g_At_l[(size_t)BATCH * NPIX * NPIX];     // attn fp16 lo

// ---------------------------------------------------------------------------
// helpers
// ---------------------------------------------------------------------------
__device__ __forceinline__ uint32_t smem_u32(const void* p) {
    uint32_t a;
    asm("{ .reg .u64 t; cvta.to.shared.u64 t, %1; cvt.u32.u64 %0, t; }"
        : "=r"(a) : "l"(p));
    return a;
}
__device__ __forceinline__ uint32_t swz(uint32_t b) {       // 128B-row swizzle
    return b ^ ((b >> 3) & 0x70);
}
__device__ __forceinline__ void cp_async16(uint32_t dst, const void* src) {
    asm volatile("cp.async.cg.shared.global [%0], [%1], 16;\n"
                 :: "r"(dst), "l"(src) : "memory");
}
__device__ __forceinline__ void ldsm_x4(uint32_t* r, uint32_t addr) {
    asm volatile("ldmatrix.sync.aligned.m8n8.x4.shared.b16 {%0,%1,%2,%3}, [%4];"
                 : "=r"(r[0]), "=r"(r[1]), "=r"(r[2]), "=r"(r[3]) : "r"(addr));
}
__device__ __forceinline__ void mma16816(float* d, const uint32_t* a,
                                         const uint32_t* b) {
    asm volatile(
        "mma.sync.aligned.m16n8k16.row.col.f32.f16.f16.f32 "
        "{%0,%1,%2,%3}, {%4,%5,%6,%7}, {%8,%9}, {%0,%1,%2,%3};"
        : "+f"(d[0]), "+f"(d[1]), "+f"(d[2]), "+f"(d[3])
        : "r"(a[0]), "r"(a[1]), "r"(a[2]), "r"(a[3]), "r"(b[0]), "r"(b[1]));
}
__device__ __forceinline__ void split_h(float v, fp16& h, fp16& l) {
    h = __float2half_rn(v);
    l = __float2half_rn(v - __half2float(h));
}

// ---------------------------------------------------------------------------
// Pack + transpose: f_rgb/f_i -> fp32 output copies and Xt hi/lo (fp16)
// ---------------------------------------------------------------------------
__global__ void pack_transpose_kernel(const float* __restrict__ frgb,
                                      const float* __restrict__ fi,
                                      float* __restrict__ out)
{
    __shared__ float tile[32][33];
    const int s = blockIdx.z & 1, b = blockIdx.z >> 1;
    const float* src = s ? fi : frgb;
    const int pix0 = blockIdx.x * 32, ch0 = blockIdx.y * 32;
    const size_t base = (size_t)b * C2 * NPIX;
    const size_t PER  = (size_t)BATCH * C2 * NPIX;
    const int tx = threadIdx.x, ty = threadIdx.y;
#pragma unroll
    for (int i = 0; i < 4; ++i) {
        const int ch = ch0 + ty + i * 8;
        const size_t idx = base + (size_t)ch * NPIX + pix0 + tx;
        float v = src[idx];
        out[PER * (1 + s) + idx] = v;          // f_rgb / f_i copy
        tile[ty + i * 8][tx] = v;
    }
    __syncthreads();
    const size_t xbase = (size_t)b * NPIX * (2 * C2) + (size_t)s * C2;
#pragma unroll
    for (int i = 0; i < 4; ++i) {
        const int pix = pix0 + ty + i * 8;
        float v = tile[tx][ty + i * 8];
        fp16 h, l; split_h(v, h, l);
        const size_t idx = xbase + (size_t)pix * (2 * C2) + ch0 + tx;
        g_Xt_h[idx] = h;
        g_Xt_l[idx] = l;
    }
}

// ---------------------------------------------------------------------------
// Weight prep: fused [wq;wk] hi, fold wv -> hi, biases
// ---------------------------------------------------------------------------
__global__ void weights_prep_kernel(const float* __restrict__ wq,
                                    const float* __restrict__ wk,
                                    const float* __restrict__ wv,
                                    const float* __restrict__ bq,
                                    const float* __restrict__ bk,
                                    const float* __restrict__ bv)
{
    const size_t NW = (size_t)C2 * 2 * C2;
    size_t i = (size_t)blockIdx.x * blockDim.x + threadIdx.x;
    if (i < NW) {
        g_wqk_h[i]      = __float2half_rn(wq[i]);
        g_wqk_h[NW + i] = __float2half_rn(wk[i]);
        g_wv2_h[i]      = __float2half_rn(wv[i] + wv[i + NW]);
    }
    if (i < C2) {
        g_bqk[i]      = bq[i];
        g_bqk[C2 + i] = bk[i];
        g_bv2[i]      = bv[i] + bv[i + C2];
    }
}

// ---------------------------------------------------------------------------
// HMMA GEMM:  D[M,N] = alpha * A[M,K] @ B[N,K]^T (+bias)
// 2-product split (LO=true): D ~= Ah*Bh + Ah*Bl;  LO=false: D = Ah*Bh.
// lda/ldb: row strides of A/B (reduction length K may be smaller).
// CTA tile 128x128, kTile 64, 8 warps (warp tile 64x32), 2-stage cp.async
// (96KB smem) -> 2 CTAs/SM.
// MODE 0: out fp16 hi (+lo if out1v), row-major; MODE 1: out f32 * alpha.
// ---------------------------------------------------------------------------
static constexpr int TILE16K   = 16384;          // one 128x64 fp16 tile
static constexpr int STAGE_B   = 3 * TILE16K;    // Ah, Bh, Bl = 48KB
static constexpr int GEMM_SMEM = 2 * STAGE_B + 128;

template<int MODE, bool LO>
__global__ void __launch_bounds__(256, 2)
hgemm(const fp16* __restrict__ Ah,
      const fp16* __restrict__ Bh, const fp16* __restrict__ Bl,
      size_t sAb, size_t sBb, int lda, int ldb, int K,
      void* __restrict__ out0v, void* __restrict__ out1v,
      int ldo, size_t sOb, float alpha,
      const float* __restrict__ bias_m, const float* __restrict__ bias_n)
{
    extern __shared__ __align__(128) char dsm[];
    const uint32_t smbase = (smem_u32(dsm) + 127u) & ~127u;

    const int tid  = threadIdx.x;
    const int lane = tid & 31, warp = tid >> 5;
    const int m0 = blockIdx.y * 128;
    const int n0 = blockIdx.x * 128;
    const int b  = blockIdx.z;
    Ah += sAb * b;
    Bh += sBb * b;  if (LO) Bl += sBb * b;

    const int wm = (warp >> 2) * 64;     // warp M offset
    const int wn = (warp & 3) * 32;      // warp N offset

    float acc[4][4][4];
#pragma unroll
    for (int i = 0; i < 4; ++i)
#pragma unroll
        for (int j = 0; j < 4; ++j)
#pragma unroll
            for (int q = 0; q < 4; ++q) acc[i][j][q] = 0.f;

    // ---- hoisted ldmatrix addressing ----
    const int arow = wm + (lane & 15);
    const int brow = wn + (lane & 15);
    const uint32_t hk  = (uint32_t)(lane >> 4);
    const uint32_t sxa = (uint32_t)(arow & 7);
    const uint32_t sxb = (uint32_t)(brow & 7);
    uint32_t colA[4], colB[4], aoff[4];
#pragma unroll
    for (int kc = 0; kc < 4; ++kc) {
        colA[kc] = (((uint32_t)(kc * 2) + hk) ^ sxa) << 4;
        colB[kc] = (((uint32_t)(kc * 2) + hk) ^ sxb) << 4;
    }
#pragma unroll
    for (int mi = 0; mi < 4; ++mi) aoff[mi] = (uint32_t)((arow + mi * 16) * 128);
    const uint32_t boff0 = (uint32_t)(brow * 128);
    const uint32_t boff1 = (uint32_t)((brow + 16) * 128);

    // ---- hoisted cp.async addressing ----
    const int r0t = tid >> 3;                         // row 0..31 (first chunk)
    const int c8  = (tid & 7) * 8;                    // fp16 col of 16B chunk
    const size_t gA0 = (size_t)(m0 + r0t) * lda + c8;
    const size_t gB0 = (size_t)(n0 + r0t) * ldb + c8;
    const size_t gstepA = (size_t)32 * lda;           // +32 rows per chunk
    const size_t gstepB = (size_t)32 * ldb;
    const uint32_t soff0 = swz((uint32_t)(r0t * 128 + (tid & 7) * 16));

    const int NK = K / 64;

    auto load_stage = [&](int kt, int slot) {
        if (kt < NK) {
            const uint32_t sb = smbase + (uint32_t)slot * STAGE_B;
            const int k0 = kt * 64;
            const fp16* pAh = Ah + gA0 + k0;
            const fp16* pBh = Bh + gB0 + k0;
            const fp16* pBl = LO ? (Bl + gB0 + k0) : nullptr;
#pragma unroll
            for (int j = 0; j < 4; ++j) {
                const uint32_t so = soff0 + (uint32_t)(j * 4096);
                cp_async16(sb + so,           pAh + (size_t)j * gstepA);
                cp_async16(sb + TILE16K + so, pBh + (size_t)j * gstepB);
                if (LO)
                    cp_async16(sb + 2 * TILE16K + so, pBl + (size_t)j * gstepB);
            }
        }
        asm volatile("cp.async.commit_group;" ::: "memory");
    };

    load_stage(0, 0);

    for (int kt = 0; kt < NK; ++kt) {
        const int buf = kt & 1;
        asm volatile("cp.async.wait_group 0;" ::: "memory");
        __syncthreads();
        load_stage(kt + 1, buf ^ 1);

        const uint32_t sb = smbase + (uint32_t)buf * STAGE_B;
        const uint32_t aH = sb;
        const uint32_t bH = sb + TILE16K, bL = sb + 2 * TILE16K;

#pragma unroll
        for (int kc = 0; kc < 4; ++kc) {
            const uint32_t cA = colA[kc], cB = colB[kc];
            uint32_t a1[4][4], b1[4][2], t[4];

#pragma unroll
            for (int mi = 0; mi < 4; ++mi)
                ldsm_x4(a1[mi], aH + aoff[mi] + cA);
            ldsm_x4(t, bH + boff0 + cB);
            b1[0][0] = t[0]; b1[0][1] = t[2]; b1[1][0] = t[1]; b1[1][1] = t[3];
            ldsm_x4(t, bH + boff1 + cB);
            b1[2][0] = t[0]; b1[2][1] = t[2]; b1[3][0] = t[1]; b1[3][1] = t[3];
#pragma unroll
            for (int mi = 0; mi < 4; ++mi)
#pragma unroll
                for (int ni = 0; ni < 4; ++ni)
                    mma16816(acc[mi][ni], a1[mi], b1[ni]);      // hh

            if (LO) {
                uint32_t b2[4][2];
                ldsm_x4(t, bL + boff0 + cB);
                b2[0][0] = t[0]; b2[0][1] = t[2]; b2[1][0] = t[1]; b2[1][1] = t[3];
                ldsm_x4(t, bL + boff1 + cB);
                b2[2][0] = t[0]; b2[2][1] = t[2]; b2[3][0] = t[1]; b2[3][1] = t[3];
#pragma unroll
                for (int mi = 0; mi < 4; ++mi)
#pragma unroll
                    for (int ni = 0; ni < 4; ++ni)
                        mma16816(acc[mi][ni], a1[mi], b2[ni]);  // hl
            }
        }
        __syncthreads();
    }

    // ------------------------------- epilogue ------------------------------
    const int r0 = m0 + wm + (lane >> 2);
    const int c0 = n0 + wn + (lane & 3) * 2;
#pragma unroll
    for (int mi = 0; mi < 4; ++mi) {
        const int rA = r0 + mi * 16, rB = rA + 8;
        float bmA = 0.f, bmB = 0.f;
        if (MODE == 0 && bias_m) { bmA = bias_m[rA]; bmB = bias_m[rB]; }
#pragma unroll
        for (int ni = 0; ni < 4; ++ni) {
            const int col = c0 + ni * 8;
            if (MODE == 1) {
                float* o = (float*)out0v + sOb * b;
                float2 u;
                u.x = acc[mi][ni][0] * alpha; u.y = acc[mi][ni][1] * alpha;
                *(float2*)(o + (size_t)rA * ldo + col) = u;
                u.x = acc[mi][ni][2] * alpha; u.y = acc[mi][ni][3] * alpha;
                *(float2*)(o + (size_t)rB * ldo + col) = u;
            } else {
                fp16* oh = (fp16*)out0v + sOb * b;
                float bn0 = 0.f, bn1 = 0.f;
                if (bias_n) { bn0 = bias_n[col]; bn1 = bias_n[col + 1]; }
                float v0 = acc[mi][ni][0] + bmA + bn0;
                float v1 = acc[mi][ni][1] + bmA + bn1;
                float v2 = acc[mi][ni][2] + bmB + bn0;
                float v3 = acc[mi][ni][3] + bmB + bn1;
                fp16 h0, l0, h1, l1, h2, l2, h3, l3;
                split_h(v0, h0, l0); split_h(v1, h1, l1);
                split_h(v2, h2, l2); split_h(v3, h3, l3);
                *(__half2*)(oh + (size_t)rA * ldo + col) = __halves2half2(h0, h1);
                *(__half2*)(oh + (size_t)rB * ldo + col) = __halves2half2(h2, h3);
                if (out1v) {
                    fp16* ol = (fp16*)out1v + sOb * b;
                    *(__half2*)(ol + (size_t)rA * ldo + col) = __halves2half2(l0, l1);
                    *(__half2*)(ol + (size_t)rB * ldo + col) = __halves2half2(l2, l3);
                }
            }
        }
    }
}

// ---------------------------------------------------------------------------
// Row softmax: f32 in/out on attn, plus fp16 hi/lo pair for the final GEMM
// ---------------------------------------------------------------------------
__global__ void softmax_kernel(float* __restrict__ attn,
                               fp16* __restrict__ ah, fp16* __restrict__ al)
{
    const size_t roff = (size_t)blockIdx.x * NPIX;
    float* p = attn + roff;
    const int t = threadIdx.x;
    float v[16];
    float mx = -1e30f;
#pragma unroll
    for (int j = 0; j < 16; ++j) {
        v[j] = p[t + 256 * j];
        mx = fmaxf(mx, v[j]);
    }
    __shared__ float sred[8];
#pragma unroll
    for (int o = 16; o; o >>= 1)
        mx = fmaxf(mx, __shfl_xor_sync(0xffffffffu, mx, o));
    if ((t & 31) == 0) sred[t >> 5] = mx;
    __syncthreads();
    mx = sred[0];
#pragma unroll
    for (int k = 1; k < 8; ++k) mx = fmaxf(mx, sred[k]);

    float s = 0.f;
#pragma unroll
    for (int j = 0; j < 16; ++j) {
        v[j] = __expf(v[j] - mx);
        s += v[j];
    }
#pragma unroll
    for (int o = 16; o; o >>= 1)
        s += __shfl_xor_sync(0xffffffffu, s, o);
    __syncthreads();
    if ((t & 31) == 0) sred[t >> 5] = s;
    __syncthreads();
    s = 0.f;
#pragma unroll
    for (int k = 0; k < 8; ++k) s += sred[k];

    const float inv = 1.f / s;
#pragma unroll
    for (int j = 0; j < 16; ++j) {
        const int idx = t + 256 * j;
        float o = v[j] * inv;
        p[idx] = o;
        fp16 h, l; split_h(o, h, l);
        ah[roff + idx] = h;
        al[roff + idx] = l;
    }
}

// ---------------------------------------------------------------------------
// kernel_launch (single stream — graph-capture safe)
// Inputs: f_rgb, f_i, wq, bq, wk, bk, wv, bv
// Output: [f_final | f_rgb | f_i | attn] fp32
// ---------------------------------------------------------------------------
extern "C" void kernel_launch(void* const* d_in, const int* in_sizes, int n_in,
                              void* d_out, int out_size)
{
    const float* f_rgb = (const float*)d_in[0];
    const float* f_i   = (const float*)d_in[1];
    const float* wq    = (const float*)d_in[2];
    const float* bq    = (const float*)d_in[3];
    const float* wk    = (const float*)d_in[4];
    const float* bk    = (const float*)d_in[5];
    const float* wv    = (const float*)d_in[6];
    const float* bv    = (const float*)d_in[7];
    float* out = (float*)d_out;

    cudaFuncSetAttribute(hgemm<0, false>, cudaFuncAttributeMaxDynamicSharedMemorySize, GEMM_SMEM);
    cudaFuncSetAttribute(hgemm<0, true>,  cudaFuncAttributeMaxDynamicSharedMemorySize, GEMM_SMEM);
    cudaFuncSetAttribute(hgemm<1, true>,  cudaFuncAttributeMaxDynamicSharedMemorySize, GEMM_SMEM);

    fp16 *Xh, *Xl, *qkh, *vh;
    fp16 *QKh, *QKl, *Vh, *Ath, *Atl;
    float *bqk, *bv2;
    cudaGetSymbolAddress((void**)&Xh,  g_Xt_h);
    cudaGetSymbolAddress((void**)&Xl,  g_Xt_l);
    cudaGetSymbolAddress((void**)&qkh, g_wqk_h);
    cudaGetSymbolAddress((void**)&vh,  g_wv2_h);
    cudaGetSymbolAddress((void**)&QKh, g_QKt_h);
    cudaGetSymbolAddress((void**)&QKl, g_QKt_l);
    cudaGetSymbolAddress((void**)&Vh,  g_V2_h);
    cudaGetSymbolAddress((void**)&Ath, g_At_h);
    cudaGetSymbolAddress((void**)&Atl, g_At_l);
    cudaGetSymbolAddress((void**)&bqk, g_bqk);
    cudaGetSymbolAddress((void**)&bv2, g_bv2);

    float* f_final = out;
    float* attn    = out + (size_t)3 * BATCH * C2 * NPIX;

    const size_t sX  = (size_t)NPIX * 2 * C2;  // per-batch Xt / QKt
    const size_t sQ  = (size_t)NPIX * C2;      // per-batch V2 / f_final
    const size_t sS  = (size_t)NPIX * NPIX;    // per-batch attn

    // 1) copies + transpose/split X
    pack_transpose_kernel<<<dim3(NPIX / 32, C2 / 32, BATCH * 2), dim3(32, 8)>>>(
        f_rgb, f_i, out);
    // 2) weight prep (fused [wq;wk] hi, folded wv hi, biases)
    weights_prep_kernel<<<(unsigned)((size_t)C2 * 2 * C2 / 256), 256>>>(
        wq, wk, wv, bq, bk, bv);

    // 3a) fused Q+K projection, single product (hi x hi); epilogue splits
    //     the fp32 result into hi/lo so S can still correct K's rounding.
    hgemm<0, false><<<dim3(2 * C2 / 128, NPIX / 128, BATCH), 256, GEMM_SMEM>>>(
        Xh, qkh, nullptr, sX, 0, 2 * C2, 2 * C2, 2 * C2,
        QKh, QKl, 2 * C2, sX, 1.f, nullptr, bqk);

    // 3b) V2[ch][pix] hi   (A = wv2 hi, B = X hi+lo)
    hgemm<0, true><<<dim3(NPIX / 128, C2 / 128, BATCH), 256, GEMM_SMEM>>>(
        vh, Xh, Xl, 0, sX, 2 * C2, 2 * C2, 2 * C2,
        Vh, nullptr, NPIX, sQ, 1.f, bv2, nullptr);

    // 4) scores S[n][m] = Q.K/64 : A = Q half (cols 0..2047), B = K half hi+lo
    hgemm<1, true><<<dim3(NPIX / 128, NPIX / 128, BATCH), 256, GEMM_SMEM>>>(
        QKh, QKh + C2, QKl + C2, sX, sX, 2 * C2, 2 * C2, C2,
        attn, nullptr, NPIX, sS, 1.f / 64.f, nullptr, nullptr);

    // 5) softmax (f32 out + fp16 hi/lo)
    softmax_kernel<<<BATCH * NPIX, 256>>>(attn, Ath, Atl);

    // 6) f_final[c][n] = sum_m V2[c,m] attn[n,m]  (attn hi+lo corrected)
    hgemm<1, true><<<dim3(NPIX / 128, C2 / 128, BATCH), 256, GEMM_SMEM>>>(
        Vh, Ath, Atl, sQ, sS, NPIX, NPIX, NPIX,
        f_final, nullptr, NPIX, sQ, 1.f, nullptr, nullptr);
}

// round 11
// speedup vs baseline: 2.8037x; 1.2639x over previous
#include <cuda_runtime.h>
#include <cuda_fp16.h>
#include <cstdint>

#define C2    2048
#define NPIX  4096
#define BATCH 2

typedef __half fp16;

// ---------------------------------------------------------------------------
// Static device scratch (no allocations anywhere)
// ---------------------------------------------------------------------------
__device__ fp16 g_Xt_h[(size_t)BATCH * NPIX * 2 * C2];   // [b][pix][4096 ch]
__device__ fp16 g_Xt_l[(size_t)BATCH * NPIX * 2 * C2];
__device__ fp16 g_wqk_h[(size_t)2 * C2 * 2 * C2];        // [wq;wk] fused, hi only
__device__ fp16 g_wv2_h[(size_t)C2 * 2 * C2];            // folded V weights (hi only)
__device__ float g_bqk[2 * C2];                          // [bq;bk]
__device__ float g_bv2[C2];
__device__ fp16 g_QKt_h[(size_t)BATCH * NPIX * 2 * C2];  // [b][pix][Q 0..2047|K 2048..4095]
__device__ fp16 g_V2_h[(size_t)BATCH * C2 * NPIX];       // [b][ch][pix] (hi only)
__device__ fp16 g_At_h[(size_t)BATCH * NPIX * NPIX];     // attn fp16 hi

// ---------------------------------------------------------------------------
// helpers
// ---------------------------------------------------------------------------
__device__ __forceinline__ uint32_t smem_u32(const void* p) {
    uint32_t a;
    asm("{ .reg .u64 t; cvta.to.shared.u64 t, %1; cvt.u32.u64 %0, t; }"
        : "=r"(a) : "l"(p));
    return a;
}
__device__ __forceinline__ uint32_t swz(uint32_t b) {       // 128B-row swizzle
    return b ^ ((b >> 3) & 0x70);
}
__device__ __forceinline__ void cp_async16(uint32_t dst, const void* src) {
    asm volatile("cp.async.cg.shared.global [%0], [%1], 16;\n"
                 :: "r"(dst), "l"(src) : "memory");
}
__device__ __forceinline__ void ldsm_x4(uint32_t* r, uint32_t addr) {
    asm volatile("ldmatrix.sync.aligned.m8n8.x4.shared.b16 {%0,%1,%2,%3}, [%4];"
                 : "=r"(r[0]), "=r"(r[1]), "=r"(r[2]), "=r"(r[3]) : "r"(addr));
}
__device__ __forceinline__ void mma16816(float* d, const uint32_t* a,
                                         const uint32_t* b) {
    asm volatile(
        "mma.sync.aligned.m16n8k16.row.col.f32.f16.f16.f32 "
        "{%0,%1,%2,%3}, {%4,%5,%6,%7}, {%8,%9}, {%0,%1,%2,%3};"
        : "+f"(d[0]), "+f"(d[1]), "+f"(d[2]), "+f"(d[3])
        : "r"(a[0]), "r"(a[1]), "r"(a[2]), "r"(a[3]), "r"(b[0]), "r"(b[1]));
}
__device__ __forceinline__ void split_h(float v, fp16& h, fp16& l) {
    h = __float2half_rn(v);
    l = __float2half_rn(v - __half2float(h));
}

// ---------------------------------------------------------------------------
// Pack + transpose: f_rgb/f_i -> fp32 output copies and Xt hi/lo (fp16)
// ---------------------------------------------------------------------------
__global__ void pack_transpose_kernel(const float* __restrict__ frgb,
                                      const float* __restrict__ fi,
                                      float* __restrict__ out)
{
    __shared__ float tile[32][33];
    const int s = blockIdx.z & 1, b = blockIdx.z >> 1;
    const float* src = s ? fi : frgb;
    const int pix0 = blockIdx.x * 32, ch0 = blockIdx.y * 32;
    const size_t base = (size_t)b * C2 * NPIX;
    const size_t PER  = (size_t)BATCH * C2 * NPIX;
    const int tx = threadIdx.x, ty = threadIdx.y;
#pragma unroll
    for (int i = 0; i < 4; ++i) {
        const int ch = ch0 + ty + i * 8;
        const size_t idx = base + (size_t)ch * NPIX + pix0 + tx;
        float v = src[idx];
        out[PER * (1 + s) + idx] = v;          // f_rgb / f_i copy
        tile[ty + i * 8][tx] = v;
    }
    __syncthreads();
    const size_t xbase = (size_t)b * NPIX * (2 * C2) + (size_t)s * C2;
#pragma unroll
    for (int i = 0; i < 4; ++i) {
        const int pix = pix0 + ty + i * 8;
        float v = tile[tx][ty + i * 8];
        fp16 h, l; split_h(v, h, l);
        const size_t idx = xbase + (size_t)pix * (2 * C2) + ch0 + tx;
        g_Xt_h[idx] = h;
        g_Xt_l[idx] = l;
    }
}

// ---------------------------------------------------------------------------
// Weight prep: fused [wq;wk] hi, fold wv -> hi, biases
// ---------------------------------------------------------------------------
__global__ void weights_prep_kernel(const float* __restrict__ wq,
                                    const float* __restrict__ wk,
                                    const float* __restrict__ wv,
                                    const float* __restrict__ bq,
                                    const float* __restrict__ bk,
                                    const float* __restrict__ bv)
{
    const size_t NW = (size_t)C2 * 2 * C2;
    size_t i = (size_t)blockIdx.x * blockDim.x + threadIdx.x;
    if (i < NW) {
        g_wqk_h[i]      = __float2half_rn(wq[i]);
        g_wqk_h[NW + i] = __float2half_rn(wk[i]);
        g_wv2_h[i]      = __float2half_rn(wv[i] + wv[i + NW]);
    }
    if (i < C2) {
        g_bqk[i]      = bq[i];
        g_bqk[C2 + i] = bk[i];
        g_bv2[i]      = bv[i] + bv[i + C2];
    }
}

// ---------------------------------------------------------------------------
// HMMA GEMM:  D[M,N] = alpha * A[M,K] @ B[N,K]^T (+bias)
// 2-product split (LO=true): D ~= Ah*Bh + Ah*Bl;  LO=false: D = Ah*Bh.
// lda/ldb: row strides of A/B (reduction length K may be smaller).
// CTA tile 128x128, kTile 64, 8 warps (warp tile 64x32), 2-stage cp.async
// (96KB smem) -> 2 CTAs/SM.
// MODE 0: out fp16 hi (+lo if out1v), row-major; MODE 1: out f32 * alpha.
// ---------------------------------------------------------------------------
static constexpr int TILE16K   = 16384;          // one 128x64 fp16 tile
static constexpr int STAGE_B   = 3 * TILE16K;    // Ah, Bh, Bl = 48KB
static constexpr int GEMM_SMEM = 2 * STAGE_B + 128;

template<int MODE, bool LO>
__global__ void __launch_bounds__(256, 2)
hgemm(const fp16* __restrict__ Ah,
      const fp16* __restrict__ Bh, const fp16* __restrict__ Bl,
      size_t sAb, size_t sBb, int lda, int ldb, int K,
      void* __restrict__ out0v, void* __restrict__ out1v,
      int ldo, size_t sOb, float alpha,
      const float* __restrict__ bias_m, const float* __restrict__ bias_n)
{
    extern __shared__ __align__(128) char dsm[];
    const uint32_t smbase = (smem_u32(dsm) + 127u) & ~127u;

    const int tid  = threadIdx.x;
    const int lane = tid & 31, warp = tid >> 5;
    const int m0 = blockIdx.y * 128;
    const int n0 = blockIdx.x * 128;
    const int b  = blockIdx.z;
    Ah += sAb * b;
    Bh += sBb * b;  if (LO) Bl += sBb * b;

    const int wm = (warp >> 2) * 64;     // warp M offset
    const int wn = (warp & 3) * 32;      // warp N offset

    float acc[4][4][4];
#pragma unroll
    for (int i = 0; i < 4; ++i)
#pragma unroll
        for (int j = 0; j < 4; ++j)
#pragma unroll
            for (int q = 0; q < 4; ++q) acc[i][j][q] = 0.f;

    // ---- hoisted ldmatrix addressing ----
    const int arow = wm + (lane & 15);
    const int brow = wn + (lane & 15);
    const uint32_t hk  = (uint32_t)(lane >> 4);
    const uint32_t sxa = (uint32_t)(arow & 7);
    const uint32_t sxb = (uint32_t)(brow & 7);
    uint32_t colA[4], colB[4], aoff[4];
#pragma unroll
    for (int kc = 0; kc < 4; ++kc) {
        colA[kc] = (((uint32_t)(kc * 2) + hk) ^ sxa) << 4;
        colB[kc] = (((uint32_t)(kc * 2) + hk) ^ sxb) << 4;
    }
#pragma unroll
    for (int mi = 0; mi < 4; ++mi) aoff[mi] = (uint32_t)((arow + mi * 16) * 128);
    const uint32_t boff0 = (uint32_t)(brow * 128);
    const uint32_t boff1 = (uint32_t)((brow + 16) * 128);

    // ---- hoisted cp.async addressing ----
    const int r0t = tid >> 3;                         // row 0..31 (first chunk)
    const int c8  = (tid & 7) * 8;                    // fp16 col of 16B chunk
    const size_t gA0 = (size_t)(m0 + r0t) * lda + c8;
    const size_t gB0 = (size_t)(n0 + r0t) * ldb + c8;
    const size_t gstepA = (size_t)32 * lda;           // +32 rows per chunk
    const size_t gstepB = (size_t)32 * ldb;
    const uint32_t soff0 = swz((uint32_t)(r0t * 128 + (tid & 7) * 16));

    const int NK = K / 64;

    auto load_stage = [&](int kt, int slot) {
        if (kt < NK) {
            const uint32_t sb = smbase + (uint32_t)slot * STAGE_B;
            const int k0 = kt * 64;
            const fp16* pAh = Ah + gA0 + k0;
            const fp16* pBh = Bh + gB0 + k0;
            const fp16* pBl = LO ? (Bl + gB0 + k0) : nullptr;
#pragma unroll
            for (int j = 0; j < 4; ++j) {
                const uint32_t so = soff0 + (uint32_t)(j * 4096);
                cp_async16(sb + so,           pAh + (size_t)j * gstepA);
                cp_async16(sb + TILE16K + so, pBh + (size_t)j * gstepB);
                if (LO)
                    cp_async16(sb + 2 * TILE16K + so, pBl + (size_t)j * gstepB);
            }
        }
        asm volatile("cp.async.commit_group;" ::: "memory");
    };

    load_stage(0, 0);

    for (int kt = 0; kt < NK; ++kt) {
        const int buf = kt & 1;
        asm volatile("cp.async.wait_group 0;" ::: "memory");
        __syncthreads();
        load_stage(kt + 1, buf ^ 1);

        const uint32_t sb = smbase + (uint32_t)buf * STAGE_B;
        const uint32_t aH = sb;
        const uint32_t bH = sb + TILE16K, bL = sb + 2 * TILE16K;

#pragma unroll
        for (int kc = 0; kc < 4; ++kc) {
            const uint32_t cA = colA[kc], cB = colB[kc];
            uint32_t a1[4][4], b1[4][2], t[4];

#pragma unroll
            for (int mi = 0; mi < 4; ++mi)
                ldsm_x4(a1[mi], aH + aoff[mi] + cA);
            ldsm_x4(t, bH + boff0 + cB);
            b1[0][0] = t[0]; b1[0][1] = t[2]; b1[1][0] = t[1]; b1[1][1] = t[3];
            ldsm_x4(t, bH + boff1 + cB);
            b1[2][0] = t[0]; b1[2][1] = t[2]; b1[3][0] = t[1]; b1[3][1] = t[3];
#pragma unroll
            for (int mi = 0; mi < 4; ++mi)
#pragma unroll
                for (int ni = 0; ni < 4; ++ni)
                    mma16816(acc[mi][ni], a1[mi], b1[ni]);      // hh

            if (LO) {
                uint32_t b2[4][2];
                ldsm_x4(t, bL + boff0 + cB);
                b2[0][0] = t[0]; b2[0][1] = t[2]; b2[1][0] = t[1]; b2[1][1] = t[3];
                ldsm_x4(t, bL + boff1 + cB);
                b2[2][0] = t[0]; b2[2][1] = t[2]; b2[3][0] = t[1]; b2[3][1] = t[3];
#pragma unroll
                for (int mi = 0; mi < 4; ++mi)
#pragma unroll
                    for (int ni = 0; ni < 4; ++ni)
                        mma16816(acc[mi][ni], a1[mi], b2[ni]);  // hl
            }
        }
        __syncthreads();
    }

    // ------------------------------- epilogue ------------------------------
    const int r0 = m0 + wm + (lane >> 2);
    const int c0 = n0 + wn + (lane & 3) * 2;
#pragma unroll
    for (int mi = 0; mi < 4; ++mi) {
        const int rA = r0 + mi * 16, rB = rA + 8;
        float bmA = 0.f, bmB = 0.f;
        if (MODE == 0 && bias_m) { bmA = bias_m[rA]; bmB = bias_m[rB]; }
#pragma unroll
        for (int ni = 0; ni < 4; ++ni) {
            const int col = c0 + ni * 8;
            if (MODE == 1) {
                float* o = (float*)out0v + sOb * b;
                float2 u;
                u.x = acc[mi][ni][0] * alpha; u.y = acc[mi][ni][1] * alpha;
                *(float2*)(o + (size_t)rA * ldo + col) = u;
                u.x = acc[mi][ni][2] * alpha; u.y = acc[mi][ni][3] * alpha;
                *(float2*)(o + (size_t)rB * ldo + col) = u;
            } else {
                fp16* oh = (fp16*)out0v + sOb * b;
                float bn0 = 0.f, bn1 = 0.f;
                if (bias_n) { bn0 = bias_n[col]; bn1 = bias_n[col + 1]; }
                float v0 = acc[mi][ni][0] + bmA + bn0;
                float v1 = acc[mi][ni][1] + bmA + bn1;
                float v2 = acc[mi][ni][2] + bmB + bn0;
                float v3 = acc[mi][ni][3] + bmB + bn1;
                fp16 h0, l0, h1, l1, h2, l2, h3, l3;
                split_h(v0, h0, l0); split_h(v1, h1, l1);
                split_h(v2, h2, l2); split_h(v3, h3, l3);
                *(__half2*)(oh + (size_t)rA * ldo + col) = __halves2half2(h0, h1);
                *(__half2*)(oh + (size_t)rB * ldo + col) = __halves2half2(h2, h3);
                if (out1v) {
                    fp16* ol = (fp16*)out1v + sOb * b;
                    *(__half2*)(ol + (size_t)rA * ldo + col) = __halves2half2(l0, l1);
                    *(__half2*)(ol + (size_t)rB * ldo + col) = __halves2half2(l2, l3);
                }
            }
        }
    }
}

// ---------------------------------------------------------------------------
// Row softmax: f32 in/out on attn, plus fp16 hi for the final GEMM
// ---------------------------------------------------------------------------
__global__ void softmax_kernel(float* __restrict__ attn,
                               fp16* __restrict__ ah)
{
    const size_t roff = (size_t)blockIdx.x * NPIX;
    float* p = attn + roff;
    const int t = threadIdx.x;
    float v[16];
    float mx = -1e30f;
#pragma unroll
    for (int j = 0; j < 16; ++j) {
        v[j] = p[t + 256 * j];
        mx = fmaxf(mx, v[j]);
    }
    __shared__ float sred[8];
#pragma unroll
    for (int o = 16; o; o >>= 1)
        mx = fmaxf(mx, __shfl_xor_sync(0xffffffffu, mx, o));
    if ((t & 31) == 0) sred[t >> 5] = mx;
    __syncthreads();
    mx = sred[0];
#pragma unroll
    for (int k = 1; k < 8; ++k) mx = fmaxf(mx, sred[k]);

    float s = 0.f;
#pragma unroll
    for (int j = 0; j < 16; ++j) {
        v[j] = __expf(v[j] - mx);
        s += v[j];
    }
#pragma unroll
    for (int o = 16; o; o >>= 1)
        s += __shfl_xor_sync(0xffffffffu, s, o);
    __syncthreads();
    if ((t & 31) == 0) sred[t >> 5] = s;
    __syncthreads();
    s = 0.f;
#pragma unroll
    for (int k = 0; k < 8; ++k) s += sred[k];

    const float inv = 1.f / s;
#pragma unroll
    for (int j = 0; j < 16; ++j) {
        const int idx = t + 256 * j;
        float o = v[j] * inv;
        p[idx] = o;
        ah[roff + idx] = __float2half_rn(o);
    }
}

// ---------------------------------------------------------------------------
// kernel_launch (single stream — graph-capture safe)
// Inputs: f_rgb, f_i, wq, bq, wk, bk, wv, bv
// Output: [f_final | f_rgb | f_i | attn] fp32
// ---------------------------------------------------------------------------
extern "C" void kernel_launch(void* const* d_in, const int* in_sizes, int n_in,
                              void* d_out, int out_size)
{
    const float* f_rgb = (const float*)d_in[0];
    const float* f_i   = (const float*)d_in[1];
    const float* wq    = (const float*)d_in[2];
    const float* bq    = (const float*)d_in[3];
    const float* wk    = (const float*)d_in[4];
    const float* bk    = (const float*)d_in[5];
    const float* wv    = (const float*)d_in[6];
    const float* bv    = (const float*)d_in[7];
    float* out = (float*)d_out;

    cudaFuncSetAttribute(hgemm<0, false>, cudaFuncAttributeMaxDynamicSharedMemorySize, GEMM_SMEM);
    cudaFuncSetAttribute(hgemm<0, true>,  cudaFuncAttributeMaxDynamicSharedMemorySize, GEMM_SMEM);
    cudaFuncSetAttribute(hgemm<1, false>, cudaFuncAttributeMaxDynamicSharedMemorySize, GEMM_SMEM);

    fp16 *Xh, *Xl, *qkh, *vh;
    fp16 *QKh, *Vh, *Ath;
    float *bqk, *bv2;
    cudaGetSymbolAddress((void**)&Xh,  g_Xt_h);
    cudaGetSymbolAddress((void**)&Xl,  g_Xt_l);
    cudaGetSymbolAddress((void**)&qkh, g_wqk_h);
    cudaGetSymbolAddress((void**)&vh,  g_wv2_h);
    cudaGetSymbolAddress((void**)&QKh, g_QKt_h);
    cudaGetSymbolAddress((void**)&Vh,  g_V2_h);
    cudaGetSymbolAddress((void**)&Ath, g_At_h);
    cudaGetSymbolAddress((void**)&bqk, g_bqk);
    cudaGetSymbolAddress((void**)&bv2, g_bv2);

    float* f_final = out;
    float* attn    = out + (size_t)3 * BATCH * C2 * NPIX;

    const size_t sX  = (size_t)NPIX * 2 * C2;  // per-batch Xt / QKt
    const size_t sQ  = (size_t)NPIX * C2;      // per-batch V2 / f_final
    const size_t sS  = (size_t)NPIX * NPIX;    // per-batch attn

    // 1) copies + transpose/split X
    pack_transpose_kernel<<<dim3(NPIX / 32, C2 / 32, BATCH * 2), dim3(32, 8)>>>(
        f_rgb, f_i, out);
    // 2) weight prep (fused [wq;wk] hi, folded wv hi, biases)
    weights_prep_kernel<<<(unsigned)((size_t)C2 * 2 * C2 / 256), 256>>>(
        wq, wk, wv, bq, bk, bv);

    // 3a) fused Q+K projection, single product (hi x hi), hi-only output
    hgemm<0, false><<<dim3(2 * C2 / 128, NPIX / 128, BATCH), 256, GEMM_SMEM>>>(
        Xh, qkh, nullptr, sX, 0, 2 * C2, 2 * C2, 2 * C2,
        QKh, nullptr, 2 * C2, sX, 1.f, nullptr, bqk);

    // 3b) V2[ch][pix] hi   (A = wv2 hi, B = X hi+lo — kept correction)
    hgemm<0, true><<<dim3(NPIX / 128, C2 / 128, BATCH), 256, GEMM_SMEM>>>(
        vh, Xh, Xl, 0, sX, 2 * C2, 2 * C2, 2 * C2,
        Vh, nullptr, NPIX, sQ, 1.f, bv2, nullptr);

    // 4) scores S[n][m] = Q.K/64, single product (Qh x Kh)
    hgemm<1, false><<<dim3(NPIX / 128, NPIX / 128, BATCH), 256, GEMM_SMEM>>>(
        QKh, QKh + C2, nullptr, sX, sX, 2 * C2, 2 * C2, C2,
        attn, nullptr, NPIX, sS, 1.f / 64.f, nullptr, nullptr);

    // 5) softmax (f32 out + fp16 hi)
    softmax_kernel<<<BATCH * NPIX, 256>>>(attn, Ath);

    // 6) f_final[c][n] = sum_m V2[c,m] attn[n,m], single product
    hgemm<1, false><<<dim3(NPIX / 128, C2 / 128, BATCH), 256, GEMM_SMEM>>>(
        Vh, Ath, nullptr, sQ, sS, NPIX, NPIX, NPIX,
        f_final, nullptr, NPIX, sQ, 1.f, nullptr, nullptr);
}

// round 12
// speedup vs baseline: 3.1903x; 1.1379x over previous
#include <cuda_runtime.h>
#include <cuda_fp16.h>
#include <cstdint>

#define C2    2048
#define NPIX  4096
#define BATCH 2

typedef __half fp16;

// ---------------------------------------------------------------------------
// Static device scratch (no allocations anywhere)
// ---------------------------------------------------------------------------
__device__ fp16 g_Xt_h[(size_t)BATCH * NPIX * 2 * C2];   // [b][pix][4096 ch]
__device__ fp16 g_wqk_h[(size_t)2 * C2 * 2 * C2];        // [wq;wk] fused, hi only
__device__ fp16 g_wv2_h[(size_t)C2 * 2 * C2];            // folded V weights (hi only)
__device__ float g_bqk[2 * C2];                          // [bq;bk]
__device__ float g_bv2[C2];
__device__ fp16 g_QKt_h[(size_t)BATCH * NPIX * 2 * C2];  // [b][pix][Q 0..2047|K 2048..4095]
__device__ fp16 g_V2_h[(size_t)BATCH * C2 * NPIX];       // [b][ch][pix]
__device__ fp16 g_At_h[(size_t)BATCH * NPIX * NPIX];     // attn fp16 hi

// ---------------------------------------------------------------------------
// helpers
// ---------------------------------------------------------------------------
__device__ __forceinline__ uint32_t smem_u32(const void* p) {
    uint32_t a;
    asm("{ .reg .u64 t; cvta.to.shared.u64 t, %1; cvt.u32.u64 %0, t; }"
        : "=r"(a) : "l"(p));
    return a;
}
__device__ __forceinline__ uint32_t swz(uint32_t b) {       // 128B-row swizzle
    return b ^ ((b >> 3) & 0x70);
}
__device__ __forceinline__ void cp_async16(uint32_t dst, const void* src) {
    asm volatile("cp.async.cg.shared.global [%0], [%1], 16;\n"
                 :: "r"(dst), "l"(src) : "memory");
}
__device__ __forceinline__ void ldsm_x4(uint32_t* r, uint32_t addr) {
    asm volatile("ldmatrix.sync.aligned.m8n8.x4.shared.b16 {%0,%1,%2,%3}, [%4];"
                 : "=r"(r[0]), "=r"(r[1]), "=r"(r[2]), "=r"(r[3]) : "r"(addr));
}
__device__ __forceinline__ void mma16816(float* d, const uint32_t* a,
                                         const uint32_t* b) {
    asm volatile(
        "mma.sync.aligned.m16n8k16.row.col.f32.f16.f16.f32 "
        "{%0,%1,%2,%3}, {%4,%5,%6,%7}, {%8,%9}, {%0,%1,%2,%3};"
        : "+f"(d[0]), "+f"(d[1]), "+f"(d[2]), "+f"(d[3])
        : "r"(a[0]), "r"(a[1]), "r"(a[2]), "r"(a[3]), "r"(b[0]), "r"(b[1]));
}
__device__ __forceinline__ void split_h(float v, fp16& h, fp16& l) {
    h = __float2half_rn(v);
    l = __float2half_rn(v - __half2float(h));
}

// ---------------------------------------------------------------------------
// Pack + transpose: f_rgb/f_i -> fp32 output copies and Xt hi (fp16)
// ---------------------------------------------------------------------------
__global__ void pack_transpose_kernel(const float* __restrict__ frgb,
                                      const float* __restrict__ fi,
                                      float* __restrict__ out)
{
    __shared__ float tile[32][33];
    const int s = blockIdx.z & 1, b = blockIdx.z >> 1;
    const float* src = s ? fi : frgb;
    const int pix0 = blockIdx.x * 32, ch0 = blockIdx.y * 32;
    const size_t base = (size_t)b * C2 * NPIX;
    const size_t PER  = (size_t)BATCH * C2 * NPIX;
    const int tx = threadIdx.x, ty = threadIdx.y;
#pragma unroll
    for (int i = 0; i < 4; ++i) {
        const int ch = ch0 + ty + i * 8;
        const size_t idx = base + (size_t)ch * NPIX + pix0 + tx;
        float v = src[idx];
        out[PER * (1 + s) + idx] = v;          // f_rgb / f_i copy
        tile[ty + i * 8][tx] = v;
    }
    __syncthreads();
    const size_t xbase = (size_t)b * NPIX * (2 * C2) + (size_t)s * C2;
#pragma unroll
    for (int i = 0; i < 4; ++i) {
        const int pix = pix0 + ty + i * 8;
        float v = tile[tx][ty + i * 8];
        const size_t idx = xbase + (size_t)pix * (2 * C2) + ch0 + tx;
        g_Xt_h[idx] = __float2half_rn(v);
    }
}

// ---------------------------------------------------------------------------
// Weight prep: fused [wq;wk] hi, fold wv -> hi, biases
// ---------------------------------------------------------------------------
__global__ void weights_prep_kernel(const float* __restrict__ wq,
                                    const float* __restrict__ wk,
                                    const float* __restrict__ wv,
                                    const float* __restrict__ bq,
                                    const float* __restrict__ bk,
                                    const float* __restrict__ bv)
{
    const size_t NW = (size_t)C2 * 2 * C2;
    size_t i = (size_t)blockIdx.x * blockDim.x + threadIdx.x;
    if (i < NW) {
        g_wqk_h[i]      = __float2half_rn(wq[i]);
        g_wqk_h[NW + i] = __float2half_rn(wk[i]);
        g_wv2_h[i]      = __float2half_rn(wv[i] + wv[i + NW]);
    }
    if (i < C2) {
        g_bqk[i]      = bq[i];
        g_bqk[C2 + i] = bk[i];
        g_bv2[i]      = bv[i] + bv[i + C2];
    }
}

// ---------------------------------------------------------------------------
// HMMA GEMM:  D[M,N] = alpha * A[M,K] @ B[N,K]^T (+bias)
// 2-product split (LO=true): D ~= Ah*Bh + Ah*Bl;  LO=false: D = Ah*Bh.
// lda/ldb: row strides of A/B (reduction length K may be smaller).
// CTA tile 128x128, kTile 64, 8 warps (warp tile 64x32), 2-stage cp.async
// (96KB smem) -> 2 CTAs/SM.
// MODE 0: out fp16 hi (+lo if out1v), row-major; MODE 1: out f32 * alpha.
// ---------------------------------------------------------------------------
static constexpr int TILE16K   = 16384;          // one 128x64 fp16 tile
static constexpr int STAGE_B   = 3 * TILE16K;    // Ah, Bh, (Bl) = 48KB
static constexpr int GEMM_SMEM = 2 * STAGE_B + 128;

template<int MODE, bool LO>
__global__ void __launch_bounds__(256, 2)
hgemm(const fp16* __restrict__ Ah,
      const fp16* __restrict__ Bh, const fp16* __restrict__ Bl,
      size_t sAb, size_t sBb, int lda, int ldb, int K,
      void* __restrict__ out0v, void* __restrict__ out1v,
      int ldo, size_t sOb, float alpha,
      const float* __restrict__ bias_m, const float* __restrict__ bias_n)
{
    extern __shared__ __align__(128) char dsm[];
    const uint32_t smbase = (smem_u32(dsm) + 127u) & ~127u;

    const int tid  = threadIdx.x;
    const int lane = tid & 31, warp = tid >> 5;
    const int m0 = blockIdx.y * 128;
    const int n0 = blockIdx.x * 128;
    const int b  = blockIdx.z;
    Ah += sAb * b;
    Bh += sBb * b;  if (LO) Bl += sBb * b;

    const int wm = (warp >> 2) * 64;     // warp M offset
    const int wn = (warp & 3) * 32;      // warp N offset

    float acc[4][4][4];
#pragma unroll
    for (int i = 0; i < 4; ++i)
#pragma unroll
        for (int j = 0; j < 4; ++j)
#pragma unroll
            for (int q = 0; q < 4; ++q) acc[i][j][q] = 0.f;

    // ---- hoisted ldmatrix addressing ----
    const int arow = wm + (lane & 15);
    const int brow = wn + (lane & 15);
    const uint32_t hk  = (uint32_t)(lane >> 4);
    const uint32_t sxa = (uint32_t)(arow & 7);
    const uint32_t sxb = (uint32_t)(brow & 7);
    uint32_t colA[4], colB[4], aoff[4];
#pragma unroll
    for (int kc = 0; kc < 4; ++kc) {
        colA[kc] = (((uint32_t)(kc * 2) + hk) ^ sxa) << 4;
        colB[kc] = (((uint32_t)(kc * 2) + hk) ^ sxb) << 4;
    }
#pragma unroll
    for (int mi = 0; mi < 4; ++mi) aoff[mi] = (uint32_t)((arow + mi * 16) * 128);
    const uint32_t boff0 = (uint32_t)(brow * 128);
    const uint32_t boff1 = (uint32_t)((brow + 16) * 128);

    // ---- hoisted cp.async addressing ----
    const int r0t = tid >> 3;                         // row 0..31 (first chunk)
    const int c8  = (tid & 7) * 8;                    // fp16 col of 16B chunk
    const size_t gA0 = (size_t)(m0 + r0t) * lda + c8;
    const size_t gB0 = (size_t)(n0 + r0t) * ldb + c8;
    const size_t gstepA = (size_t)32 * lda;           // +32 rows per chunk
    const size_t gstepB = (size_t)32 * ldb;
    const uint32_t soff0 = swz((uint32_t)(r0t * 128 + (tid & 7) * 16));

    const int NK = K / 64;

    auto load_stage = [&](int kt, int slot) {
        if (kt < NK) {
            const uint32_t sb = smbase + (uint32_t)slot * STAGE_B;
            const int k0 = kt * 64;
            const fp16* pAh = Ah + gA0 + k0;
            const fp16* pBh = Bh + gB0 + k0;
            const fp16* pBl = LO ? (Bl + gB0 + k0) : nullptr;
#pragma unroll
            for (int j = 0; j < 4; ++j) {
                const uint32_t so = soff0 + (uint32_t)(j * 4096);
                cp_async16(sb + so,           pAh + (size_t)j * gstepA);
                cp_async16(sb + TILE16K + so, pBh + (size_t)j * gstepB);
                if (LO)
                    cp_async16(sb + 2 * TILE16K + so, pBl + (size_t)j * gstepB);
            }
        }
        asm volatile("cp.async.commit_group;" ::: "memory");
    };

    load_stage(0, 0);

    for (int kt = 0; kt < NK; ++kt) {
        const int buf = kt & 1;
        asm volatile("cp.async.wait_group 0;" ::: "memory");
        __syncthreads();
        load_stage(kt + 1, buf ^ 1);

        const uint32_t sb = smbase + (uint32_t)buf * STAGE_B;
        const uint32_t aH = sb;
        const uint32_t bH = sb + TILE16K, bL = sb + 2 * TILE16K;

#pragma unroll
        for (int kc = 0; kc < 4; ++kc) {
            const uint32_t cA = colA[kc], cB = colB[kc];
            uint32_t a1[4][4], b1[4][2], t[4];

#pragma unroll
            for (int mi = 0; mi < 4; ++mi)
                ldsm_x4(a1[mi], aH + aoff[mi] + cA);
            ldsm_x4(t, bH + boff0 + cB);
            b1[0][0] = t[0]; b1[0][1] = t[2]; b1[1][0] = t[1]; b1[1][1] = t[3];
            ldsm_x4(t, bH + boff1 + cB);
            b1[2][0] = t[0]; b1[2][1] = t[2]; b1[3][0] = t[1]; b1[3][1] = t[3];
#pragma unroll
            for (int mi = 0; mi < 4; ++mi)
#pragma unroll
                for (int ni = 0; ni < 4; ++ni)
                    mma16816(acc[mi][ni], a1[mi], b1[ni]);      // hh

            if (LO) {
                uint32_t b2[4][2];
                ldsm_x4(t, bL + boff0 + cB);
                b2[0][0] = t[0]; b2[0][1] = t[2]; b2[1][0] = t[1]; b2[1][1] = t[3];
                ldsm_x4(t, bL + boff1 + cB);
                b2[2][0] = t[0]; b2[2][1] = t[2]; b2[3][0] = t[1]; b2[3][1] = t[3];
#pragma unroll
                for (int mi = 0; mi < 4; ++mi)
#pragma unroll
                    for (int ni = 0; ni < 4; ++ni)
                        mma16816(acc[mi][ni], a1[mi], b2[ni]);  // hl
            }
        }
        __syncthreads();
    }

    // ------------------------------- epilogue ------------------------------
    const int r0 = m0 + wm + (lane >> 2);
    const int c0 = n0 + wn + (lane & 3) * 2;
#pragma unroll
    for (int mi = 0; mi < 4; ++mi) {
        const int rA = r0 + mi * 16, rB = rA + 8;
        float bmA = 0.f, bmB = 0.f;
        if (MODE == 0 && bias_m) { bmA = bias_m[rA]; bmB = bias_m[rB]; }
#pragma unroll
        for (int ni = 0; ni < 4; ++ni) {
            const int col = c0 + ni * 8;
            if (MODE == 1) {
                float* o = (float*)out0v + sOb * b;
                float2 u;
                u.x = acc[mi][ni][0] * alpha; u.y = acc[mi][ni][1] * alpha;
                *(float2*)(o + (size_t)rA * ldo + col) = u;
                u.x = acc[mi][ni][2] * alpha; u.y = acc[mi][ni][3] * alpha;
                *(float2*)(o + (size_t)rB * ldo + col) = u;
            } else {
                fp16* oh = (fp16*)out0v + sOb * b;
                float bn0 = 0.f, bn1 = 0.f;
                if (bias_n) { bn0 = bias_n[col]; bn1 = bias_n[col + 1]; }
                float v0 = acc[mi][ni][0] + bmA + bn0;
                float v1 = acc[mi][ni][1] + bmA + bn1;
                float v2 = acc[mi][ni][2] + bmB + bn0;
                float v3 = acc[mi][ni][3] + bmB + bn1;
                fp16 h0, l0, h1, l1, h2, l2, h3, l3;
                split_h(v0, h0, l0); split_h(v1, h1, l1);
                split_h(v2, h2, l2); split_h(v3, h3, l3);
                *(__half2*)(oh + (size_t)rA * ldo + col) = __halves2half2(h0, h1);
                *(__half2*)(oh + (size_t)rB * ldo + col) = __halves2half2(h2, h3);
                if (out1v) {
                    fp16* ol = (fp16*)out1v + sOb * b;
                    *(__half2*)(ol + (size_t)rA * ldo + col) = __halves2half2(l0, l1);
                    *(__half2*)(ol + (size_t)rB * ldo + col) = __halves2half2(l2, l3);
                }
            }
        }
    }
}

// ---------------------------------------------------------------------------
// Row softmax: f32 in/out on attn, plus fp16 hi for the final GEMM
// ---------------------------------------------------------------------------
__global__ void softmax_kernel(float* __restrict__ attn,
                               fp16* __restrict__ ah)
{
    const size_t roff = (size_t)blockIdx.x * NPIX;
    float* p = attn + roff;
    const int t = threadIdx.x;
    float v[16];
    float mx = -1e30f;
#pragma unroll
    for (int j = 0; j < 16; ++j) {
        v[j] = p[t + 256 * j];
        mx = fmaxf(mx, v[j]);
    }
    __shared__ float sred[8];
#pragma unroll
    for (int o = 16; o; o >>= 1)
        mx = fmaxf(mx, __shfl_xor_sync(0xffffffffu, mx, o));
    if ((t & 31) == 0) sred[t >> 5] = mx;
    __syncthreads();
    mx = sred[0];
#pragma unroll
    for (int k = 1; k < 8; ++k) mx = fmaxf(mx, sred[k]);

    float s = 0.f;
#pragma unroll
    for (int j = 0; j < 16; ++j) {
        v[j] = __expf(v[j] - mx);
        s += v[j];
    }
#pragma unroll
    for (int o = 16; o; o >>= 1)
        s += __shfl_xor_sync(0xffffffffu, s, o);
    __syncthreads();
    if ((t & 31) == 0) sred[t >> 5] = s;
    __syncthreads();
    s = 0.f;
#pragma unroll
    for (int k = 0; k < 8; ++k) s += sred[k];

    const float inv = 1.f / s;
#pragma unroll
    for (int j = 0; j < 16; ++j) {
        const int idx = t + 256 * j;
        float o = v[j] * inv;
        p[idx] = o;
        ah[roff + idx] = __float2half_rn(o);
    }
}

// ---------------------------------------------------------------------------
// kernel_launch (single stream — graph-capture safe)
// Inputs: f_rgb, f_i, wq, bq, wk, bk, wv, bv
// Output: [f_final | f_rgb | f_i | attn] fp32
// ---------------------------------------------------------------------------
extern "C" void kernel_launch(void* const* d_in, const int* in_sizes, int n_in,
                              void* d_out, int out_size)
{
    const float* f_rgb = (const float*)d_in[0];
    const float* f_i   = (const float*)d_in[1];
    const float* wq    = (const float*)d_in[2];
    const float* bq    = (const float*)d_in[3];
    const float* wk    = (const float*)d_in[4];
    const float* bk    = (const float*)d_in[5];
    const float* wv    = (const float*)d_in[6];
    const float* bv    = (const float*)d_in[7];
    float* out = (float*)d_out;

    cudaFuncSetAttribute(hgemm<0, false>, cudaFuncAttributeMaxDynamicSharedMemorySize, GEMM_SMEM);
    cudaFuncSetAttribute(hgemm<1, false>, cudaFuncAttributeMaxDynamicSharedMemorySize, GEMM_SMEM);

    fp16 *Xh, *qkh, *vh;
    fp16 *QKh, *Vh, *Ath;
    float *bqk, *bv2;
    cudaGetSymbolAddress((void**)&Xh,  g_Xt_h);
    cudaGetSymbolAddress((void**)&qkh, g_wqk_h);
    cudaGetSymbolAddress((void**)&vh,  g_wv2_h);
    cudaGetSymbolAddress((void**)&QKh, g_QKt_h);
    cudaGetSymbolAddress((void**)&Vh,  g_V2_h);
    cudaGetSymbolAddress((void**)&Ath, g_At_h);
    cudaGetSymbolAddress((void**)&bqk, g_bqk);
    cudaGetSymbolAddress((void**)&bv2, g_bv2);

    float* f_final = out;
    float* attn    = out + (size_t)3 * BATCH * C2 * NPIX;

    const size_t sX  = (size_t)NPIX * 2 * C2;  // per-batch Xt / QKt
    const size_t sQ  = (size_t)NPIX * C2;      // per-batch V2 / f_final
    const size_t sS  = (size_t)NPIX * NPIX;    // per-batch attn

    // 1) copies + transpose X (hi only)
    pack_transpose_kernel<<<dim3(NPIX / 32, C2 / 32, BATCH * 2), dim3(32, 8)>>>(
        f_rgb, f_i, out);
    // 2) weight prep (fused [wq;wk] hi, folded wv hi, biases)
    weights_prep_kernel<<<(unsigned)((size_t)C2 * 2 * C2 / 256), 256>>>(
        wq, wk, wv, bq, bk, bv);

    // 3a) fused Q+K projection (hi x hi), hi-only output
    hgemm<0, false><<<dim3(2 * C2 / 128, NPIX / 128, BATCH), 256, GEMM_SMEM>>>(
        Xh, qkh, nullptr, sX, 0, 2 * C2, 2 * C2, 2 * C2,
        QKh, nullptr, 2 * C2, sX, 1.f, nullptr, bqk);

    // 3b) V2[ch][pix] (hi x hi)
    hgemm<0, false><<<dim3(NPIX / 128, C2 / 128, BATCH), 256, GEMM_SMEM>>>(
        vh, Xh, nullptr, 0, sX, 2 * C2, 2 * C2, 2 * C2,
        Vh, nullptr, NPIX, sQ, 1.f, bv2, nullptr);

    // 4) scores S[n][m] = Q.K/64 (hi x hi)
    hgemm<1, false><<<dim3(NPIX / 128, NPIX / 128, BATCH), 256, GEMM_SMEM>>>(
        QKh, QKh + C2, nullptr, sX, sX, 2 * C2, 2 * C2, C2,
        attn, nullptr, NPIX, sS, 1.f / 64.f, nullptr, nullptr);

    // 5) softmax (f32 out + fp16 hi)
    softmax_kernel<<<BATCH * NPIX, 256>>>(attn, Ath);

    // 6) f_final[c][n] = sum_m V2[c,m] attn[n,m] (hi x hi)
    hgemm<1, false><<<dim3(NPIX / 128, C2 / 128, BATCH), 256, GEMM_SMEM>>>(
        Vh, Ath, nullptr, sQ, sS, NPIX, NPIX, NPIX,
        f_final, nullptr, NPIX, sQ, 1.f, nullptr, nullptr);
}

// round 13
// speedup vs baseline: 3.3056x; 1.0362x over previous
#include <cuda_runtime.h>
#include <cuda_fp16.h>
#include <cstdint>

#define C2    2048
#define NPIX  4096
#define BATCH 2

typedef __half fp16;

// ---------------------------------------------------------------------------
// Static device scratch (no allocations anywhere)
// ---------------------------------------------------------------------------
__device__ fp16 g_Xt_h[(size_t)BATCH * NPIX * 2 * C2];   // [b][pix][4096 ch]
__device__ fp16 g_wqk_h[(size_t)2 * C2 * 2 * C2];        // [wq;wk] fused
__device__ fp16 g_wv2_h[(size_t)C2 * 2 * C2];            // folded V weights
__device__ float g_bqk[2 * C2];                          // [bq;bk]
__device__ float g_bv2[C2];
__device__ fp16 g_QKt_h[(size_t)BATCH * NPIX * 2 * C2];  // [b][pix][Q 0..2047|K 2048..4095]
__device__ fp16 g_V2_h[(size_t)BATCH * C2 * NPIX];       // [b][ch][pix]
__device__ fp16 g_At_h[(size_t)BATCH * NPIX * NPIX];     // attn fp16

// ---------------------------------------------------------------------------
// helpers
// ---------------------------------------------------------------------------
__device__ __forceinline__ uint32_t smem_u32(const void* p) {
    uint32_t a;
    asm("{ .reg .u64 t; cvta.to.shared.u64 t, %1; cvt.u32.u64 %0, t; }"
        : "=r"(a) : "l"(p));
    return a;
}
__device__ __forceinline__ uint32_t swz(uint32_t b) {       // 128B-row swizzle
    return b ^ ((b >> 3) & 0x70);
}
__device__ __forceinline__ void cp_async16(uint32_t dst, const void* src) {
    asm volatile("cp.async.cg.shared.global [%0], [%1], 16;\n"
                 :: "r"(dst), "l"(src) : "memory");
}
__device__ __forceinline__ void ldsm_x4(uint32_t* r, uint32_t addr) {
    asm volatile("ldmatrix.sync.aligned.m8n8.x4.shared.b16 {%0,%1,%2,%3}, [%4];"
                 : "=r"(r[0]), "=r"(r[1]), "=r"(r[2]), "=r"(r[3]) : "r"(addr));
}
__device__ __forceinline__ void mma16816(float* d, const uint32_t* a,
                                         const uint32_t* b) {
    asm volatile(
        "mma.sync.aligned.m16n8k16.row.col.f32.f16.f16.f32 "
        "{%0,%1,%2,%3}, {%4,%5,%6,%7}, {%8,%9}, {%0,%1,%2,%3};"
        : "+f"(d[0]), "+f"(d[1]), "+f"(d[2]), "+f"(d[3])
        : "r"(a[0]), "r"(a[1]), "r"(a[2]), "r"(a[3]), "r"(b[0]), "r"(b[1]));
}

// ---------------------------------------------------------------------------
// Pack + transpose: f_rgb/f_i -> fp32 output copies and Xt (fp16)
// ---------------------------------------------------------------------------
__global__ void pack_transpose_kernel(const float* __restrict__ frgb,
                                      const float* __restrict__ fi,
                                      float* __restrict__ out)
{
    __shared__ float tile[32][33];
    const int s = blockIdx.z & 1, b = blockIdx.z >> 1;
    const float* src = s ? fi : frgb;
    const int pix0 = blockIdx.x * 32, ch0 = blockIdx.y * 32;
    const size_t base = (size_t)b * C2 * NPIX;
    const size_t PER  = (size_t)BATCH * C2 * NPIX;
    const int tx = threadIdx.x, ty = threadIdx.y;
#pragma unroll
    for (int i = 0; i < 4; ++i) {
        const int ch = ch0 + ty + i * 8;
        const size_t idx = base + (size_t)ch * NPIX + pix0 + tx;
        float v = src[idx];
        out[PER * (1 + s) + idx] = v;          // f_rgb / f_i copy
        tile[ty + i * 8][tx] = v;
    }
    __syncthreads();
    const size_t xbase = (size_t)b * NPIX * (2 * C2) + (size_t)s * C2;
#pragma unroll
    for (int i = 0; i < 4; ++i) {
        const int pix = pix0 + ty + i * 8;
        float v = tile[tx][ty + i * 8];
        const size_t idx = xbase + (size_t)pix * (2 * C2) + ch0 + tx;
        g_Xt_h[idx] = __float2half_rn(v);
    }
}

// ---------------------------------------------------------------------------
// Weight prep: fused [wq;wk], fold wv, biases
// ---------------------------------------------------------------------------
__global__ void weights_prep_kernel(const float* __restrict__ wq,
                                    const float* __restrict__ wk,
                                    const float* __restrict__ wv,
                                    const float* __restrict__ bq,
                                    const float* __restrict__ bk,
                                    const float* __restrict__ bv)
{
    const size_t NW = (size_t)C2 * 2 * C2;
    size_t i = (size_t)blockIdx.x * blockDim.x + threadIdx.x;
    if (i < NW) {
        g_wqk_h[i]      = __float2half_rn(wq[i]);
        g_wqk_h[NW + i] = __float2half_rn(wk[i]);
        g_wv2_h[i]      = __float2half_rn(wv[i] + wv[i + NW]);
    }
    if (i < C2) {
        g_bqk[i]      = bq[i];
        g_bqk[C2 + i] = bk[i];
        g_bv2[i]      = bv[i] + bv[i + C2];
    }
}

// ---------------------------------------------------------------------------
// HMMA GEMM:  D[M,N] = alpha * A[M,K] @ B[N,K]^T (+bias)
// CTA tile 128x128, kTile 64, 8 warps (warp tile 64x32),
// 3-slot cp.async ring (32KB/stage, 96KB smem) with wait_group 1,
// 2 CTAs/SM.
// MODE 0: out fp16 row-major (+bias); MODE 1: out f32 row-major * alpha.
// ---------------------------------------------------------------------------
static constexpr int TILE16K   = 16384;          // one 128x64 fp16 tile
static constexpr int STAGE_B   = 2 * TILE16K;    // Ah, Bh = 32KB
static constexpr int GEMM_SMEM = 3 * STAGE_B + 128;

template<int MODE>
__global__ void __launch_bounds__(256, 2)
hgemm(const fp16* __restrict__ Ah, const fp16* __restrict__ Bh,
      size_t sAb, size_t sBb, int lda, int ldb, int K,
      void* __restrict__ out0v,
      int ldo, size_t sOb, float alpha,
      const float* __restrict__ bias_m, const float* __restrict__ bias_n)
{
    extern __shared__ __align__(128) char dsm[];
    const uint32_t smbase = (smem_u32(dsm) + 127u) & ~127u;

    const int tid  = threadIdx.x;
    const int lane = tid & 31, warp = tid >> 5;
    const int m0 = blockIdx.y * 128;
    const int n0 = blockIdx.x * 128;
    const int b  = blockIdx.z;
    Ah += sAb * b;
    Bh += sBb * b;

    const int wm = (warp >> 2) * 64;     // warp M offset
    const int wn = (warp & 3) * 32;      // warp N offset

    float acc[4][4][4];
#pragma unroll
    for (int i = 0; i < 4; ++i)
#pragma unroll
        for (int j = 0; j < 4; ++j)
#pragma unroll
            for (int q = 0; q < 4; ++q) acc[i][j][q] = 0.f;

    // ---- hoisted ldmatrix addressing ----
    const int arow = wm + (lane & 15);
    const int brow = wn + (lane & 15);
    const uint32_t hk  = (uint32_t)(lane >> 4);
    const uint32_t sxa = (uint32_t)(arow & 7);
    const uint32_t sxb = (uint32_t)(brow & 7);
    uint32_t colA[4], colB[4], aoff[4];
#pragma unroll
    for (int kc = 0; kc < 4; ++kc) {
        colA[kc] = (((uint32_t)(kc * 2) + hk) ^ sxa) << 4;
        colB[kc] = (((uint32_t)(kc * 2) + hk) ^ sxb) << 4;
    }
#pragma unroll
    for (int mi = 0; mi < 4; ++mi) aoff[mi] = (uint32_t)((arow + mi * 16) * 128);
    const uint32_t boff0 = (uint32_t)(brow * 128);
    const uint32_t boff1 = (uint32_t)((brow + 16) * 128);

    // ---- hoisted cp.async addressing ----
    const int r0t = tid >> 3;                         // row 0..31 (first chunk)
    const int c8  = (tid & 7) * 8;                    // fp16 col of 16B chunk
    const size_t gA0 = (size_t)(m0 + r0t) * lda + c8;
    const size_t gB0 = (size_t)(n0 + r0t) * ldb + c8;
    const size_t gstepA = (size_t)32 * lda;           // +32 rows per chunk
    const size_t gstepB = (size_t)32 * ldb;
    const uint32_t soff0 = swz((uint32_t)(r0t * 128 + (tid & 7) * 16));

    const int NK = K / 64;

    auto load_stage = [&](int kt, int slot) {
        if (kt < NK) {
            const uint32_t sb = smbase + (uint32_t)slot * STAGE_B;
            const int k0 = kt * 64;
            const fp16* pAh = Ah + gA0 + k0;
            const fp16* pBh = Bh + gB0 + k0;
#pragma unroll
            for (int j = 0; j < 4; ++j) {
                const uint32_t so = soff0 + (uint32_t)(j * 4096);
                cp_async16(sb + so,           pAh + (size_t)j * gstepA);
                cp_async16(sb + TILE16K + so, pBh + (size_t)j * gstepB);
            }
        }
        asm volatile("cp.async.commit_group;" ::: "memory");
    };

    load_stage(0, 0);
    load_stage(1, 1);
    int cur = 0, wr = 2;

    for (int kt = 0; kt < NK; ++kt) {
        asm volatile("cp.async.wait_group 1;" ::: "memory");
        __syncthreads();
        load_stage(kt + 2, wr);
        wr = (wr == 2) ? 0 : wr + 1;

        const uint32_t sb = smbase + (uint32_t)cur * STAGE_B;
        cur = (cur == 2) ? 0 : cur + 1;
        const uint32_t aH = sb;
        const uint32_t bH = sb + TILE16K;

#pragma unroll
        for (int kc = 0; kc < 4; ++kc) {
            const uint32_t cA = colA[kc], cB = colB[kc];
            uint32_t a1[4][4], b1[4][2], t[4];

#pragma unroll
            for (int mi = 0; mi < 4; ++mi)
                ldsm_x4(a1[mi], aH + aoff[mi] + cA);
            ldsm_x4(t, bH + boff0 + cB);
            b1[0][0] = t[0]; b1[0][1] = t[2]; b1[1][0] = t[1]; b1[1][1] = t[3];
            ldsm_x4(t, bH + boff1 + cB);
            b1[2][0] = t[0]; b1[2][1] = t[2]; b1[3][0] = t[1]; b1[3][1] = t[3];
#pragma unroll
            for (int mi = 0; mi < 4; ++mi)
#pragma unroll
                for (int ni = 0; ni < 4; ++ni)
                    mma16816(acc[mi][ni], a1[mi], b1[ni]);
        }
    }

    // ------------------------------- epilogue ------------------------------
    const int r0 = m0 + wm + (lane >> 2);
    const int c0 = n0 + wn + (lane & 3) * 2;
#pragma unroll
    for (int mi = 0; mi < 4; ++mi) {
        const int rA = r0 + mi * 16, rB = rA + 8;
        float bmA = 0.f, bmB = 0.f;
        if (MODE == 0 && bias_m) { bmA = bias_m[rA]; bmB = bias_m[rB]; }
#pragma unroll
        for (int ni = 0; ni < 4; ++ni) {
            const int col = c0 + ni * 8;
            if (MODE == 1) {
                float* o = (float*)out0v + sOb * b;
                float2 u;
                u.x = acc[mi][ni][0] * alpha; u.y = acc[mi][ni][1] * alpha;
                *(float2*)(o + (size_t)rA * ldo + col) = u;
                u.x = acc[mi][ni][2] * alpha; u.y = acc[mi][ni][3] * alpha;
                *(float2*)(o + (size_t)rB * ldo + col) = u;
            } else {
                fp16* oh = (fp16*)out0v + sOb * b;
                float bn0 = 0.f, bn1 = 0.f;
                if (bias_n) { bn0 = bias_n[col]; bn1 = bias_n[col + 1]; }
                float v0 = acc[mi][ni][0] + bmA + bn0;
                float v1 = acc[mi][ni][1] + bmA + bn1;
                float v2 = acc[mi][ni][2] + bmB + bn0;
                float v3 = acc[mi][ni][3] + bmB + bn1;
                *(__half2*)(oh + (size_t)rA * ldo + col) =
                    __halves2half2(__float2half_rn(v0), __float2half_rn(v1));
                *(__half2*)(oh + (size_t)rB * ldo + col) =
                    __halves2half2(__float2half_rn(v2), __float2half_rn(v3));
            }
        }
    }
}

// ---------------------------------------------------------------------------
// Row softmax: f32 in/out on attn, plus fp16 for the final GEMM
// ---------------------------------------------------------------------------
__global__ void softmax_kernel(float* __restrict__ attn,
                               fp16* __restrict__ ah)
{
    const size_t roff = (size_t)blockIdx.x * NPIX;
    float* p = attn + roff;
    const int t = threadIdx.x;
    float v[16];
    float mx = -1e30f;
#pragma unroll
    for (int j = 0; j < 16; ++j) {
        v[j] = p[t + 256 * j];
        mx = fmaxf(mx, v[j]);
    }
    __shared__ float sred[8];
#pragma unroll
    for (int o = 16; o; o >>= 1)
        mx = fmaxf(mx, __shfl_xor_sync(0xffffffffu, mx, o));
    if ((t & 31) == 0) sred[t >> 5] = mx;
    __syncthreads();
    mx = sred[0];
#pragma unroll
    for (int k = 1; k < 8; ++k) mx = fmaxf(mx, sred[k]);

    float s = 0.f;
#pragma unroll
    for (int j = 0; j < 16; ++j) {
        v[j] = __expf(v[j] - mx);
        s += v[j];
    }
#pragma unroll
    for (int o = 16; o; o >>= 1)
        s += __shfl_xor_sync(0xffffffffu, s, o);
    __syncthreads();
    if ((t & 31) == 0) sred[t >> 5] = s;
    __syncthreads();
    s = 0.f;
#pragma unroll
    for (int k = 0; k < 8; ++k) s += sred[k];

    const float inv = 1.f / s;
#pragma unroll
    for (int j = 0; j < 16; ++j) {
        const int idx = t + 256 * j;
        float o = v[j] * inv;
        p[idx] = o;
        ah[roff + idx] = __float2half_rn(o);
    }
}

// ---------------------------------------------------------------------------
// kernel_launch (single stream — graph-capture safe)
// Inputs: f_rgb, f_i, wq, bq, wk, bk, wv, bv
// Output: [f_final | f_rgb | f_i | attn] fp32
// ---------------------------------------------------------------------------
extern "C" void kernel_launch(void* const* d_in, const int* in_sizes, int n_in,
                              void* d_out, int out_size)
{
    const float* f_rgb = (const float*)d_in[0];
    const float* f_i   = (const float*)d_in[1];
    const float* wq    = (const float*)d_in[2];
    const float* bq    = (const float*)d_in[3];
    const float* wk    = (const float*)d_in[4];
    const float* bk    = (const float*)d_in[5];
    const float* wv    = (const float*)d_in[6];
    const float* bv    = (const float*)d_in[7];
    float* out = (float*)d_out;

    cudaFuncSetAttribute(hgemm<0>, cudaFuncAttributeMaxDynamicSharedMemorySize, GEMM_SMEM);
    cudaFuncSetAttribute(hgemm<1>, cudaFuncAttributeMaxDynamicSharedMemorySize, GEMM_SMEM);

    fp16 *Xh, *qkh, *vh;
    fp16 *QKh, *Vh, *Ath;
    float *bqk, *bv2;
    cudaGetSymbolAddress((void**)&Xh,  g_Xt_h);
    cudaGetSymbolAddress((void**)&qkh, g_wqk_h);
    cudaGetSymbolAddress((void**)&vh,  g_wv2_h);
    cudaGetSymbolAddress((void**)&QKh, g_QKt_h);
    cudaGetSymbolAddress((void**)&Vh,  g_V2_h);
    cudaGetSymbolAddress((void**)&Ath, g_At_h);
    cudaGetSymbolAddress((void**)&bqk, g_bqk);
    cudaGetSymbolAddress((void**)&bv2, g_bv2);

    float* f_final = out;
    float* attn    = out + (size_t)3 * BATCH * C2 * NPIX;

    const size_t sX  = (size_t)NPIX * 2 * C2;  // per-batch Xt / QKt
    const size_t sQ  = (size_t)NPIX * C2;      // per-batch V2 / f_final
    const size_t sS  = (size_t)NPIX * NPIX;    // per-batch attn

    // 1) copies + transpose X
    pack_transpose_kernel<<<dim3(NPIX / 32, C2 / 32, BATCH * 2), dim3(32, 8)>>>(
        f_rgb, f_i, out);
    // 2) weight prep
    weights_prep_kernel<<<(unsigned)((size_t)C2 * 2 * C2 / 256), 256>>>(
        wq, wk, wv, bq, bk, bv);

    // 3a) fused Q+K projection
    hgemm<0><<<dim3(2 * C2 / 128, NPIX / 128, BATCH), 256, GEMM_SMEM>>>(
        Xh, qkh, sX, 0, 2 * C2, 2 * C2, 2 * C2,
        QKh, 2 * C2, sX, 1.f, nullptr, bqk);

    // 3b) V2[ch][pix]
    hgemm<0><<<dim3(NPIX / 128, C2 / 128, BATCH), 256, GEMM_SMEM>>>(
        vh, Xh, 0, sX, 2 * C2, 2 * C2, 2 * C2,
        Vh, NPIX, sQ, 1.f, bv2, nullptr);

    // 4) scores S[n][m] = Q.K/64
    hgemm<1><<<dim3(NPIX / 128, NPIX / 128, BATCH), 256, GEMM_SMEM>>>(
        QKh, QKh + C2, sX, sX, 2 * C2, 2 * C2, C2,
        attn, NPIX, sS, 1.f / 64.f, nullptr, nullptr);

    // 5) softmax (f32 out + fp16)
    softmax_kernel<<<BATCH * NPIX, 256>>>(attn, Ath);

    // 6) f_final[c][n] = sum_m V2[c,m] attn[n,m]
    hgemm<1><<<dim3(NPIX / 128, C2 / 128, BATCH), 256, GEMM_SMEM>>>(
        Vh, Ath, sQ, sS, NPIX, NPIX, NPIX,
        f_final, NPIX, sQ, 1.f, nullptr, nullptr);
}

// round 14
// speedup vs baseline: 3.3343x; 1.0087x over previous
#include <cuda_runtime.h>
#include <cuda_fp16.h>
#include <cstdint>

#define C2    2048
#define NPIX  4096
#define BATCH 2

typedef __half fp16;

// ---------------------------------------------------------------------------
// Static device scratch (no allocations anywhere)
// ---------------------------------------------------------------------------
__device__ fp16 g_Xt_h[(size_t)BATCH * NPIX * 2 * C2];   // [b][pix][4096 ch]
__device__ fp16 g_wqk_h[(size_t)2 * C2 * 2 * C2];        // [wq;wk] fused
__device__ fp16 g_wv2_h[(size_t)C2 * 2 * C2];            // folded V weights
__device__ float g_bqk[2 * C2];                          // [bq;bk]
__device__ float g_bv2[C2];
__device__ fp16 g_QKt_h[(size_t)BATCH * NPIX * 2 * C2];  // [b][pix][Q 0..2047|K 2048..4095]
__device__ fp16 g_V2_h[(size_t)BATCH * C2 * NPIX];       // [b][ch][pix]
__device__ fp16 g_At_h[(size_t)BATCH * NPIX * NPIX];     // attn fp16

// ---------------------------------------------------------------------------
// helpers
// ---------------------------------------------------------------------------
__device__ __forceinline__ uint32_t smem_u32(const void* p) {
    uint32_t a;
    asm("{ .reg .u64 t; cvta.to.shared.u64 t, %1; cvt.u32.u64 %0, t; }"
        : "=r"(a) : "l"(p));
    return a;
}
__device__ __forceinline__ uint32_t swz(uint32_t b) {       // 128B-row swizzle
    return b ^ ((b >> 3) & 0x70);
}
__device__ __forceinline__ void cp_async16(uint32_t dst, const void* src) {
    asm volatile("cp.async.cg.shared.global [%0], [%1], 16;\n"
                 :: "r"(dst), "l"(src) : "memory");
}
__device__ __forceinline__ void ldsm_x4(uint32_t* r, uint32_t addr) {
    asm volatile("ldmatrix.sync.aligned.m8n8.x4.shared.b16 {%0,%1,%2,%3}, [%4];"
                 : "=r"(r[0]), "=r"(r[1]), "=r"(r[2]), "=r"(r[3]) : "r"(addr));
}
__device__ __forceinline__ void mma16816(float* d, const uint32_t* a,
                                         const uint32_t* b) {
    asm volatile(
        "mma.sync.aligned.m16n8k16.row.col.f32.f16.f16.f32 "
        "{%0,%1,%2,%3}, {%4,%5,%6,%7}, {%8,%9}, {%0,%1,%2,%3};"
        : "+f"(d[0]), "+f"(d[1]), "+f"(d[2]), "+f"(d[3])
        : "r"(a[0]), "r"(a[1]), "r"(a[2]), "r"(a[3]), "r"(b[0]), "r"(b[1]));
}

// ---------------------------------------------------------------------------
// Pack + transpose: f_rgb/f_i -> fp32 output copies and Xt (fp16)
// ---------------------------------------------------------------------------
__global__ void pack_transpose_kernel(const float* __restrict__ frgb,
                                      const float* __restrict__ fi,
                                      float* __restrict__ out)
{
    __shared__ float tile[32][33];
    const int s = blockIdx.z & 1, b = blockIdx.z >> 1;
    const float* src = s ? fi : frgb;
    const int pix0 = blockIdx.x * 32, ch0 = blockIdx.y * 32;
    const size_t base = (size_t)b * C2 * NPIX;
    const size_t PER  = (size_t)BATCH * C2 * NPIX;
    const int tx = threadIdx.x, ty = threadIdx.y;
#pragma unroll
    for (int i = 0; i < 4; ++i) {
        const int ch = ch0 + ty + i * 8;
        const size_t idx = base + (size_t)ch * NPIX + pix0 + tx;
        float v = src[idx];
        out[PER * (1 + s) + idx] = v;          // f_rgb / f_i copy
        tile[ty + i * 8][tx] = v;
    }
    __syncthreads();
    const size_t xbase = (size_t)b * NPIX * (2 * C2) + (size_t)s * C2;
#pragma unroll
    for (int i = 0; i < 4; ++i) {
        const int pix = pix0 + ty + i * 8;
        float v = tile[tx][ty + i * 8];
        const size_t idx = xbase + (size_t)pix * (2 * C2) + ch0 + tx;
        g_Xt_h[idx] = __float2half_rn(v);
    }
}

// ---------------------------------------------------------------------------
// Weight prep: fused [wq;wk], fold wv, biases
// ---------------------------------------------------------------------------
__global__ void weights_prep_kernel(const float* __restrict__ wq,
                                    const float* __restrict__ wk,
                                    const float* __restrict__ wv,
                                    const float* __restrict__ bq,
                                    const float* __restrict__ bk,
                                    const float* __restrict__ bv)
{
    const size_t NW = (size_t)C2 * 2 * C2;
    size_t i = (size_t)blockIdx.x * blockDim.x + threadIdx.x;
    if (i < NW) {
        g_wqk_h[i]      = __float2half_rn(wq[i]);
        g_wqk_h[NW + i] = __float2half_rn(wk[i]);
        g_wv2_h[i]      = __float2half_rn(wv[i] + wv[i + NW]);
    }
    if (i < C2) {
        g_bqk[i]      = bq[i];
        g_bqk[C2 + i] = bk[i];
        g_bv2[i]      = bv[i] + bv[i + C2];
    }
}

// ---------------------------------------------------------------------------
// HMMA GEMM:  D[M,N] = alpha * A[M,K] @ B[N,K]^T (+bias)
// CTA tile 128x128, kTile 64, 8 warps (warp tile 64x32),
// 3-slot cp.async ring (32KB/stage) with wait_group 1, 2 CTAs/SM.
// Warp groups process the 4 kc slices in STAGGERED order (warps 0-3:
// 0,1,2,3; warps 4-7: 2,3,0,1) so LDSM bursts of one group overlap the
// MMA phase of the other -- breaks the barrier-induced lockstep.
// MODE 0: out fp16 row-major (+bias); MODE 1: out f32 row-major * alpha.
// ---------------------------------------------------------------------------
static constexpr int TILE16K   = 16384;          // one 128x64 fp16 tile
static constexpr int STAGE_B   = 2 * TILE16K;    // Ah, Bh = 32KB
static constexpr int GEMM_SMEM = 3 * STAGE_B + 128;

template<int MODE>
__global__ void __launch_bounds__(256, 2)
hgemm(const fp16* __restrict__ Ah, const fp16* __restrict__ Bh,
      size_t sAb, size_t sBb, int lda, int ldb, int K,
      void* __restrict__ out0v,
      int ldo, size_t sOb, float alpha,
      const float* __restrict__ bias_m, const float* __restrict__ bias_n)
{
    extern __shared__ __align__(128) char dsm[];
    const uint32_t smbase = (smem_u32(dsm) + 127u) & ~127u;

    const int tid  = threadIdx.x;
    const int lane = tid & 31, warp = tid >> 5;
    const int m0 = blockIdx.y * 128;
    const int n0 = blockIdx.x * 128;
    const int b  = blockIdx.z;
    Ah += sAb * b;
    Bh += sBb * b;

    const int wm = (warp >> 2) * 64;     // warp M offset
    const int wn = (warp & 3) * 32;      // warp N offset
    const int kcrot = (warp >> 2) * 2;   // kc phase rotation per warp group

    float acc[4][4][4];
#pragma unroll
    for (int i = 0; i < 4; ++i)
#pragma unroll
        for (int j = 0; j < 4; ++j)
#pragma unroll
            for (int q = 0; q < 4; ++q) acc[i][j][q] = 0.f;

    // ---- hoisted ldmatrix addressing (indexed by rotated kc) ----
    const int arow = wm + (lane & 15);
    const int brow = wn + (lane & 15);
    const uint32_t hk  = (uint32_t)(lane >> 4);
    const uint32_t sxa = (uint32_t)(arow & 7);
    const uint32_t sxb = (uint32_t)(brow & 7);
    uint32_t colA[4], colB[4], aoff[4];
#pragma unroll
    for (int kc = 0; kc < 4; ++kc) {
        const uint32_t kce = (uint32_t)((kc + kcrot) & 3);
        colA[kc] = (((kce * 2) + hk) ^ sxa) << 4;
        colB[kc] = (((kce * 2) + hk) ^ sxb) << 4;
    }
#pragma unroll
    for (int mi = 0; mi < 4; ++mi) aoff[mi] = (uint32_t)((arow + mi * 16) * 128);
    const uint32_t boff0 = (uint32_t)(brow * 128);
    const uint32_t boff1 = (uint32_t)((brow + 16) * 128);

    // ---- hoisted cp.async addressing ----
    const int r0t = tid >> 3;                         // row 0..31 (first chunk)
    const int c8  = (tid & 7) * 8;                    // fp16 col of 16B chunk
    const size_t gA0 = (size_t)(m0 + r0t) * lda + c8;
    const size_t gB0 = (size_t)(n0 + r0t) * ldb + c8;
    const size_t gstepA = (size_t)32 * lda;           // +32 rows per chunk
    const size_t gstepB = (size_t)32 * ldb;
    const uint32_t soff0 = swz((uint32_t)(r0t * 128 + (tid & 7) * 16));

    const int NK = K / 64;

    auto load_stage = [&](int kt, int slot) {
        if (kt < NK) {
            const uint32_t sb = smbase + (uint32_t)slot * STAGE_B;
            const int k0 = kt * 64;
            const fp16* pAh = Ah + gA0 + k0;
            const fp16* pBh = Bh + gB0 + k0;
#pragma unroll
            for (int j = 0; j < 4; ++j) {
                const uint32_t so = soff0 + (uint32_t)(j * 4096);
                cp_async16(sb + so,           pAh + (size_t)j * gstepA);
                cp_async16(sb + TILE16K + so, pBh + (size_t)j * gstepB);
            }
        }
        asm volatile("cp.async.commit_group;" ::: "memory");
    };

    load_stage(0, 0);
    load_stage(1, 1);
    int cur = 0, wr = 2;

    for (int kt = 0; kt < NK; ++kt) {
        asm volatile("cp.async.wait_group 1;" ::: "memory");
        __syncthreads();
        load_stage(kt + 2, wr);
        wr = (wr == 2) ? 0 : wr + 1;

        const uint32_t sb = smbase + (uint32_t)cur * STAGE_B;
        cur = (cur == 2) ? 0 : cur + 1;
        const uint32_t aH = sb;
        const uint32_t bH = sb + TILE16K;

#pragma unroll
        for (int kc = 0; kc < 4; ++kc) {
            const uint32_t cA = colA[kc], cB = colB[kc];
            uint32_t a1[4][4], b1[4][2], t[4];

#pragma unroll
            for (int mi = 0; mi < 4; ++mi)
                ldsm_x4(a1[mi], aH + aoff[mi] + cA);
            ldsm_x4(t, bH + boff0 + cB);
            b1[0][0] = t[0]; b1[0][1] = t[2]; b1[1][0] = t[1]; b1[1][1] = t[3];
            ldsm_x4(t, bH + boff1 + cB);
            b1[2][0] = t[0]; b1[2][1] = t[2]; b1[3][0] = t[1]; b1[3][1] = t[3];
#pragma unroll
            for (int mi = 0; mi < 4; ++mi)
#pragma unroll
                for (int ni = 0; ni < 4; ++ni)
                    mma16816(acc[mi][ni], a1[mi], b1[ni]);
        }
    }

    // ------------------------------- epilogue ------------------------------
    const int r0 = m0 + wm + (lane >> 2);
    const int c0 = n0 + wn + (lane & 3) * 2;
#pragma unroll
    for (int mi = 0; mi < 4; ++mi) {
        const int rA = r0 + mi * 16, rB = rA + 8;
        float bmA = 0.f, bmB = 0.f;
        if (MODE == 0 && bias_m) { bmA = bias_m[rA]; bmB = bias_m[rB]; }
#pragma unroll
        for (int ni = 0; ni < 4; ++ni) {
            const int col = c0 + ni * 8;
            if (MODE == 1) {
                float* o = (float*)out0v + sOb * b;
                float2 u;
                u.x = acc[mi][ni][0] * alpha; u.y = acc[mi][ni][1] * alpha;
                *(float2*)(o + (size_t)rA * ldo + col) = u;
                u.x = acc[mi][ni][2] * alpha; u.y = acc[mi][ni][3] * alpha;
                *(float2*)(o + (size_t)rB * ldo + col) = u;
            } else {
                fp16* oh = (fp16*)out0v + sOb * b;
                float bn0 = 0.f, bn1 = 0.f;
                if (bias_n) { bn0 = bias_n[col]; bn1 = bias_n[col + 1]; }
                float v0 = acc[mi][ni][0] + bmA + bn0;
                float v1 = acc[mi][ni][1] + bmA + bn1;
                float v2 = acc[mi][ni][2] + bmB + bn0;
                float v3 = acc[mi][ni][3] + bmB + bn1;
                *(__half2*)(oh + (size_t)rA * ldo + col) =
                    __halves2half2(__float2half_rn(v0), __float2half_rn(v1));
                *(__half2*)(oh + (size_t)rB * ldo + col) =
                    __halves2half2(__float2half_rn(v2), __float2half_rn(v3));
            }
        }
    }
}

// ---------------------------------------------------------------------------
// Row softmax: f32 in/out on attn, plus fp16 for the final GEMM
// ---------------------------------------------------------------------------
__global__ void softmax_kernel(float* __restrict__ attn,
                               fp16* __restrict__ ah)
{
    const size_t roff = (size_t)blockIdx.x * NPIX;
    float* p = attn + roff;
    const int t = threadIdx.x;
    float v[16];
    float mx = -1e30f;
#pragma unroll
    for (int j = 0; j < 16; ++j) {
        v[j] = p[t + 256 * j];
        mx = fmaxf(mx, v[j]);
    }
    __shared__ float sred[8];
#pragma unroll
    for (int o = 16; o; o >>= 1)
        mx = fmaxf(mx, __shfl_xor_sync(0xffffffffu, mx, o));
    if ((t & 31) == 0) sred[t >> 5] = mx;
    __syncthreads();
    mx = sred[0];
#pragma unroll
    for (int k = 1; k < 8; ++k) mx = fmaxf(mx, sred[k]);

    float s = 0.f;
#pragma unroll
    for (int j = 0; j < 16; ++j) {
        v[j] = __expf(v[j] - mx);
        s += v[j];
    }
#pragma unroll
    for (int o = 16; o; o >>= 1)
        s += __shfl_xor_sync(0xffffffffu, s, o);
    __syncthreads();
    if ((t & 31) == 0) sred[t >> 5] = s;
    __syncthreads();
    s = 0.f;
#pragma unroll
    for (int k = 0; k < 8; ++k) s += sred[k];

    const float inv = 1.f / s;
#pragma unroll
    for (int j = 0; j < 16; ++j) {
        const int idx = t + 256 * j;
        float o = v[j] * inv;
        p[idx] = o;
        ah[roff + idx] = __float2half_rn(o);
    }
}

// ---------------------------------------------------------------------------
// kernel_launch (single stream — graph-capture safe)
// Inputs: f_rgb, f_i, wq, bq, wk, bk, wv, bv
// Output: [f_final | f_rgb | f_i | attn] fp32
// ---------------------------------------------------------------------------
extern "C" void kernel_launch(void* const* d_in, const int* in_sizes, int n_in,
                              void* d_out, int out_size)
{
    const float* f_rgb = (const float*)d_in[0];
    const float* f_i   = (const float*)d_in[1];
    const float* wq    = (const float*)d_in[2];
    const float* bq    = (const float*)d_in[3];
    const float* wk    = (const float*)d_in[4];
    const float* bk    = (const float*)d_in[5];
    const float* wv    = (const float*)d_in[6];
    const float* bv    = (const float*)d_in[7];
    float* out = (float*)d_out;

    cudaFuncSetAttribute(hgemm<0>, cudaFuncAttributeMaxDynamicSharedMemorySize, GEMM_SMEM);
    cudaFuncSetAttribute(hgemm<1>, cudaFuncAttributeMaxDynamicSharedMemorySize, GEMM_SMEM);

    fp16 *Xh, *qkh, *vh;
    fp16 *QKh, *Vh, *Ath;
    float *bqk, *bv2;
    cudaGetSymbolAddress((void**)&Xh,  g_Xt_h);
    cudaGetSymbolAddress((void**)&qkh, g_wqk_h);
    cudaGetSymbolAddress((void**)&vh,  g_wv2_h);
    cudaGetSymbolAddress((void**)&QKh, g_QKt_h);
    cudaGetSymbolAddress((void**)&Vh,  g_V2_h);
    cudaGetSymbolAddress((void**)&Ath, g_At_h);
    cudaGetSymbolAddress((void**)&bqk, g_bqk);
    cudaGetSymbolAddress((void**)&bv2, g_bv2);

    float* f_final = out;
    float* attn    = out + (size_t)3 * BATCH * C2 * NPIX;

    const size_t sX  = (size_t)NPIX * 2 * C2;  // per-batch Xt / QKt
    const size_t sQ  = (size_t)NPIX * C2;      // per-batch V2 / f_final
    const size_t sS  = (size_t)NPIX * NPIX;    // per-batch attn

    // 1) copies + transpose X
    pack_transpose_kernel<<<dim3(NPIX / 32, C2 / 32, BATCH * 2), dim3(32, 8)>>>(
        f_rgb, f_i, out);
    // 2) weight prep
    weights_prep_kernel<<<(unsigned)((size_t)C2 * 2 * C2 / 256), 256>>>(
        wq, wk, wv, bq, bk, bv);

    // 3a) fused Q+K projection
    hgemm<0><<<dim3(2 * C2 / 128, NPIX / 128, BATCH), 256, GEMM_SMEM>>>(
        Xh, qkh, sX, 0, 2 * C2, 2 * C2, 2 * C2,
        QKh, 2 * C2, sX, 1.f, nullptr, bqk);

    // 3b) V2[ch][pix]
    hgemm<0><<<dim3(NPIX / 128, C2 / 128, BATCH), 256, GEMM_SMEM>>>(
        vh, Xh, 0, sX, 2 * C2, 2 * C2, 2 * C2,
        Vh, NPIX, sQ, 1.f, bv2, nullptr);

    // 4) scores S[n][m] = Q.K/64
    hgemm<1><<<dim3(NPIX / 128, NPIX / 128, BATCH), 256, GEMM_SMEM>>>(
        QKh, QKh + C2, sX, sX, 2 * C2, 2 * C2, C2,
        attn, NPIX, sS, 1.f / 64.f, nullptr, nullptr);

    // 5) softmax (f32 out + fp16)
    softmax_kernel<<<BATCH * NPIX, 256>>>(attn, Ath);

    // 6) f_final[c][n] = sum_m V2[c,m] attn[n,m]
    hgemm<1><<<dim3(NPIX / 128, C2 / 128, BATCH), 256, GEMM_SMEM>>>(
        Vh, Ath, sQ, sS, NPIX, NPIX, NPIX,
        f_final, NPIX, sQ, 1.f, nullptr, nullptr);
}